// round 2
// baseline (speedup 1.0000x reference)
#include <cuda_runtime.h>
#include <cuda_bf16.h>
#include <math.h>

// ---------------------------------------------------------------------------
// Problem constants
// ---------------------------------------------------------------------------
#define BATCH   32
#define SEQL    196          // 14*14 patches
#define TOK     (BATCH*SEQL) // 6272
#define DMODEL  512
#define DINNER  256
#define DSTATE  16
#define DTRANK  16
#define NHEAD   8
#define HDIM    64
#define NBH     (BATCH*NHEAD) // 256
#define PATCHK  768          // 3*16*16

// ---------------------------------------------------------------------------
// Scratch (static device globals; no runtime allocation allowed)
// ---------------------------------------------------------------------------
__device__ float g_col  [TOK * PATCHK];       // im2col patches
__device__ float g_t    [TOK * DMODEL];       // residual stream
__device__ float g_ln   [TOK * DMODEL];       // layernorm out (reused)
__device__ float g_xz   [TOK * DMODEL];       // in_proj out
__device__ float g_xm   [TOK * DINNER];       // silu(conv(xm))  (= u for scan)
__device__ float g_xdbl [TOK * 48];           // x_proj out (dt_r | B | C)
__device__ float g_dt   [TOK * DINNER];       // softplus(dt)
__device__ float g_cat  [TOK * DMODEL];       // [y | silu(conv(z))]
__device__ float g_qkv  [TOK * 3 * DMODEL];
__device__ float g_q    [NBH * SEQL * HDIM];
__device__ float g_k    [NBH * SEQL * HDIM];
__device__ float g_v    [NBH * SEQL * HDIM];
__device__ float g_sc   [NBH * SEQL * SEQL]; // attention scores / probs
__device__ float g_obh  [NBH * SEQL * HDIM];
__device__ float g_o    [TOK * DMODEL];
__device__ float g_mlp  [TOK * 4 * DMODEL];
__device__ float g_feat [TOK * 1024];
__device__ float g_pool [BATCH * 1024];

// ---------------------------------------------------------------------------
// Activation helpers
// ---------------------------------------------------------------------------
__device__ __forceinline__ float act_gelu(float x) {
    // tanh approximation (JAX default approximate=True)
    float x3 = x * x * x;
    return 0.5f * x * (1.0f + tanhf(0.7978845608028654f * (x + 0.044715f * x3)));
}
__device__ __forceinline__ float act_softplus(float x) {
    return (x > 20.0f) ? x : log1pf(expf(x));
}
__device__ __forceinline__ float act_silu(float x) {
    return x / (1.0f + expf(-x));
}

// ---------------------------------------------------------------------------
// Generic fp32 GEMM.
//   C[M,N] = alpha * A[M,K] * op(B)   (+bias) (act) (+res)
//   TRANS_B=1 : B is row-major [N,K]  (i.e. X @ W.T with W=[N,K])
//   TRANS_B=0 : B is row-major [K,N]
// Batched via blockIdx.z with element strides sA/sB/sC (res uses sC).
// Tile 64x64x16, 256 threads, 4x4 per thread.
// ---------------------------------------------------------------------------
template<int TRANS_B, int ACT, int HAS_BIAS, int HAS_RES>
__global__ __launch_bounds__(256)
void gemm_kernel(const float* __restrict__ A, const float* __restrict__ B,
                 const float* __restrict__ bias, const float* __restrict__ res,
                 float* __restrict__ C,
                 int M, int N, int K, int lda, int ldb, int ldc,
                 long sA, long sB, long sC, float alpha)
{
    A += (long)blockIdx.z * sA;
    B += (long)blockIdx.z * sB;
    C += (long)blockIdx.z * sC;
    if (HAS_RES) res += (long)blockIdx.z * sC;

    __shared__ float As[16][65];
    __shared__ float Bs[16][65];

    const int tid = threadIdx.x;
    const int bm = blockIdx.y * 64;
    const int bn = blockIdx.x * 64;
    const int ty = tid >> 4;   // 0..15
    const int tx = tid & 15;   // 0..15

    float acc[4][4];
#pragma unroll
    for (int i = 0; i < 4; i++)
#pragma unroll
        for (int j = 0; j < 4; j++) acc[i][j] = 0.0f;

    const int nkt = (K + 15) >> 4;
    for (int kt = 0; kt < nkt; kt++) {
        const int k0 = kt << 4;
        // load A tile: thread -> (row = tid/16 + p*16, k = tid%16)
#pragma unroll
        for (int p = 0; p < 4; p++) {
            int r  = (tid >> 4) + p * 16;
            int gm = bm + r;
            int gk = k0 + (tid & 15);
            As[tid & 15][r] = (gm < M && gk < K) ? A[(long)gm * lda + gk] : 0.0f;
        }
        // load B tile
        if (TRANS_B) {
#pragma unroll
            for (int p = 0; p < 4; p++) {
                int r  = (tid >> 4) + p * 16;
                int gn = bn + r;
                int gk = k0 + (tid & 15);
                Bs[tid & 15][r] = (gn < N && gk < K) ? B[(long)gn * ldb + gk] : 0.0f;
            }
        } else {
#pragma unroll
            for (int p = 0; p < 4; p++) {
                int kk = (tid >> 6) + p * 4;
                int nn = tid & 63;
                int gk = k0 + kk;
                int gn = bn + nn;
                Bs[kk][nn] = (gk < K && gn < N) ? B[(long)gk * ldb + gn] : 0.0f;
            }
        }
        __syncthreads();
#pragma unroll
        for (int kk = 0; kk < 16; kk++) {
            float a[4], b[4];
#pragma unroll
            for (int i = 0; i < 4; i++) a[i] = As[kk][ty * 4 + i];
#pragma unroll
            for (int j = 0; j < 4; j++) b[j] = Bs[kk][tx * 4 + j];
#pragma unroll
            for (int i = 0; i < 4; i++)
#pragma unroll
                for (int j = 0; j < 4; j++) acc[i][j] = fmaf(a[i], b[j], acc[i][j]);
        }
        __syncthreads();
    }

    // epilogue
#pragma unroll
    for (int i = 0; i < 4; i++) {
        int gm = bm + ty * 4 + i;
        if (gm >= M) continue;
#pragma unroll
        for (int j = 0; j < 4; j++) {
            int gn = bn + tx * 4 + j;
            if (gn >= N) continue;
            float v = acc[i][j] * alpha;
            if (HAS_BIAS) v += bias[gn];
            if (ACT == 1) v = act_gelu(v);
            else if (ACT == 2) v = act_softplus(v);
            if (HAS_RES) v += res[(long)gm * ldc + gn];
            C[(long)gm * ldc + gn] = v;
        }
    }
}

// ---------------------------------------------------------------------------
// im2col for the 16x16/stride-16 patch conv.
// col[(b*196 + ph*14 + pw)][c*256 + kh*16 + kw] = x[b,c,ph*16+kh,pw*16+kw]
// ---------------------------------------------------------------------------
__global__ void im2col_kernel(const float* __restrict__ x)
{
    int idx = blockIdx.x * blockDim.x + threadIdx.x;
    const int n = TOK * PATCHK;
    if (idx >= n) return;
    int tok  = idx / PATCHK;
    int cidx = idx - tok * PATCHK;
    int b  = tok / SEQL;
    int l  = tok - b * SEQL;
    int ph = l / 14, pw = l - ph * 14;
    int c  = cidx >> 8;              // /256
    int r  = cidx & 255;
    int kh = r >> 4, kw = r & 15;
    g_col[idx] = x[(((long)b * 3 + c) * 224 + (ph * 16 + kh)) * 224 + (pw * 16 + kw)];
}

// ---------------------------------------------------------------------------
// LayerNorm over last dim (512). One block (128 thr) per token.
// ---------------------------------------------------------------------------
__global__ __launch_bounds__(128)
void layernorm_kernel(const float* __restrict__ in, const float* __restrict__ g,
                      const float* __restrict__ b, float* __restrict__ out)
{
    int tok = blockIdx.x;
    int tid = threadIdx.x;
    const float* row = in + (long)tok * DMODEL;
    float v[4];
    float s = 0.0f, s2 = 0.0f;
#pragma unroll
    for (int i = 0; i < 4; i++) {
        v[i] = row[tid + i * 128];
        s  += v[i];
        s2 += v[i] * v[i];
    }
#pragma unroll
    for (int o = 16; o > 0; o >>= 1) {
        s  += __shfl_xor_sync(0xffffffffu, s,  o);
        s2 += __shfl_xor_sync(0xffffffffu, s2, o);
    }
    __shared__ float ss[4], ss2[4];
    int warp = tid >> 5, lane = tid & 31;
    if (lane == 0) { ss[warp] = s; ss2[warp] = s2; }
    __syncthreads();
    s  = ss[0] + ss[1] + ss[2] + ss[3];
    s2 = ss2[0] + ss2[1] + ss2[2] + ss2[3];
    float mean = s * (1.0f / DMODEL);
    float var  = s2 * (1.0f / DMODEL) - mean * mean;
    float inv  = rsqrtf(var + 1e-6f);
    float* orow = out + (long)tok * DMODEL;
#pragma unroll
    for (int i = 0; i < 4; i++) {
        int col = tid + i * 128;
        orow[col] = (v[i] - mean) * inv * g[col] + b[col];
    }
}

// ---------------------------------------------------------------------------
// Causal depthwise conv (width 4) + SiLU for both halves of xz.
//  half 0 (cols   0:256, weights convx) -> g_xm
//  half 1 (cols 256:512, weights convz) -> g_cat[:, 256:512]
// ---------------------------------------------------------------------------
__global__ void dwconv_silu_kernel(const float* __restrict__ wx, const float* __restrict__ bx,
                                   const float* __restrict__ wz, const float* __restrict__ bz)
{
    int idx = blockIdx.x * blockDim.x + threadIdx.x;
    const int n = TOK * DINNER;
    if (idx >= 2 * n) return;
    int half = idx >= n;
    int id   = half ? idx - n : idx;
    int tok  = id >> 8;            // /256
    int c    = id & 255;
    int b    = tok / SEQL;
    int l    = tok - b * SEQL;
    const float* w  = half ? wz : wx;
    const float* bb = half ? bz : bx;
    int off = half ? DINNER : 0;
    float sum = bb[c];
#pragma unroll
    for (int k = 0; k < 4; k++) {
        int ll = l - 3 + k;
        if (ll >= 0)
            sum += g_xz[((long)(b * SEQL + ll)) * DMODEL + off + c] * w[c * 4 + k];
    }
    sum = act_silu(sum);
    if (half) g_cat[(long)tok * DMODEL + DINNER + c] = sum;
    else      g_xm[(long)tok * DINNER + c] = sum;
}

// ---------------------------------------------------------------------------
// Selective scan. Thread per (b, d, n): 16 lanes per (b,d) reduce y via shfl.
// grid = BATCH*16 blocks of 256 threads (16 d x 16 n).
// Writes y + u*Dp into g_cat[:, 0:256].
// ---------------------------------------------------------------------------
__global__ __launch_bounds__(256)
void scan_kernel(const float* __restrict__ A_log, const float* __restrict__ Dp)
{
    int b    = blockIdx.x >> 4;
    int dblk = blockIdx.x & 15;
    int nidx = threadIdx.x & 15;
    int d    = dblk * 16 + (threadIdx.x >> 4);

    float An = -expf(A_log[d * DSTATE + nidx]);
    float Dd = Dp[d];
    float h  = 0.0f;
    const long tokbase = (long)b * SEQL;
    for (int l = 0; l < SEQL; l++) {
        long t   = tokbase + l;
        float dtv = g_dt[t * DINNER + d];
        float u   = g_xm[t * DINNER + d];
        float Bn  = g_xdbl[t * 48 + DTRANK + nidx];
        float Cn  = g_xdbl[t * 48 + DTRANK + DSTATE + nidx];
        h = __expf(dtv * An) * h + dtv * u * Bn;
        float y = h * Cn;
        y += __shfl_xor_sync(0xffffffffu, y, 8);
        y += __shfl_xor_sync(0xffffffffu, y, 4);
        y += __shfl_xor_sync(0xffffffffu, y, 2);
        y += __shfl_xor_sync(0xffffffffu, y, 1);
        if (nidx == 0)
            g_cat[t * DMODEL + d] = y + u * Dd;
    }
}

// ---------------------------------------------------------------------------
// qkv split: [tok, 3, 8, 64] -> q/k/v [bh, 196, 64]
// ---------------------------------------------------------------------------
__global__ void split_qkv_kernel()
{
    int idx = blockIdx.x * blockDim.x + threadIdx.x;
    const int n = TOK * 3 * DMODEL;
    if (idx >= n) return;
    int tok = idx / (3 * DMODEL);
    int r   = idx - tok * (3 * DMODEL);
    int which = r / DMODEL;
    int h  = (r % DMODEL) / HDIM;
    int dd = r % HDIM;
    int b = tok / SEQL, l = tok - b * SEQL;
    long dst = ((long)(b * NHEAD + h) * SEQL + l) * HDIM + dd;
    float val = g_qkv[idx];
    if (which == 0)      g_q[dst] = val;
    else if (which == 1) g_k[dst] = val;
    else                 g_v[dst] = val;
}

// ---------------------------------------------------------------------------
// Row softmax over 196 cols. One block (128 thr) per row.
// ---------------------------------------------------------------------------
__global__ __launch_bounds__(128)
void softmax_kernel()
{
    long rowbase = (long)blockIdx.x * SEQL;
    int tid = threadIdx.x;
    float m = -1e30f;
    for (int j = tid; j < SEQL; j += 128) m = fmaxf(m, g_sc[rowbase + j]);
#pragma unroll
    for (int o = 16; o > 0; o >>= 1) m = fmaxf(m, __shfl_xor_sync(0xffffffffu, m, o));
    __shared__ float sm[4], ssum[4];
    int warp = tid >> 5, lane = tid & 31;
    if (lane == 0) sm[warp] = m;
    __syncthreads();
    m = fmaxf(fmaxf(sm[0], sm[1]), fmaxf(sm[2], sm[3]));
    float s = 0.0f;
    for (int j = tid; j < SEQL; j += 128) {
        float e = __expf(g_sc[rowbase + j] - m);
        g_sc[rowbase + j] = e;
        s += e;
    }
#pragma unroll
    for (int o = 16; o > 0; o >>= 1) s += __shfl_xor_sync(0xffffffffu, s, o);
    if (lane == 0) ssum[warp] = s;
    __syncthreads();
    s = ssum[0] + ssum[1] + ssum[2] + ssum[3];
    float inv = 1.0f / s;
    for (int j = tid; j < SEQL; j += 128) g_sc[rowbase + j] *= inv;
}

// ---------------------------------------------------------------------------
// Merge attention output: [bh, 196, 64] -> [tok, 512]
// ---------------------------------------------------------------------------
__global__ void merge_o_kernel()
{
    int idx = blockIdx.x * blockDim.x + threadIdx.x;
    const int n = TOK * DMODEL;
    if (idx >= n) return;
    int tok = idx >> 9;            // /512
    int ch  = idx & 511;
    int h = ch >> 6, dd = ch & 63;
    int b = tok / SEQL, l = tok - b * SEQL;
    g_o[idx] = g_obh[((long)(b * NHEAD + h) * SEQL + l) * HDIM + dd];
}

// ---------------------------------------------------------------------------
// Mean pool over L. One block per batch element.
// ---------------------------------------------------------------------------
__global__ __launch_bounds__(256)
void pool_kernel()
{
    int b = blockIdx.x;
    for (int j = threadIdx.x; j < 1024; j += blockDim.x) {
        float s = 0.0f;
        const float* base = g_feat + (long)b * SEQL * 1024 + j;
        for (int l = 0; l < SEQL; l++) s += base[(long)l * 1024];
        g_pool[b * 1024 + j] = s * (1.0f / SEQL);
    }
}

// ---------------------------------------------------------------------------
// Final fc: [32,1024] @ [4,1024]^T + b -> [32,4]
// ---------------------------------------------------------------------------
__global__ __launch_bounds__(128)
void fc_kernel(const float* __restrict__ fc_w, const float* __restrict__ fc_b,
               float* __restrict__ out)
{
    int o = threadIdx.x;
    if (o >= BATCH * 4) return;
    int b = o >> 2, c = o & 3;
    float s = fc_b[c];
    const float* p = g_pool + b * 1024;
    const float* w = fc_w + c * 1024;
    for (int k = 0; k < 1024; k++) s = fmaf(p[k], w[k], s);
    out[o] = s;
}

// ---------------------------------------------------------------------------
// Launch
// ---------------------------------------------------------------------------
static inline dim3 gemm_grid(int M, int N, int batch) {
    return dim3((N + 63) / 64, (M + 63) / 64, batch);
}

extern "C" void kernel_launch(void* const* d_in, const int* in_sizes, int n_in,
                              void* d_out, int out_size)
{
    const float* x          = (const float*)d_in[0];
    const float* patch_w    = (const float*)d_in[1];
    const float* patch_b    = (const float*)d_in[2];
    const float* ln1_g      = (const float*)d_in[3];
    const float* ln1_b      = (const float*)d_in[4];
    const float* in_proj_w  = (const float*)d_in[5];
    const float* convx_w    = (const float*)d_in[6];
    const float* convx_b    = (const float*)d_in[7];
    const float* convz_w    = (const float*)d_in[8];
    const float* convz_b    = (const float*)d_in[9];
    const float* x_proj_w   = (const float*)d_in[10];
    const float* dt_proj_w  = (const float*)d_in[11];
    const float* dt_proj_b  = (const float*)d_in[12];
    const float* A_log      = (const float*)d_in[13];
    const float* Dp         = (const float*)d_in[14];
    const float* out_proj_w = (const float*)d_in[15];
    const float* ln2_g      = (const float*)d_in[16];
    const float* ln2_b      = (const float*)d_in[17];
    const float* qkv_w      = (const float*)d_in[18];
    const float* attn_proj_w= (const float*)d_in[19];
    const float* ln3_g      = (const float*)d_in[20];
    const float* ln3_b      = (const float*)d_in[21];
    const float* mlp_w1     = (const float*)d_in[22];
    const float* mlp_b1     = (const float*)d_in[23];
    const float* mlp_w2     = (const float*)d_in[24];
    const float* mlp_b2     = (const float*)d_in[25];
    const float* head_w     = (const float*)d_in[26];
    const float* head_b     = (const float*)d_in[27];
    const float* fc_w       = (const float*)d_in[28];
    const float* fc_b       = (const float*)d_in[29];
    float* out = (float*)d_out;

    // Resolve device-global addresses (host-side)
    float *p_col, *p_t, *p_ln, *p_xz, *p_xm, *p_xdbl, *p_dt, *p_cat, *p_qkv;
    float *p_q, *p_k, *p_v, *p_sc, *p_obh, *p_o, *p_mlp, *p_feat;
    cudaGetSymbolAddress((void**)&p_col,  g_col);
    cudaGetSymbolAddress((void**)&p_t,    g_t);
    cudaGetSymbolAddress((void**)&p_ln,   g_ln);
    cudaGetSymbolAddress((void**)&p_xz,   g_xz);
    cudaGetSymbolAddress((void**)&p_xm,   g_xm);
    cudaGetSymbolAddress((void**)&p_xdbl, g_xdbl);
    cudaGetSymbolAddress((void**)&p_dt,   g_dt);
    cudaGetSymbolAddress((void**)&p_cat,  g_cat);
    cudaGetSymbolAddress((void**)&p_qkv,  g_qkv);
    cudaGetSymbolAddress((void**)&p_q,    g_q);
    cudaGetSymbolAddress((void**)&p_k,    g_k);
    cudaGetSymbolAddress((void**)&p_v,    g_v);
    cudaGetSymbolAddress((void**)&p_sc,   g_sc);
    cudaGetSymbolAddress((void**)&p_obh,  g_obh);
    cudaGetSymbolAddress((void**)&p_o,    g_o);
    cudaGetSymbolAddress((void**)&p_mlp,  g_mlp);
    cudaGetSymbolAddress((void**)&p_feat, g_feat);

    // 1) im2col
    {
        int n = TOK * PATCHK;
        im2col_kernel<<<(n + 255) / 256, 256>>>(x);
    }
    // 2) patch embed GEMM: [6272,768] x [512,768]^T + patch_b -> g_t
    gemm_kernel<1,0,1,0><<<gemm_grid(TOK, DMODEL, 1), 256>>>(
        p_col, patch_w, patch_b, nullptr, p_t,
        TOK, DMODEL, PATCHK, PATCHK, PATCHK, DMODEL, 0, 0, 0, 1.0f);
    // 3) LN1
    layernorm_kernel<<<TOK, 128>>>(p_t, ln1_g, ln1_b, p_ln);
    // 4) in_proj: [6272,512] x [512,512]^T -> g_xz
    gemm_kernel<1,0,0,0><<<gemm_grid(TOK, DMODEL, 1), 256>>>(
        p_ln, in_proj_w, nullptr, nullptr, p_xz,
        TOK, DMODEL, DMODEL, DMODEL, DMODEL, DMODEL, 0, 0, 0, 1.0f);
    // 5) causal dwconv + silu for xm and z
    {
        int n = 2 * TOK * DINNER;
        dwconv_silu_kernel<<<(n + 255) / 256, 256>>>(convx_w, convx_b, convz_w, convz_b);
    }
    // 6) x_proj: [6272,256] x [48,256]^T -> g_xdbl
    gemm_kernel<1,0,0,0><<<gemm_grid(TOK, 48, 1), 256>>>(
        p_xm, x_proj_w, nullptr, nullptr, p_xdbl,
        TOK, 48, DINNER, DINNER, DINNER, 48, 0, 0, 0, 1.0f);
    // 7) dt_proj + softplus: [6272,16](lda=48) x [256,16]^T + b -> g_dt
    gemm_kernel<1,2,1,0><<<gemm_grid(TOK, DINNER, 1), 256>>>(
        p_xdbl, dt_proj_w, dt_proj_b, nullptr, p_dt,
        TOK, DINNER, DTRANK, 48, DTRANK, DINNER, 0, 0, 0, 1.0f);
    // 8) selective scan -> g_cat[:, 0:256]
    scan_kernel<<<BATCH * 16, 256>>>(A_log, Dp);
    // 9) out_proj + residual: t += cat @ W^T
    gemm_kernel<1,0,0,1><<<gemm_grid(TOK, DMODEL, 1), 256>>>(
        p_cat, out_proj_w, nullptr, p_t, p_t,
        TOK, DMODEL, DMODEL, DMODEL, DMODEL, DMODEL, 0, 0, 0, 1.0f);
    // 10) LN2
    layernorm_kernel<<<TOK, 128>>>(p_t, ln2_g, ln2_b, p_ln);
    // 11) qkv: [6272,512] x [1536,512]^T -> g_qkv
    gemm_kernel<1,0,0,0><<<gemm_grid(TOK, 3 * DMODEL, 1), 256>>>(
        p_ln, qkv_w, nullptr, nullptr, p_qkv,
        TOK, 3 * DMODEL, DMODEL, DMODEL, DMODEL, 3 * DMODEL, 0, 0, 0, 1.0f);
    // 12) split qkv
    {
        int n = TOK * 3 * DMODEL;
        split_qkv_kernel<<<(n + 255) / 256, 256>>>();
    }
    // 13) scores = Q K^T / 8 (batched over 256 bh)
    gemm_kernel<1,0,0,0><<<gemm_grid(SEQL, SEQL, NBH), 256>>>(
        p_q, p_k, nullptr, nullptr, p_sc,
        SEQL, SEQL, HDIM, HDIM, HDIM, SEQL,
        (long)SEQL * HDIM, (long)SEQL * HDIM, (long)SEQL * SEQL, 0.125f);
    // 14) softmax rows
    softmax_kernel<<<NBH * SEQL, 128>>>();
    // 15) O = P V (batched, NN)
    gemm_kernel<0,0,0,0><<<gemm_grid(SEQL, HDIM, NBH), 256>>>(
        p_sc, p_v, nullptr, nullptr, p_obh,
        SEQL, HDIM, SEQL, SEQL, HDIM, HDIM,
        (long)SEQL * SEQL, (long)SEQL * HDIM, (long)SEQL * HDIM, 1.0f);
    // 16) merge O
    {
        int n = TOK * DMODEL;
        merge_o_kernel<<<(n + 255) / 256, 256>>>();
    }
    // 17) attn_proj + residual
    gemm_kernel<1,0,0,1><<<gemm_grid(TOK, DMODEL, 1), 256>>>(
        p_o, attn_proj_w, nullptr, p_t, p_t,
        TOK, DMODEL, DMODEL, DMODEL, DMODEL, DMODEL, 0, 0, 0, 1.0f);
    // 18) LN3
    layernorm_kernel<<<TOK, 128>>>(p_t, ln3_g, ln3_b, p_ln);
    // 19) mlp1 + gelu: [6272,512] x [2048,512]^T + b1 -> g_mlp
    gemm_kernel<1,1,1,0><<<gemm_grid(TOK, 4 * DMODEL, 1), 256>>>(
        p_ln, mlp_w1, mlp_b1, nullptr, p_mlp,
        TOK, 4 * DMODEL, DMODEL, DMODEL, DMODEL, 4 * DMODEL, 0, 0, 0, 1.0f);
    // 20) mlp2 + b2 + residual
    gemm_kernel<1,0,1,1><<<gemm_grid(TOK, DMODEL, 1), 256>>>(
        p_mlp, mlp_w2, mlp_b2, p_t, p_t,
        TOK, DMODEL, 4 * DMODEL, 4 * DMODEL, 4 * DMODEL, DMODEL, 0, 0, 0, 1.0f);
    // 21) head: [6272,512] x [1024,512]^T + head_b -> g_feat
    gemm_kernel<1,0,1,0><<<gemm_grid(TOK, 1024, 1), 256>>>(
        p_t, head_w, head_b, nullptr, p_feat,
        TOK, 1024, DMODEL, DMODEL, DMODEL, 1024, 0, 0, 0, 1.0f);
    // 22) mean pool
    pool_kernel<<<BATCH, 256>>>();
    // 23) fc
    fc_kernel<<<1, 128>>>(fc_w, fc_b, out);
}

// round 3
// speedup vs baseline: 2.4316x; 2.4316x over previous
#include <cuda_runtime.h>
#include <cuda_bf16.h>
#include <math.h>
#include <stdint.h>

// ---------------------------------------------------------------------------
// Problem constants
// ---------------------------------------------------------------------------
#define BATCH   32
#define SEQL    196          // 14*14 patches
#define TOK     (BATCH*SEQL) // 6272
#define DMODEL  512
#define DINNER  256
#define DSTATE  16
#define DTRANK  16
#define NHEAD   8
#define HDIM    64
#define NBH     (BATCH*NHEAD) // 256
#define PATCHK  768          // 3*16*16

// ---------------------------------------------------------------------------
// Scratch (static device globals; no runtime allocation allowed)
// ---------------------------------------------------------------------------
__device__ float g_col  [TOK * PATCHK];       // im2col patches
__device__ float g_t    [TOK * DMODEL];       // residual stream
__device__ float g_ln   [TOK * DMODEL];       // layernorm out (reused)
__device__ float g_xz   [TOK * DMODEL];       // in_proj out
__device__ float g_xm   [TOK * DINNER];       // silu(conv(xm))  (= u for scan)
__device__ float g_xdbl [TOK * 48];           // x_proj out (dt_r | B | C)
__device__ float g_dt   [TOK * DINNER];       // softplus(dt)
__device__ float g_cat  [TOK * DMODEL];       // [y | silu(conv(z))]
__device__ float g_qkv  [TOK * 3 * DMODEL];
__device__ float g_q    [NBH * SEQL * HDIM];
__device__ float g_k    [NBH * SEQL * HDIM];
__device__ float g_v    [NBH * SEQL * HDIM];
__device__ float g_sc   [NBH * SEQL * SEQL]; // attention scores / probs
__device__ float g_obh  [NBH * SEQL * HDIM];
__device__ float g_o    [TOK * DMODEL];
__device__ float g_mlp  [TOK * 4 * DMODEL];
__device__ float g_feat [TOK * 1024];
__device__ float g_pool [BATCH * 1024];

// ---------------------------------------------------------------------------
// Activation helpers
// ---------------------------------------------------------------------------
__device__ __forceinline__ float act_gelu(float x) {
    float x3 = x * x * x;
    return 0.5f * x * (1.0f + tanhf(0.7978845608028654f * (x + 0.044715f * x3)));
}
__device__ __forceinline__ float act_softplus(float x) {
    return (x > 20.0f) ? x : log1pf(expf(x));
}
__device__ __forceinline__ float act_silu(float x) {
    return x / (1.0f + expf(-x));
}

// ---------------------------------------------------------------------------
// tf32 helpers
// ---------------------------------------------------------------------------
__device__ __forceinline__ uint32_t f2tf32(float x) {
    uint32_t r;
    asm("cvt.rna.tf32.f32 %0, %1;" : "=r"(r) : "f"(x));
    return r;
}
__device__ __forceinline__ void mma_tf32(float* d, const uint32_t* a, const uint32_t* b) {
    asm volatile(
        "mma.sync.aligned.m16n8k8.row.col.f32.tf32.tf32.f32 "
        "{%0,%1,%2,%3}, {%4,%5,%6,%7}, {%8,%9}, {%0,%1,%2,%3};\n"
        : "+f"(d[0]), "+f"(d[1]), "+f"(d[2]), "+f"(d[3])
        : "r"(a[0]), "r"(a[1]), "r"(a[2]), "r"(a[3]), "r"(b[0]), "r"(b[1]));
}

// ---------------------------------------------------------------------------
// Tensor-core tf32 GEMM: C[M,N] = A[M,K] * B[N,K]^T (+bias)(act)(+res)
// Requires M%128==0, N%128==0, K%16==0.
// CTA tile 128x128x16; 8 warps as 4(m) x 2(n); warp tile 32x64.
// smem row stride 136 -> fragment loads are bank-conflict-free.
// ---------------------------------------------------------------------------
template<int ACT, int HAS_BIAS, int HAS_RES>
__global__ __launch_bounds__(256)
void gemm_tc_kernel(const float* __restrict__ A, const float* __restrict__ B,
                    const float* __restrict__ bias, const float* __restrict__ res,
                    float* __restrict__ C, int M, int N, int K,
                    int lda, int ldb, int ldc)
{
    __shared__ uint32_t As[16][136];
    __shared__ uint32_t Bs[16][136];

    const int tid  = threadIdx.x;
    const int wid  = tid >> 5;
    const int lane = tid & 31;
    const int bm = blockIdx.y * 128;
    const int bn = blockIdx.x * 128;
    const int warp_m = (wid >> 1) * 32;   // 0,32,64,96
    const int warp_n = (wid & 1) * 64;    // 0,64
    const int tig = lane & 3;             // thread-in-group
    const int grp = lane >> 2;            // group id (0..7)

    float acc[2][8][4];
#pragma unroll
    for (int mt = 0; mt < 2; mt++)
#pragma unroll
        for (int nt = 0; nt < 8; nt++)
#pragma unroll
            for (int i = 0; i < 4; i++) acc[mt][nt][i] = 0.0f;

    const int lrow = tid >> 1;          // 0..127
    const int lkq  = (tid & 1) * 8;     // 0 or 8

    for (int k0 = 0; k0 < K; k0 += 16) {
        // A tile: 128 rows x 16 k
        {
            const float* ap = A + (long)(bm + lrow) * lda + k0 + lkq;
            float4 v0 = *(const float4*)ap;
            float4 v1 = *(const float4*)(ap + 4);
            As[lkq + 0][lrow] = f2tf32(v0.x);
            As[lkq + 1][lrow] = f2tf32(v0.y);
            As[lkq + 2][lrow] = f2tf32(v0.z);
            As[lkq + 3][lrow] = f2tf32(v0.w);
            As[lkq + 4][lrow] = f2tf32(v1.x);
            As[lkq + 5][lrow] = f2tf32(v1.y);
            As[lkq + 6][lrow] = f2tf32(v1.z);
            As[lkq + 7][lrow] = f2tf32(v1.w);
        }
        // B tile: 128 n-rows x 16 k  (B is [N,K])
        {
            const float* bp = B + (long)(bn + lrow) * ldb + k0 + lkq;
            float4 v0 = *(const float4*)bp;
            float4 v1 = *(const float4*)(bp + 4);
            Bs[lkq + 0][lrow] = f2tf32(v0.x);
            Bs[lkq + 1][lrow] = f2tf32(v0.y);
            Bs[lkq + 2][lrow] = f2tf32(v0.z);
            Bs[lkq + 3][lrow] = f2tf32(v0.w);
            Bs[lkq + 4][lrow] = f2tf32(v1.x);
            Bs[lkq + 5][lrow] = f2tf32(v1.y);
            Bs[lkq + 6][lrow] = f2tf32(v1.z);
            Bs[lkq + 7][lrow] = f2tf32(v1.w);
        }
        __syncthreads();

#pragma unroll
        for (int ks = 0; ks < 16; ks += 8) {
            uint32_t af[2][4];
            uint32_t bf[8][2];
#pragma unroll
            for (int mt = 0; mt < 2; mt++) {
                int m = warp_m + mt * 16;
                af[mt][0] = As[ks + tig    ][m + grp    ];
                af[mt][1] = As[ks + tig    ][m + grp + 8];
                af[mt][2] = As[ks + tig + 4][m + grp    ];
                af[mt][3] = As[ks + tig + 4][m + grp + 8];
            }
#pragma unroll
            for (int nt = 0; nt < 8; nt++) {
                int n = warp_n + nt * 8;
                bf[nt][0] = Bs[ks + tig    ][n + grp];
                bf[nt][1] = Bs[ks + tig + 4][n + grp];
            }
#pragma unroll
            for (int mt = 0; mt < 2; mt++)
#pragma unroll
                for (int nt = 0; nt < 8; nt++)
                    mma_tf32(acc[mt][nt], af[mt], bf[nt]);
        }
        __syncthreads();
    }

    // epilogue
#pragma unroll
    for (int mt = 0; mt < 2; mt++) {
        int r0 = bm + warp_m + mt * 16 + grp;
#pragma unroll
        for (int nt = 0; nt < 8; nt++) {
            int c0 = bn + warp_n + nt * 8 + tig * 2;
            float v0 = acc[mt][nt][0];
            float v1 = acc[mt][nt][1];
            float v2 = acc[mt][nt][2];
            float v3 = acc[mt][nt][3];
            if (HAS_BIAS) {
                float b0 = bias[c0], b1 = bias[c0 + 1];
                v0 += b0; v1 += b1; v2 += b0; v3 += b1;
            }
            if (ACT == 1) { v0 = act_gelu(v0); v1 = act_gelu(v1); v2 = act_gelu(v2); v3 = act_gelu(v3); }
            long o0 = (long)r0 * ldc + c0;
            long o1 = (long)(r0 + 8) * ldc + c0;
            if (HAS_RES) {
                v0 += res[o0]; v1 += res[o0 + 1];
                v2 += res[o1]; v3 += res[o1 + 1];
            }
            C[o0] = v0; C[o0 + 1] = v1;
            C[o1] = v2; C[o1 + 1] = v3;
        }
    }
}

// ---------------------------------------------------------------------------
// Generic fp32 GEMM (kept for odd shapes: x_proj, dt_proj, attention).
// ---------------------------------------------------------------------------
template<int TRANS_B, int ACT, int HAS_BIAS, int HAS_RES>
__global__ __launch_bounds__(256)
void gemm_kernel(const float* __restrict__ A, const float* __restrict__ B,
                 const float* __restrict__ bias, const float* __restrict__ res,
                 float* __restrict__ C,
                 int M, int N, int K, int lda, int ldb, int ldc,
                 long sA, long sB, long sC, float alpha)
{
    A += (long)blockIdx.z * sA;
    B += (long)blockIdx.z * sB;
    C += (long)blockIdx.z * sC;
    if (HAS_RES) res += (long)blockIdx.z * sC;

    __shared__ float As[16][65];
    __shared__ float Bs[16][65];

    const int tid = threadIdx.x;
    const int bm = blockIdx.y * 64;
    const int bn = blockIdx.x * 64;
    const int ty = tid >> 4;
    const int tx = tid & 15;

    float acc[4][4];
#pragma unroll
    for (int i = 0; i < 4; i++)
#pragma unroll
        for (int j = 0; j < 4; j++) acc[i][j] = 0.0f;

    const int nkt = (K + 15) >> 4;
    for (int kt = 0; kt < nkt; kt++) {
        const int k0 = kt << 4;
#pragma unroll
        for (int p = 0; p < 4; p++) {
            int r  = (tid >> 4) + p * 16;
            int gm = bm + r;
            int gk = k0 + (tid & 15);
            As[tid & 15][r] = (gm < M && gk < K) ? A[(long)gm * lda + gk] : 0.0f;
        }
        if (TRANS_B) {
#pragma unroll
            for (int p = 0; p < 4; p++) {
                int r  = (tid >> 4) + p * 16;
                int gn = bn + r;
                int gk = k0 + (tid & 15);
                Bs[tid & 15][r] = (gn < N && gk < K) ? B[(long)gn * ldb + gk] : 0.0f;
            }
        } else {
#pragma unroll
            for (int p = 0; p < 4; p++) {
                int kk = (tid >> 6) + p * 4;
                int nn = tid & 63;
                int gk = k0 + kk;
                int gn = bn + nn;
                Bs[kk][nn] = (gk < K && gn < N) ? B[(long)gk * ldb + gn] : 0.0f;
            }
        }
        __syncthreads();
#pragma unroll
        for (int kk = 0; kk < 16; kk++) {
            float a[4], b[4];
#pragma unroll
            for (int i = 0; i < 4; i++) a[i] = As[kk][ty * 4 + i];
#pragma unroll
            for (int j = 0; j < 4; j++) b[j] = Bs[kk][tx * 4 + j];
#pragma unroll
            for (int i = 0; i < 4; i++)
#pragma unroll
                for (int j = 0; j < 4; j++) acc[i][j] = fmaf(a[i], b[j], acc[i][j]);
        }
        __syncthreads();
    }

#pragma unroll
    for (int i = 0; i < 4; i++) {
        int gm = bm + ty * 4 + i;
        if (gm >= M) continue;
#pragma unroll
        for (int j = 0; j < 4; j++) {
            int gn = bn + tx * 4 + j;
            if (gn >= N) continue;
            float v = acc[i][j] * alpha;
            if (HAS_BIAS) v += bias[gn];
            if (ACT == 1) v = act_gelu(v);
            else if (ACT == 2) v = act_softplus(v);
            if (HAS_RES) v += res[(long)gm * ldc + gn];
            C[(long)gm * ldc + gn] = v;
        }
    }
}

// ---------------------------------------------------------------------------
// im2col for the 16x16/stride-16 patch conv.
// ---------------------------------------------------------------------------
__global__ void im2col_kernel(const float* __restrict__ x)
{
    int idx = blockIdx.x * blockDim.x + threadIdx.x;
    const int n = TOK * PATCHK;
    if (idx >= n) return;
    int tok  = idx / PATCHK;
    int cidx = idx - tok * PATCHK;
    int b  = tok / SEQL;
    int l  = tok - b * SEQL;
    int ph = l / 14, pw = l - ph * 14;
    int c  = cidx >> 8;
    int r  = cidx & 255;
    int kh = r >> 4, kw = r & 15;
    g_col[idx] = x[(((long)b * 3 + c) * 224 + (ph * 16 + kh)) * 224 + (pw * 16 + kw)];
}

// ---------------------------------------------------------------------------
// LayerNorm over last dim (512). One block (128 thr) per token.
// ---------------------------------------------------------------------------
__global__ __launch_bounds__(128)
void layernorm_kernel(const float* __restrict__ in, const float* __restrict__ g,
                      const float* __restrict__ b, float* __restrict__ out)
{
    int tok = blockIdx.x;
    int tid = threadIdx.x;
    const float* row = in + (long)tok * DMODEL;
    float v[4];
    float s = 0.0f, s2 = 0.0f;
#pragma unroll
    for (int i = 0; i < 4; i++) {
        v[i] = row[tid + i * 128];
        s  += v[i];
        s2 += v[i] * v[i];
    }
#pragma unroll
    for (int o = 16; o > 0; o >>= 1) {
        s  += __shfl_xor_sync(0xffffffffu, s,  o);
        s2 += __shfl_xor_sync(0xffffffffu, s2, o);
    }
    __shared__ float ss[4], ss2[4];
    int warp = tid >> 5, lane = tid & 31;
    if (lane == 0) { ss[warp] = s; ss2[warp] = s2; }
    __syncthreads();
    s  = ss[0] + ss[1] + ss[2] + ss[3];
    s2 = ss2[0] + ss2[1] + ss2[2] + ss2[3];
    float mean = s * (1.0f / DMODEL);
    float var  = s2 * (1.0f / DMODEL) - mean * mean;
    float inv  = rsqrtf(var + 1e-6f);
    float* orow = out + (long)tok * DMODEL;
#pragma unroll
    for (int i = 0; i < 4; i++) {
        int col = tid + i * 128;
        orow[col] = (v[i] - mean) * inv * g[col] + b[col];
    }
}

// ---------------------------------------------------------------------------
// Causal depthwise conv (width 4) + SiLU for both halves of xz.
// ---------------------------------------------------------------------------
__global__ void dwconv_silu_kernel(const float* __restrict__ wx, const float* __restrict__ bx,
                                   const float* __restrict__ wz, const float* __restrict__ bz)
{
    int idx = blockIdx.x * blockDim.x + threadIdx.x;
    const int n = TOK * DINNER;
    if (idx >= 2 * n) return;
    int half = idx >= n;
    int id   = half ? idx - n : idx;
    int tok  = id >> 8;
    int c    = id & 255;
    int b    = tok / SEQL;
    int l    = tok - b * SEQL;
    const float* w  = half ? wz : wx;
    const float* bb = half ? bz : bx;
    int off = half ? DINNER : 0;
    float sum = bb[c];
#pragma unroll
    for (int k = 0; k < 4; k++) {
        int ll = l - 3 + k;
        if (ll >= 0)
            sum += g_xz[((long)(b * SEQL + ll)) * DMODEL + off + c] * w[c * 4 + k];
    }
    sum = act_silu(sum);
    if (half) g_cat[(long)tok * DMODEL + DINNER + c] = sum;
    else      g_xm[(long)tok * DINNER + c] = sum;
}

// ---------------------------------------------------------------------------
// Selective scan. Thread per (b, d, n): 16 lanes per (b,d) reduce y via shfl.
// ---------------------------------------------------------------------------
__global__ __launch_bounds__(256)
void scan_kernel(const float* __restrict__ A_log, const float* __restrict__ Dp)
{
    int b    = blockIdx.x >> 4;
    int dblk = blockIdx.x & 15;
    int nidx = threadIdx.x & 15;
    int d    = dblk * 16 + (threadIdx.x >> 4);

    float An = -expf(A_log[d * DSTATE + nidx]);
    float Dd = Dp[d];
    float h  = 0.0f;
    const long tokbase = (long)b * SEQL;
    for (int l = 0; l < SEQL; l++) {
        long t   = tokbase + l;
        float dtv = g_dt[t * DINNER + d];
        float u   = g_xm[t * DINNER + d];
        float Bn  = g_xdbl[t * 48 + DTRANK + nidx];
        float Cn  = g_xdbl[t * 48 + DTRANK + DSTATE + nidx];
        h = __expf(dtv * An) * h + dtv * u * Bn;
        float y = h * Cn;
        y += __shfl_xor_sync(0xffffffffu, y, 8);
        y += __shfl_xor_sync(0xffffffffu, y, 4);
        y += __shfl_xor_sync(0xffffffffu, y, 2);
        y += __shfl_xor_sync(0xffffffffu, y, 1);
        if (nidx == 0)
            g_cat[t * DMODEL + d] = y + u * Dd;
    }
}

// ---------------------------------------------------------------------------
// qkv split: [tok, 3, 8, 64] -> q/k/v [bh, 196, 64]
// ---------------------------------------------------------------------------
__global__ void split_qkv_kernel()
{
    int idx = blockIdx.x * blockDim.x + threadIdx.x;
    const int n = TOK * 3 * DMODEL;
    if (idx >= n) return;
    int tok = idx / (3 * DMODEL);
    int r   = idx - tok * (3 * DMODEL);
    int which = r / DMODEL;
    int h  = (r % DMODEL) / HDIM;
    int dd = r % HDIM;
    int b = tok / SEQL, l = tok - b * SEQL;
    long dst = ((long)(b * NHEAD + h) * SEQL + l) * HDIM + dd;
    float val = g_qkv[idx];
    if (which == 0)      g_q[dst] = val;
    else if (which == 1) g_k[dst] = val;
    else                 g_v[dst] = val;
}

// ---------------------------------------------------------------------------
// Row softmax over 196 cols.
// ---------------------------------------------------------------------------
__global__ __launch_bounds__(128)
void softmax_kernel()
{
    long rowbase = (long)blockIdx.x * SEQL;
    int tid = threadIdx.x;
    float m = -1e30f;
    for (int j = tid; j < SEQL; j += 128) m = fmaxf(m, g_sc[rowbase + j]);
#pragma unroll
    for (int o = 16; o > 0; o >>= 1) m = fmaxf(m, __shfl_xor_sync(0xffffffffu, m, o));
    __shared__ float sm[4], ssum[4];
    int warp = tid >> 5, lane = tid & 31;
    if (lane == 0) sm[warp] = m;
    __syncthreads();
    m = fmaxf(fmaxf(sm[0], sm[1]), fmaxf(sm[2], sm[3]));
    float s = 0.0f;
    for (int j = tid; j < SEQL; j += 128) {
        float e = __expf(g_sc[rowbase + j] - m);
        g_sc[rowbase + j] = e;
        s += e;
    }
#pragma unroll
    for (int o = 16; o > 0; o >>= 1) s += __shfl_xor_sync(0xffffffffu, s, o);
    if (lane == 0) ssum[warp] = s;
    __syncthreads();
    s = ssum[0] + ssum[1] + ssum[2] + ssum[3];
    float inv = 1.0f / s;
    for (int j = tid; j < SEQL; j += 128) g_sc[rowbase + j] *= inv;
}

// ---------------------------------------------------------------------------
// Merge attention output: [bh, 196, 64] -> [tok, 512]
// ---------------------------------------------------------------------------
__global__ void merge_o_kernel()
{
    int idx = blockIdx.x * blockDim.x + threadIdx.x;
    const int n = TOK * DMODEL;
    if (idx >= n) return;
    int tok = idx >> 9;
    int ch  = idx & 511;
    int h = ch >> 6, dd = ch & 63;
    int b = tok / SEQL, l = tok - b * SEQL;
    g_o[idx] = g_obh[((long)(b * NHEAD + h) * SEQL + l) * HDIM + dd];
}

// ---------------------------------------------------------------------------
// Mean pool over L.
// ---------------------------------------------------------------------------
__global__ __launch_bounds__(256)
void pool_kernel()
{
    int b = blockIdx.x;
    for (int j = threadIdx.x; j < 1024; j += blockDim.x) {
        float s = 0.0f;
        const float* base = g_feat + (long)b * SEQL * 1024 + j;
        for (int l = 0; l < SEQL; l++) s += base[(long)l * 1024];
        g_pool[b * 1024 + j] = s * (1.0f / SEQL);
    }
}

// ---------------------------------------------------------------------------
// Final fc: [32,1024] @ [4,1024]^T + b -> [32,4]
// ---------------------------------------------------------------------------
__global__ __launch_bounds__(128)
void fc_kernel(const float* __restrict__ fc_w, const float* __restrict__ fc_b,
               float* __restrict__ out)
{
    int o = threadIdx.x;
    if (o >= BATCH * 4) return;
    int b = o >> 2, c = o & 3;
    float s = fc_b[c];
    const float* p = g_pool + b * 1024;
    const float* w = fc_w + c * 1024;
    for (int k = 0; k < 1024; k++) s = fmaf(p[k], w[k], s);
    out[o] = s;
}

// ---------------------------------------------------------------------------
// Launch
// ---------------------------------------------------------------------------
static inline dim3 gemm_grid(int M, int N, int batch) {
    return dim3((N + 63) / 64, (M + 63) / 64, batch);
}
static inline dim3 tc_grid(int M, int N) {
    return dim3(N / 128, M / 128, 1);
}

extern "C" void kernel_launch(void* const* d_in, const int* in_sizes, int n_in,
                              void* d_out, int out_size)
{
    const float* x          = (const float*)d_in[0];
    const float* patch_w    = (const float*)d_in[1];
    const float* patch_b    = (const float*)d_in[2];
    const float* ln1_g      = (const float*)d_in[3];
    const float* ln1_b      = (const float*)d_in[4];
    const float* in_proj_w  = (const float*)d_in[5];
    const float* convx_w    = (const float*)d_in[6];
    const float* convx_b    = (const float*)d_in[7];
    const float* convz_w    = (const float*)d_in[8];
    const float* convz_b    = (const float*)d_in[9];
    const float* x_proj_w   = (const float*)d_in[10];
    const float* dt_proj_w  = (const float*)d_in[11];
    const float* dt_proj_b  = (const float*)d_in[12];
    const float* A_log      = (const float*)d_in[13];
    const float* Dp         = (const float*)d_in[14];
    const float* out_proj_w = (const float*)d_in[15];
    const float* ln2_g      = (const float*)d_in[16];
    const float* ln2_b      = (const float*)d_in[17];
    const float* qkv_w      = (const float*)d_in[18];
    const float* attn_proj_w= (const float*)d_in[19];
    const float* ln3_g      = (const float*)d_in[20];
    const float* ln3_b      = (const float*)d_in[21];
    const float* mlp_w1     = (const float*)d_in[22];
    const float* mlp_b1     = (const float*)d_in[23];
    const float* mlp_w2     = (const float*)d_in[24];
    const float* mlp_b2     = (const float*)d_in[25];
    const float* head_w     = (const float*)d_in[26];
    const float* head_b     = (const float*)d_in[27];
    const float* fc_w       = (const float*)d_in[28];
    const float* fc_b       = (const float*)d_in[29];
    float* out = (float*)d_out;

    float *p_col, *p_t, *p_ln, *p_xz, *p_xm, *p_xdbl, *p_dt, *p_cat, *p_qkv;
    float *p_q, *p_k, *p_v, *p_sc, *p_obh, *p_o, *p_mlp, *p_feat;
    cudaGetSymbolAddress((void**)&p_col,  g_col);
    cudaGetSymbolAddress((void**)&p_t,    g_t);
    cudaGetSymbolAddress((void**)&p_ln,   g_ln);
    cudaGetSymbolAddress((void**)&p_xz,   g_xz);
    cudaGetSymbolAddress((void**)&p_xm,   g_xm);
    cudaGetSymbolAddress((void**)&p_xdbl, g_xdbl);
    cudaGetSymbolAddress((void**)&p_dt,   g_dt);
    cudaGetSymbolAddress((void**)&p_cat,  g_cat);
    cudaGetSymbolAddress((void**)&p_qkv,  g_qkv);
    cudaGetSymbolAddress((void**)&p_q,    g_q);
    cudaGetSymbolAddress((void**)&p_k,    g_k);
    cudaGetSymbolAddress((void**)&p_v,    g_v);
    cudaGetSymbolAddress((void**)&p_sc,   g_sc);
    cudaGetSymbolAddress((void**)&p_obh,  g_obh);
    cudaGetSymbolAddress((void**)&p_o,    g_o);
    cudaGetSymbolAddress((void**)&p_mlp,  g_mlp);
    cudaGetSymbolAddress((void**)&p_feat, g_feat);

    // 1) im2col
    {
        int n = TOK * PATCHK;
        im2col_kernel<<<(n + 255) / 256, 256>>>(x);
    }
    // 2) patch embed: [6272,768] x [512,768]^T + patch_b -> g_t  (TC)
    gemm_tc_kernel<0,1,0><<<tc_grid(TOK, DMODEL), 256>>>(
        p_col, patch_w, patch_b, nullptr, p_t,
        TOK, DMODEL, PATCHK, PATCHK, PATCHK, DMODEL);
    // 3) LN1
    layernorm_kernel<<<TOK, 128>>>(p_t, ln1_g, ln1_b, p_ln);
    // 4) in_proj (TC)
    gemm_tc_kernel<0,0,0><<<tc_grid(TOK, DMODEL), 256>>>(
        p_ln, in_proj_w, nullptr, nullptr, p_xz,
        TOK, DMODEL, DMODEL, DMODEL, DMODEL, DMODEL);
    // 5) causal dwconv + silu
    {
        int n = 2 * TOK * DINNER;
        dwconv_silu_kernel<<<(n + 255) / 256, 256>>>(convx_w, convx_b, convz_w, convz_b);
    }
    // 6) x_proj: [6272,256] x [48,256]^T (fp32 small)
    gemm_kernel<1,0,0,0><<<gemm_grid(TOK, 48, 1), 256>>>(
        p_xm, x_proj_w, nullptr, nullptr, p_xdbl,
        TOK, 48, DINNER, DINNER, DINNER, 48, 0, 0, 0, 1.0f);
    // 7) dt_proj + softplus (fp32 small K)
    gemm_kernel<1,2,1,0><<<gemm_grid(TOK, DINNER, 1), 256>>>(
        p_xdbl, dt_proj_w, dt_proj_b, nullptr, p_dt,
        TOK, DINNER, DTRANK, 48, DTRANK, DINNER, 0, 0, 0, 1.0f);
    // 8) selective scan
    scan_kernel<<<BATCH * 16, 256>>>(A_log, Dp);
    // 9) out_proj + residual (TC)
    gemm_tc_kernel<0,0,1><<<tc_grid(TOK, DMODEL), 256>>>(
        p_cat, out_proj_w, nullptr, p_t, p_t,
        TOK, DMODEL, DMODEL, DMODEL, DMODEL, DMODEL);
    // 10) LN2
    layernorm_kernel<<<TOK, 128>>>(p_t, ln2_g, ln2_b, p_ln);
    // 11) qkv (TC)
    gemm_tc_kernel<0,0,0><<<tc_grid(TOK, 3 * DMODEL), 256>>>(
        p_ln, qkv_w, nullptr, nullptr, p_qkv,
        TOK, 3 * DMODEL, DMODEL, DMODEL, DMODEL, 3 * DMODEL);
    // 12) split qkv
    {
        int n = TOK * 3 * DMODEL;
        split_qkv_kernel<<<(n + 255) / 256, 256>>>();
    }
    // 13) scores = Q K^T / 8 (batched fp32)
    gemm_kernel<1,0,0,0><<<gemm_grid(SEQL, SEQL, NBH), 256>>>(
        p_q, p_k, nullptr, nullptr, p_sc,
        SEQL, SEQL, HDIM, HDIM, HDIM, SEQL,
        (long)SEQL * HDIM, (long)SEQL * HDIM, (long)SEQL * SEQL, 0.125f);
    // 14) softmax rows
    softmax_kernel<<<NBH * SEQL, 128>>>();
    // 15) O = P V (batched fp32, NN)
    gemm_kernel<0,0,0,0><<<gemm_grid(SEQL, HDIM, NBH), 256>>>(
        p_sc, p_v, nullptr, nullptr, p_obh,
        SEQL, HDIM, SEQL, SEQL, HDIM, HDIM,
        (long)SEQL * SEQL, (long)SEQL * HDIM, (long)SEQL * HDIM, 1.0f);
    // 16) merge O
    {
        int n = TOK * DMODEL;
        merge_o_kernel<<<(n + 255) / 256, 256>>>();
    }
    // 17) attn_proj + residual (TC)
    gemm_tc_kernel<0,0,1><<<tc_grid(TOK, DMODEL), 256>>>(
        p_o, attn_proj_w, nullptr, p_t, p_t,
        TOK, DMODEL, DMODEL, DMODEL, DMODEL, DMODEL);
    // 18) LN3
    layernorm_kernel<<<TOK, 128>>>(p_t, ln3_g, ln3_b, p_ln);
    // 19) mlp1 + gelu (TC)
    gemm_tc_kernel<1,1,0><<<tc_grid(TOK, 4 * DMODEL), 256>>>(
        p_ln, mlp_w1, mlp_b1, nullptr, p_mlp,
        TOK, 4 * DMODEL, DMODEL, DMODEL, DMODEL, 4 * DMODEL);
    // 20) mlp2 + b2 + residual (TC)
    gemm_tc_kernel<0,1,1><<<tc_grid(TOK, DMODEL), 256>>>(
        p_mlp, mlp_w2, mlp_b2, p_t, p_t,
        TOK, DMODEL, 4 * DMODEL, 4 * DMODEL, 4 * DMODEL, DMODEL);
    // 21) head (TC)
    gemm_tc_kernel<0,1,0><<<tc_grid(TOK, 1024), 256>>>(
        p_t, head_w, head_b, nullptr, p_feat,
        TOK, 1024, DMODEL, DMODEL, DMODEL, 1024);
    // 22) mean pool
    pool_kernel<<<BATCH, 256>>>();
    // 23) fc
    fc_kernel<<<1, 128>>>(fc_w, fc_b, out);
}

// round 5
// speedup vs baseline: 2.6413x; 1.0862x over previous
#include <cuda_runtime.h>
#include <cuda_bf16.h>
#include <math.h>
#include <stdint.h>

// ---------------------------------------------------------------------------
// Problem constants
// ---------------------------------------------------------------------------
#define BATCH   32
#define SEQL    196          // 14*14 patches
#define TOK     (BATCH*SEQL) // 6272
#define DMODEL  512
#define DINNER  256
#define DSTATE  16
#define DTRANK  16
#define NHEAD   8
#define HDIM    64
#define NBH     (BATCH*NHEAD) // 256
#define PATCHK  768          // 3*16*16

// ---------------------------------------------------------------------------
// Scratch (static device globals; no runtime allocation allowed)
// ---------------------------------------------------------------------------
__device__ float g_col  [TOK * PATCHK];
__device__ float g_t    [TOK * DMODEL];
__device__ float g_ln   [TOK * DMODEL];
__device__ float g_xz   [TOK * DMODEL];
__device__ float g_xm   [TOK * DINNER];
__device__ float g_xdbl [TOK * 48];
__device__ float g_dt   [TOK * DINNER];
__device__ float g_cat  [TOK * DMODEL];
__device__ float g_qkv  [TOK * 3 * DMODEL];
__device__ float g_q    [NBH * SEQL * HDIM];
__device__ float g_k    [NBH * SEQL * HDIM];
__device__ float g_v    [NBH * SEQL * HDIM];
__device__ float g_sc   [NBH * SEQL * SEQL];
__device__ float g_obh  [NBH * SEQL * HDIM];
__device__ float g_o    [TOK * DMODEL];
__device__ float g_mlp  [TOK * 4 * DMODEL];
__device__ float g_feat [TOK * 1024];
__device__ float g_pool [BATCH * 1024];

// ---------------------------------------------------------------------------
// Activation helpers
// ---------------------------------------------------------------------------
__device__ __forceinline__ float act_gelu(float x) {
    float x3 = x * x * x;
    return 0.5f * x * (1.0f + tanhf(0.7978845608028654f * (x + 0.044715f * x3)));
}
__device__ __forceinline__ float act_softplus(float x) {
    return (x > 20.0f) ? x : log1pf(expf(x));
}
__device__ __forceinline__ float act_silu(float x) {
    return x / (1.0f + expf(-x));
}

// ---------------------------------------------------------------------------
// tf32 / async-copy helpers
// ---------------------------------------------------------------------------
__device__ __forceinline__ uint32_t f2tf32(float x) {
    uint32_t r;
    asm("cvt.rna.tf32.f32 %0, %1;" : "=r"(r) : "f"(x));
    return r;
}
__device__ __forceinline__ void mma_tf32(float* d, const uint32_t* a, const uint32_t* b) {
    asm volatile(
        "mma.sync.aligned.m16n8k8.row.col.f32.tf32.tf32.f32 "
        "{%0,%1,%2,%3}, {%4,%5,%6,%7}, {%8,%9}, {%0,%1,%2,%3};\n"
        : "+f"(d[0]), "+f"(d[1]), "+f"(d[2]), "+f"(d[3])
        : "r"(a[0]), "r"(a[1]), "r"(a[2]), "r"(a[3]), "r"(b[0]), "r"(b[1]));
}
__device__ __forceinline__ void cp_async16(uint32_t saddr, const void* gptr) {
    asm volatile("cp.async.cg.shared.global [%0], [%1], 16;\n" :: "r"(saddr), "l"(gptr));
}
__device__ __forceinline__ void cp_commit() {
    asm volatile("cp.async.commit_group;\n");
}
template<int N>
__device__ __forceinline__ void cp_wait() {
    asm volatile("cp.async.wait_group %0;\n" :: "n"(N));
}

// ---------------------------------------------------------------------------
// Pipelined tensor-core tf32 GEMM: C[M,N] = A[M,K] * B[N,K]^T (+bias)(act)(+res)
// Requires M%128==0, N%128==0, K%16==0, K>=48.
// CTA tile 128x128x16; 3-stage cp.async pipeline; 8 warps 4(m)x2(n), warp 32x64.
// smem fp32 [stage][row(128)][k(16), stride 20] -> conflict-free fragment LDS.
// ---------------------------------------------------------------------------
#define TC_STAGES 3
#define TC_KSTR   20
#define TC_STAGE_FLOATS (128 * TC_KSTR)
#define TC_SMEM_BYTES (2 * TC_STAGES * TC_STAGE_FLOATS * 4)

template<int ACT, int HAS_BIAS, int HAS_RES>
__global__ __launch_bounds__(256)
void gemm_tc_kernel(const float* __restrict__ A, const float* __restrict__ B,
                    const float* __restrict__ bias, const float* __restrict__ res,
                    float* __restrict__ C, int M, int N, int K,
                    int lda, int ldb, int ldc)
{
    extern __shared__ float smem[];
    float* As = smem;                                  // [S][128][20]
    float* Bs = smem + TC_STAGES * TC_STAGE_FLOATS;    // [S][128][20]

    const int tid  = threadIdx.x;
    const int wid  = tid >> 5;
    const int lane = tid & 31;
    const int bm = blockIdx.y * 128;
    const int bn = blockIdx.x * 128;
    const int warp_m = (wid >> 1) * 32;
    const int warp_n = (wid & 1) * 64;
    const int tig = lane & 3;
    const int grp = lane >> 2;

    // load mapping: item i in [0,512): row = i>>2, kq = (i&3)*4
    const int r0 = tid >> 2,         kq0 = (tid & 3) * 4;
    const int r1 = (tid + 256) >> 2, kq1 = ((tid + 256) & 3) * 4;

    float acc[2][8][4];
#pragma unroll
    for (int mt = 0; mt < 2; mt++)
#pragma unroll
        for (int nt = 0; nt < 8; nt++)
#pragma unroll
            for (int i = 0; i < 4; i++) acc[mt][nt][i] = 0.0f;

    const int NK = K >> 4;

    auto load_stage = [&](int s, int kt) {
        const int k0 = kt << 4;
        float* as = As + s * TC_STAGE_FLOATS;
        float* bs = Bs + s * TC_STAGE_FLOATS;
        {
            const float* ga = A + (long)(bm + r0) * lda + k0 + kq0;
            cp_async16((uint32_t)__cvta_generic_to_shared(as + r0 * TC_KSTR + kq0), ga);
            const float* gb = B + (long)(bn + r0) * ldb + k0 + kq0;
            cp_async16((uint32_t)__cvta_generic_to_shared(bs + r0 * TC_KSTR + kq0), gb);
        }
        {
            const float* ga = A + (long)(bm + r1) * lda + k0 + kq1;
            cp_async16((uint32_t)__cvta_generic_to_shared(as + r1 * TC_KSTR + kq1), ga);
            const float* gb = B + (long)(bn + r1) * ldb + k0 + kq1;
            cp_async16((uint32_t)__cvta_generic_to_shared(bs + r1 * TC_KSTR + kq1), gb);
        }
    };

    // prologue: stages 0..S-2
    load_stage(0, 0); cp_commit();
    load_stage(1, 1); cp_commit();

    for (int kt = 0; kt < NK; kt++) {
        cp_wait<TC_STAGES - 2>();
        __syncthreads();

        // issue next stage load (empty commit when past the end keeps counts consistent)
        {
            int nk = kt + TC_STAGES - 1;
            if (nk < NK) load_stage(nk % TC_STAGES, nk);
            cp_commit();
        }

        const int cs = kt % TC_STAGES;
        const float* as = As + cs * TC_STAGE_FLOATS;
        const float* bs = Bs + cs * TC_STAGE_FLOATS;

#pragma unroll
        for (int ks = 0; ks < 16; ks += 8) {
            uint32_t af[2][4];
            uint32_t bf[8][2];
#pragma unroll
            for (int mt = 0; mt < 2; mt++) {
                int m = warp_m + mt * 16;
                af[mt][0] = f2tf32(as[(m + grp    ) * TC_KSTR + ks + tig    ]);
                af[mt][1] = f2tf32(as[(m + grp + 8) * TC_KSTR + ks + tig    ]);
                af[mt][2] = f2tf32(as[(m + grp    ) * TC_KSTR + ks + tig + 4]);
                af[mt][3] = f2tf32(as[(m + grp + 8) * TC_KSTR + ks + tig + 4]);
            }
#pragma unroll
            for (int nt = 0; nt < 8; nt++) {
                int n = warp_n + nt * 8;
                bf[nt][0] = f2tf32(bs[(n + grp) * TC_KSTR + ks + tig    ]);
                bf[nt][1] = f2tf32(bs[(n + grp) * TC_KSTR + ks + tig + 4]);
            }
#pragma unroll
            for (int mt = 0; mt < 2; mt++)
#pragma unroll
                for (int nt = 0; nt < 8; nt++)
                    mma_tf32(acc[mt][nt], af[mt], bf[nt]);
        }
        __syncthreads();
    }

    // epilogue
#pragma unroll
    for (int mt = 0; mt < 2; mt++) {
        int r = bm + warp_m + mt * 16 + grp;
#pragma unroll
        for (int nt = 0; nt < 8; nt++) {
            int c0 = bn + warp_n + nt * 8 + tig * 2;
            float v0 = acc[mt][nt][0];
            float v1 = acc[mt][nt][1];
            float v2 = acc[mt][nt][2];
            float v3 = acc[mt][nt][3];
            if (HAS_BIAS) {
                float b0 = bias[c0], b1 = bias[c0 + 1];
                v0 += b0; v1 += b1; v2 += b0; v3 += b1;
            }
            if (ACT == 1) { v0 = act_gelu(v0); v1 = act_gelu(v1); v2 = act_gelu(v2); v3 = act_gelu(v3); }
            long o0 = (long)r * ldc + c0;
            long o1 = (long)(r + 8) * ldc + c0;
            if (HAS_RES) {
                v0 += res[o0]; v1 += res[o0 + 1];
                v2 += res[o1]; v3 += res[o1 + 1];
            }
            C[o0] = v0; C[o0 + 1] = v1;
            C[o1] = v2; C[o1 + 1] = v3;
        }
    }
}

// ---------------------------------------------------------------------------
// Generic fp32 GEMM (odd shapes: x_proj, dt_proj, attention).
// ---------------------------------------------------------------------------
template<int TRANS_B, int ACT, int HAS_BIAS, int HAS_RES>
__global__ __launch_bounds__(256)
void gemm_kernel(const float* __restrict__ A, const float* __restrict__ B,
                 const float* __restrict__ bias, const float* __restrict__ res,
                 float* __restrict__ C,
                 int M, int N, int K, int lda, int ldb, int ldc,
                 long sA, long sB, long sC, float alpha)
{
    A += (long)blockIdx.z * sA;
    B += (long)blockIdx.z * sB;
    C += (long)blockIdx.z * sC;
    if (HAS_RES) res += (long)blockIdx.z * sC;

    __shared__ float As[16][65];
    __shared__ float Bs[16][65];

    const int tid = threadIdx.x;
    const int bm = blockIdx.y * 64;
    const int bn = blockIdx.x * 64;
    const int ty = tid >> 4;
    const int tx = tid & 15;

    float acc[4][4];
#pragma unroll
    for (int i = 0; i < 4; i++)
#pragma unroll
        for (int j = 0; j < 4; j++) acc[i][j] = 0.0f;

    const int nkt = (K + 15) >> 4;
    for (int kt = 0; kt < nkt; kt++) {
        const int k0 = kt << 4;
#pragma unroll
        for (int p = 0; p < 4; p++) {
            int r  = (tid >> 4) + p * 16;
            int gm = bm + r;
            int gk = k0 + (tid & 15);
            As[tid & 15][r] = (gm < M && gk < K) ? A[(long)gm * lda + gk] : 0.0f;
        }
        if (TRANS_B) {
#pragma unroll
            for (int p = 0; p < 4; p++) {
                int r  = (tid >> 4) + p * 16;
                int gn = bn + r;
                int gk = k0 + (tid & 15);
                Bs[tid & 15][r] = (gn < N && gk < K) ? B[(long)gn * ldb + gk] : 0.0f;
            }
        } else {
#pragma unroll
            for (int p = 0; p < 4; p++) {
                int kk = (tid >> 6) + p * 4;
                int nn = tid & 63;
                int gk = k0 + kk;
                int gn = bn + nn;
                Bs[kk][nn] = (gk < K && gn < N) ? B[(long)gk * ldb + gn] : 0.0f;
            }
        }
        __syncthreads();
#pragma unroll
        for (int kk = 0; kk < 16; kk++) {
            float a[4], b[4];
#pragma unroll
            for (int i = 0; i < 4; i++) a[i] = As[kk][ty * 4 + i];
#pragma unroll
            for (int j = 0; j < 4; j++) b[j] = Bs[kk][tx * 4 + j];
#pragma unroll
            for (int i = 0; i < 4; i++)
#pragma unroll
                for (int j = 0; j < 4; j++) acc[i][j] = fmaf(a[i], b[j], acc[i][j]);
        }
        __syncthreads();
    }

#pragma unroll
    for (int i = 0; i < 4; i++) {
        int gm = bm + ty * 4 + i;
        if (gm >= M) continue;
#pragma unroll
        for (int j = 0; j < 4; j++) {
            int gn = bn + tx * 4 + j;
            if (gn >= N) continue;
            float v = acc[i][j] * alpha;
            if (HAS_BIAS) v += bias[gn];
            if (ACT == 1) v = act_gelu(v);
            else if (ACT == 2) v = act_softplus(v);
            if (HAS_RES) v += res[(long)gm * ldc + gn];
            C[(long)gm * ldc + gn] = v;
        }
    }
}

// ---------------------------------------------------------------------------
// im2col for the 16x16/stride-16 patch conv.
// ---------------------------------------------------------------------------
__global__ void im2col_kernel(const float* __restrict__ x)
{
    int idx = blockIdx.x * blockDim.x + threadIdx.x;
    const int n = TOK * PATCHK;
    if (idx >= n) return;
    int tok  = idx / PATCHK;
    int cidx = idx - tok * PATCHK;
    int b  = tok / SEQL;
    int l  = tok - b * SEQL;
    int ph = l / 14, pw = l - ph * 14;
    int c  = cidx >> 8;
    int r  = cidx & 255;
    int kh = r >> 4, kw = r & 15;
    g_col[idx] = x[(((long)b * 3 + c) * 224 + (ph * 16 + kh)) * 224 + (pw * 16 + kw)];
}

// ---------------------------------------------------------------------------
// LayerNorm over last dim (512).
// ---------------------------------------------------------------------------
__global__ __launch_bounds__(128)
void layernorm_kernel(const float* __restrict__ in, const float* __restrict__ g,
                      const float* __restrict__ b, float* __restrict__ out)
{
    int tok = blockIdx.x;
    int tid = threadIdx.x;
    const float* row = in + (long)tok * DMODEL;
    float v[4];
    float s = 0.0f, s2 = 0.0f;
#pragma unroll
    for (int i = 0; i < 4; i++) {
        v[i] = row[tid + i * 128];
        s  += v[i];
        s2 += v[i] * v[i];
    }
#pragma unroll
    for (int o = 16; o > 0; o >>= 1) {
        s  += __shfl_xor_sync(0xffffffffu, s,  o);
        s2 += __shfl_xor_sync(0xffffffffu, s2, o);
    }
    __shared__ float ss[4], ss2[4];
    int warp = tid >> 5, lane = tid & 31;
    if (lane == 0) { ss[warp] = s; ss2[warp] = s2; }
    __syncthreads();
    s  = ss[0] + ss[1] + ss[2] + ss[3];
    s2 = ss2[0] + ss2[1] + ss2[2] + ss2[3];
    float mean = s * (1.0f / DMODEL);
    float var  = s2 * (1.0f / DMODEL) - mean * mean;
    float inv  = rsqrtf(var + 1e-6f);
    float* orow = out + (long)tok * DMODEL;
#pragma unroll
    for (int i = 0; i < 4; i++) {
        int col = tid + i * 128;
        orow[col] = (v[i] - mean) * inv * g[col] + b[col];
    }
}

// ---------------------------------------------------------------------------
// Causal depthwise conv (width 4) + SiLU for both halves of xz.
// ---------------------------------------------------------------------------
__global__ void dwconv_silu_kernel(const float* __restrict__ wx, const float* __restrict__ bx,
                                   const float* __restrict__ wz, const float* __restrict__ bz)
{
    int idx = blockIdx.x * blockDim.x + threadIdx.x;
    const int n = TOK * DINNER;
    if (idx >= 2 * n) return;
    int half = idx >= n;
    int id   = half ? idx - n : idx;
    int tok  = id >> 8;
    int c    = id & 255;
    int b    = tok / SEQL;
    int l    = tok - b * SEQL;
    const float* w  = half ? wz : wx;
    const float* bb = half ? bz : bx;
    int off = half ? DINNER : 0;
    float sum = bb[c];
#pragma unroll
    for (int k = 0; k < 4; k++) {
        int ll = l - 3 + k;
        if (ll >= 0)
            sum += g_xz[((long)(b * SEQL + ll)) * DMODEL + off + c] * w[c * 4 + k];
    }
    sum = act_silu(sum);
    if (half) g_cat[(long)tok * DMODEL + DINNER + c] = sum;
    else      g_xm[(long)tok * DINNER + c] = sum;
}

// ---------------------------------------------------------------------------
// Selective scan.
// ---------------------------------------------------------------------------
__global__ __launch_bounds__(256)
void scan_kernel(const float* __restrict__ A_log, const float* __restrict__ Dp)
{
    int b    = blockIdx.x >> 4;
    int dblk = blockIdx.x & 15;
    int nidx = threadIdx.x & 15;
    int d    = dblk * 16 + (threadIdx.x >> 4);

    float An = -expf(A_log[d * DSTATE + nidx]);
    float Dd = Dp[d];
    float h  = 0.0f;
    const long tokbase = (long)b * SEQL;
    for (int l = 0; l < SEQL; l++) {
        long t   = tokbase + l;
        float dtv = g_dt[t * DINNER + d];
        float u   = g_xm[t * DINNER + d];
        float Bn  = g_xdbl[t * 48 + DTRANK + nidx];
        float Cn  = g_xdbl[t * 48 + DTRANK + DSTATE + nidx];
        h = __expf(dtv * An) * h + dtv * u * Bn;
        float y = h * Cn;
        y += __shfl_xor_sync(0xffffffffu, y, 8);
        y += __shfl_xor_sync(0xffffffffu, y, 4);
        y += __shfl_xor_sync(0xffffffffu, y, 2);
        y += __shfl_xor_sync(0xffffffffu, y, 1);
        if (nidx == 0)
            g_cat[t * DMODEL + d] = y + u * Dd;
    }
}

// ---------------------------------------------------------------------------
// qkv split: [tok, 3, 8, 64] -> q/k/v [bh, 196, 64]
// ---------------------------------------------------------------------------
__global__ void split_qkv_kernel()
{
    int idx = blockIdx.x * blockDim.x + threadIdx.x;
    const int n = TOK * 3 * DMODEL;
    if (idx >= n) return;
    int tok = idx / (3 * DMODEL);
    int r   = idx - tok * (3 * DMODEL);
    int which = r / DMODEL;
    int h  = (r % DMODEL) / HDIM;
    int dd = r % HDIM;
    int b = tok / SEQL, l = tok - b * SEQL;
    long dst = ((long)(b * NHEAD + h) * SEQL + l) * HDIM + dd;
    float val = g_qkv[idx];
    if (which == 0)      g_q[dst] = val;
    else if (which == 1) g_k[dst] = val;
    else                 g_v[dst] = val;
}

// ---------------------------------------------------------------------------
// Row softmax over 196 cols.
// ---------------------------------------------------------------------------
__global__ __launch_bounds__(128)
void softmax_kernel()
{
    long rowbase = (long)blockIdx.x * SEQL;
    int tid = threadIdx.x;
    float m = -1e30f;
    for (int j = tid; j < SEQL; j += 128) m = fmaxf(m, g_sc[rowbase + j]);
#pragma unroll
    for (int o = 16; o > 0; o >>= 1) m = fmaxf(m, __shfl_xor_sync(0xffffffffu, m, o));
    __shared__ float sm[4], ssum[4];
    int warp = tid >> 5, lane = tid & 31;
    if (lane == 0) sm[warp] = m;
    __syncthreads();
    m = fmaxf(fmaxf(sm[0], sm[1]), fmaxf(sm[2], sm[3]));
    float s = 0.0f;
    for (int j = tid; j < SEQL; j += 128) {
        float e = __expf(g_sc[rowbase + j] - m);
        g_sc[rowbase + j] = e;
        s += e;
    }
#pragma unroll
    for (int o = 16; o > 0; o >>= 1) s += __shfl_xor_sync(0xffffffffu, s, o);
    if (lane == 0) ssum[warp] = s;
    __syncthreads();
    s = ssum[0] + ssum[1] + ssum[2] + ssum[3];
    float inv = 1.0f / s;
    for (int j = tid; j < SEQL; j += 128) g_sc[rowbase + j] *= inv;
}

// ---------------------------------------------------------------------------
// Merge attention output: [bh, 196, 64] -> [tok, 512]
// ---------------------------------------------------------------------------
__global__ void merge_o_kernel()
{
    int idx = blockIdx.x * blockDim.x + threadIdx.x;
    const int n = TOK * DMODEL;
    if (idx >= n) return;
    int tok = idx >> 9;
    int ch  = idx & 511;
    int h = ch >> 6, dd = ch & 63;
    int b = tok / SEQL, l = tok - b * SEQL;
    g_o[idx] = g_obh[((long)(b * NHEAD + h) * SEQL + l) * HDIM + dd];
}

// ---------------------------------------------------------------------------
// Mean pool over L.
// ---------------------------------------------------------------------------
__global__ __launch_bounds__(256)
void pool_kernel()
{
    int b = blockIdx.x;
    for (int j = threadIdx.x; j < 1024; j += blockDim.x) {
        float s = 0.0f;
        const float* base = g_feat + (long)b * SEQL * 1024 + j;
        for (int l = 0; l < SEQL; l++) s += base[(long)l * 1024];
        g_pool[b * 1024 + j] = s * (1.0f / SEQL);
    }
}

// ---------------------------------------------------------------------------
// Final fc: [32,1024] @ [4,1024]^T + b -> [32,4]
// ---------------------------------------------------------------------------
__global__ __launch_bounds__(128)
void fc_kernel(const float* __restrict__ fc_w, const float* __restrict__ fc_b,
               float* __restrict__ out)
{
    int o = threadIdx.x;
    if (o >= BATCH * 4) return;
    int b = o >> 2, c = o & 3;
    float s = fc_b[c];
    const float* p = g_pool + b * 1024;
    const float* w = fc_w + c * 1024;
    for (int k = 0; k < 1024; k++) s = fmaf(p[k], w[k], s);
    out[o] = s;
}

// ---------------------------------------------------------------------------
// Launch
// ---------------------------------------------------------------------------
static inline dim3 gemm_grid(int M, int N, int batch) {
    return dim3((N + 63) / 64, (M + 63) / 64, batch);
}
static inline dim3 tc_grid(int M, int N) {
    return dim3(N / 128, M / 128, 1);
}

extern "C" void kernel_launch(void* const* d_in, const int* in_sizes, int n_in,
                              void* d_out, int out_size)
{
    const float* x          = (const float*)d_in[0];
    const float* patch_w    = (const float*)d_in[1];
    const float* patch_b    = (const float*)d_in[2];
    const float* ln1_g      = (const float*)d_in[3];
    const float* ln1_b      = (const float*)d_in[4];
    const float* in_proj_w  = (const float*)d_in[5];
    const float* convx_w    = (const float*)d_in[6];
    const float* convx_b    = (const float*)d_in[7];
    const float* convz_w    = (const float*)d_in[8];
    const float* convz_b    = (const float*)d_in[9];
    const float* x_proj_w   = (const float*)d_in[10];
    const float* dt_proj_w  = (const float*)d_in[11];
    const float* dt_proj_b  = (const float*)d_in[12];
    const float* A_log      = (const float*)d_in[13];
    const float* Dp         = (const float*)d_in[14];
    const float* out_proj_w = (const float*)d_in[15];
    const float* ln2_g      = (const float*)d_in[16];
    const float* ln2_b      = (const float*)d_in[17];
    const float* qkv_w      = (const float*)d_in[18];
    const float* attn_proj_w= (const float*)d_in[19];
    const float* ln3_g      = (const float*)d_in[20];
    const float* ln3_b      = (const float*)d_in[21];
    const float* mlp_w1     = (const float*)d_in[22];
    const float* mlp_b1     = (const float*)d_in[23];
    const float* mlp_w2     = (const float*)d_in[24];
    const float* mlp_b2     = (const float*)d_in[25];
    const float* head_w     = (const float*)d_in[26];
    const float* head_b     = (const float*)d_in[27];
    const float* fc_w       = (const float*)d_in[28];
    const float* fc_b       = (const float*)d_in[29];
    float* out = (float*)d_out;

    float *p_col, *p_t, *p_ln, *p_xz, *p_xm, *p_xdbl, *p_dt, *p_cat, *p_qkv;
    float *p_q, *p_k, *p_v, *p_sc, *p_obh, *p_o, *p_mlp, *p_feat;
    cudaGetSymbolAddress((void**)&p_col,  g_col);
    cudaGetSymbolAddress((void**)&p_t,    g_t);
    cudaGetSymbolAddress((void**)&p_ln,   g_ln);
    cudaGetSymbolAddress((void**)&p_xz,   g_xz);
    cudaGetSymbolAddress((void**)&p_xm,   g_xm);
    cudaGetSymbolAddress((void**)&p_xdbl, g_xdbl);
    cudaGetSymbolAddress((void**)&p_dt,   g_dt);
    cudaGetSymbolAddress((void**)&p_cat,  g_cat);
    cudaGetSymbolAddress((void**)&p_qkv,  g_qkv);
    cudaGetSymbolAddress((void**)&p_q,    g_q);
    cudaGetSymbolAddress((void**)&p_k,    g_k);
    cudaGetSymbolAddress((void**)&p_v,    g_v);
    cudaGetSymbolAddress((void**)&p_sc,   g_sc);
    cudaGetSymbolAddress((void**)&p_obh,  g_obh);
    cudaGetSymbolAddress((void**)&p_o,    g_o);
    cudaGetSymbolAddress((void**)&p_mlp,  g_mlp);
    cudaGetSymbolAddress((void**)&p_feat, g_feat);

    // allow 61.4KB dynamic smem on all TC GEMM instantiations (idempotent)
    cudaFuncSetAttribute(gemm_tc_kernel<0,1,0>, cudaFuncAttributeMaxDynamicSharedMemorySize, TC_SMEM_BYTES);
    cudaFuncSetAttribute(gemm_tc_kernel<0,0,0>, cudaFuncAttributeMaxDynamicSharedMemorySize, TC_SMEM_BYTES);
    cudaFuncSetAttribute(gemm_tc_kernel<0,0,1>, cudaFuncAttributeMaxDynamicSharedMemorySize, TC_SMEM_BYTES);
    cudaFuncSetAttribute(gemm_tc_kernel<1,1,0>, cudaFuncAttributeMaxDynamicSharedMemorySize, TC_SMEM_BYTES);
    cudaFuncSetAttribute(gemm_tc_kernel<0,1,1>, cudaFuncAttributeMaxDynamicSharedMemorySize, TC_SMEM_BYTES);

    // 1) im2col
    {
        int n = TOK * PATCHK;
        im2col_kernel<<<(n + 255) / 256, 256>>>(x);
    }
    // 2) patch embed (TC)
    gemm_tc_kernel<0,1,0><<<tc_grid(TOK, DMODEL), 256, TC_SMEM_BYTES>>>(
        p_col, patch_w, patch_b, nullptr, p_t,
        TOK, DMODEL, PATCHK, PATCHK, PATCHK, DMODEL);
    // 3) LN1
    layernorm_kernel<<<TOK, 128>>>(p_t, ln1_g, ln1_b, p_ln);
    // 4) in_proj (TC)
    gemm_tc_kernel<0,0,0><<<tc_grid(TOK, DMODEL), 256, TC_SMEM_BYTES>>>(
        p_ln, in_proj_w, nullptr, nullptr, p_xz,
        TOK, DMODEL, DMODEL, DMODEL, DMODEL, DMODEL);
    // 5) causal dwconv + silu
    {
        int n = 2 * TOK * DINNER;
        dwconv_silu_kernel<<<(n + 255) / 256, 256>>>(convx_w, convx_b, convz_w, convz_b);
    }
    // 6) x_proj (fp32 small)
    gemm_kernel<1,0,0,0><<<gemm_grid(TOK, 48, 1), 256>>>(
        p_xm, x_proj_w, nullptr, nullptr, p_xdbl,
        TOK, 48, DINNER, DINNER, DINNER, 48, 0, 0, 0, 1.0f);
    // 7) dt_proj + softplus (fp32 small K)
    gemm_kernel<1,2,1,0><<<gemm_grid(TOK, DINNER, 1), 256>>>(
        p_xdbl, dt_proj_w, dt_proj_b, nullptr, p_dt,
        TOK, DINNER, DTRANK, 48, DTRANK, DINNER, 0, 0, 0, 1.0f);
    // 8) selective scan
    scan_kernel<<<BATCH * 16, 256>>>(A_log, Dp);
    // 9) out_proj + residual (TC)
    gemm_tc_kernel<0,0,1><<<tc_grid(TOK, DMODEL), 256, TC_SMEM_BYTES>>>(
        p_cat, out_proj_w, nullptr, p_t, p_t,
        TOK, DMODEL, DMODEL, DMODEL, DMODEL, DMODEL);
    // 10) LN2
    layernorm_kernel<<<TOK, 128>>>(p_t, ln2_g, ln2_b, p_ln);
    // 11) qkv (TC)
    gemm_tc_kernel<0,0,0><<<tc_grid(TOK, 3 * DMODEL), 256, TC_SMEM_BYTES>>>(
        p_ln, qkv_w, nullptr, nullptr, p_qkv,
        TOK, 3 * DMODEL, DMODEL, DMODEL, DMODEL, 3 * DMODEL);
    // 12) split qkv
    {
        int n = TOK * 3 * DMODEL;
        split_qkv_kernel<<<(n + 255) / 256, 256>>>();
    }
    // 13) scores = Q K^T / 8 (batched fp32)
    gemm_kernel<1,0,0,0><<<gemm_grid(SEQL, SEQL, NBH), 256>>>(
        p_q, p_k, nullptr, nullptr, p_sc,
        SEQL, SEQL, HDIM, HDIM, HDIM, SEQL,
        (long)SEQL * HDIM, (long)SEQL * HDIM, (long)SEQL * SEQL, 0.125f);
    // 14) softmax
    softmax_kernel<<<NBH * SEQL, 128>>>();
    // 15) O = P V (batched fp32, NN)
    gemm_kernel<0,0,0,0><<<gemm_grid(SEQL, HDIM, NBH), 256>>>(
        p_sc, p_v, nullptr, nullptr, p_obh,
        SEQL, HDIM, SEQL, SEQL, HDIM, HDIM,
        (long)SEQL * SEQL, (long)SEQL * HDIM, (long)SEQL * HDIM, 1.0f);
    // 16) merge O
    {
        int n = TOK * DMODEL;
        merge_o_kernel<<<(n + 255) / 256, 256>>>();
    }
    // 17) attn_proj + residual (TC)
    gemm_tc_kernel<0,0,1><<<tc_grid(TOK, DMODEL), 256, TC_SMEM_BYTES>>>(
        p_o, attn_proj_w, nullptr, p_t, p_t,
        TOK, DMODEL, DMODEL, DMODEL, DMODEL, DMODEL);
    // 18) LN3
    layernorm_kernel<<<TOK, 128>>>(p_t, ln3_g, ln3_b, p_ln);
    // 19) mlp1 + gelu (TC)
    gemm_tc_kernel<1,1,0><<<tc_grid(TOK, 4 * DMODEL), 256, TC_SMEM_BYTES>>>(
        p_ln, mlp_w1, mlp_b1, nullptr, p_mlp,
        TOK, 4 * DMODEL, DMODEL, DMODEL, DMODEL, 4 * DMODEL);
    // 20) mlp2 + b2 + residual (TC)
    gemm_tc_kernel<0,1,1><<<tc_grid(TOK, DMODEL), 256, TC_SMEM_BYTES>>>(
        p_mlp, mlp_w2, mlp_b2, p_t, p_t,
        TOK, DMODEL, 4 * DMODEL, 4 * DMODEL, 4 * DMODEL, DMODEL);
    // 21) head (TC)
    gemm_tc_kernel<0,1,0><<<tc_grid(TOK, 1024), 256, TC_SMEM_BYTES>>>(
        p_t, head_w, head_b, nullptr, p_feat,
        TOK, 1024, DMODEL, DMODEL, DMODEL, 1024);
    // 22) mean pool
    pool_kernel<<<BATCH, 256>>>();
    // 23) fc
    fc_kernel<<<1, 128>>>(fc_w, fc_b, out);
}

// round 7
// speedup vs baseline: 2.8661x; 1.0851x over previous
#include <cuda_runtime.h>
#include <cuda_bf16.h>
#include <math.h>
#include <stdint.h>

// ---------------------------------------------------------------------------
// Problem constants
// ---------------------------------------------------------------------------
#define BATCH   32
#define SEQL    196          // 14*14 patches
#define TOK     (BATCH*SEQL) // 6272
#define DMODEL  512
#define DINNER  256
#define DSTATE  16
#define DTRANK  16
#define NHEAD   8
#define HDIM    64
#define NBH     (BATCH*NHEAD) // 256
#define PATCHK  768          // 3*16*16

// ---------------------------------------------------------------------------
// Scratch (static device globals; no runtime allocation allowed)
// ---------------------------------------------------------------------------
__device__ float g_col  [TOK * PATCHK];
__device__ float g_t    [TOK * DMODEL];
__device__ float g_ln   [TOK * DMODEL];
__device__ float g_xz   [TOK * DMODEL];
__device__ float g_xm   [TOK * DINNER];
__device__ float g_xdbl [TOK * 48];
__device__ float g_dt   [TOK * DINNER];
__device__ float g_cat  [TOK * DMODEL];
__device__ float g_qkv  [TOK * 3 * DMODEL];
__device__ float g_q    [NBH * SEQL * HDIM];
__device__ float g_k    [NBH * SEQL * HDIM];
__device__ float g_v    [NBH * SEQL * HDIM];
__device__ float g_sc   [NBH * SEQL * SEQL];
__device__ float g_obh  [NBH * SEQL * HDIM];
__device__ float g_o    [TOK * DMODEL];
__device__ float g_mlp  [TOK * 4 * DMODEL];
__device__ float g_feat [TOK * 1024];
__device__ float g_pool [BATCH * 1024];

// ---------------------------------------------------------------------------
// Activation helpers
// ---------------------------------------------------------------------------
__device__ __forceinline__ float act_gelu(float x) {
    float x3 = x * x * x;
    return 0.5f * x * (1.0f + tanhf(0.7978845608028654f * (x + 0.044715f * x3)));
}
__device__ __forceinline__ float act_softplus(float x) {
    return (x > 20.0f) ? x : log1pf(expf(x));
}
__device__ __forceinline__ float act_silu(float x) {
    return x / (1.0f + expf(-x));
}

// ---------------------------------------------------------------------------
// tf32 / async-copy helpers
// ---------------------------------------------------------------------------
__device__ __forceinline__ uint32_t f2tf32(float x) {
    uint32_t r;
    asm("cvt.rna.tf32.f32 %0, %1;" : "=r"(r) : "f"(x));
    return r;
}
__device__ __forceinline__ void mma_tf32(float* d, const uint32_t* a, const uint32_t* b) {
    asm volatile(
        "mma.sync.aligned.m16n8k8.row.col.f32.tf32.tf32.f32 "
        "{%0,%1,%2,%3}, {%4,%5,%6,%7}, {%8,%9}, {%0,%1,%2,%3};\n"
        : "+f"(d[0]), "+f"(d[1]), "+f"(d[2]), "+f"(d[3])
        : "r"(a[0]), "r"(a[1]), "r"(a[2]), "r"(a[3]), "r"(b[0]), "r"(b[1]));
}
__device__ __forceinline__ void cp_async16(uint32_t saddr, const void* gptr) {
    asm volatile("cp.async.cg.shared.global [%0], [%1], 16;\n" :: "r"(saddr), "l"(gptr));
}
__device__ __forceinline__ void cp_commit() {
    asm volatile("cp.async.commit_group;\n");
}
template<int N>
__device__ __forceinline__ void cp_wait() {
    asm volatile("cp.async.wait_group %0;\n" :: "n"(N));
}

// ---------------------------------------------------------------------------
// Pipelined tensor-core tf32 GEMM: C[M,N] = A[M,K] * B[N,K]^T (+bias)(act)(+res)
// Requires M%128==0, N%128==0, K%32==0.
// CTA tile 128x128x32; 3-stage cp.async pipeline; 8 warps 4(m)x2(n), warp 32x64.
// Fragment double-buffering across the four k=8 sub-steps.
// smem fp32 [stage][row(128)][k(32), stride 36] -> conflict-free fragment LDS.
// ---------------------------------------------------------------------------
#define TC_STAGES 3
#define TC_KSLAB  32
#define TC_KSTR   36
#define TC_STAGE_FLOATS (128 * TC_KSTR)
#define TC_SMEM_BYTES (2 * TC_STAGES * TC_STAGE_FLOATS * 4)

template<int ACT, int HAS_BIAS, int HAS_RES>
__global__ __launch_bounds__(256)
void gemm_tc_kernel(const float* __restrict__ A, const float* __restrict__ B,
                    const float* __restrict__ bias, const float* __restrict__ res,
                    float* __restrict__ C, int M, int N, int K,
                    int lda, int ldb, int ldc)
{
    extern __shared__ float smem[];
    float* As = smem;                                  // [S][128][36]
    float* Bs = smem + TC_STAGES * TC_STAGE_FLOATS;    // [S][128][36]

    const int tid  = threadIdx.x;
    const int wid  = tid >> 5;
    const int lane = tid & 31;
    const int bm = blockIdx.y * 128;
    const int bn = blockIdx.x * 128;
    const int warp_m = (wid >> 1) * 32;
    const int warp_n = (wid & 1) * 64;
    const int tig = lane & 3;
    const int grp = lane >> 2;

    float acc[2][8][4];
#pragma unroll
    for (int mt = 0; mt < 2; mt++)
#pragma unroll
        for (int nt = 0; nt < 8; nt++)
#pragma unroll
            for (int i = 0; i < 4; i++) acc[mt][nt][i] = 0.0f;

    const int NK = K >> 5;   // 32-wide slabs

    // load mapping: 1024 float4 items per matrix per stage; 4 items/thread.
    // item i: row = i>>3, kq = (i&7)*4
    auto load_stage = [&](int s, int kt) {
        const int k0 = kt << 5;
        float* as = As + s * TC_STAGE_FLOATS;
        float* bs = Bs + s * TC_STAGE_FLOATS;
#pragma unroll
        for (int p = 0; p < 4; p++) {
            int item = tid + p * 256;
            int row  = item >> 3;
            int kq   = (item & 7) * 4;
            const float* ga = A + (long)(bm + row) * lda + k0 + kq;
            cp_async16((uint32_t)__cvta_generic_to_shared(as + row * TC_KSTR + kq), ga);
            const float* gb = B + (long)(bn + row) * ldb + k0 + kq;
            cp_async16((uint32_t)__cvta_generic_to_shared(bs + row * TC_KSTR + kq), gb);
        }
    };

    // prologue: stages 0..S-2
    load_stage(0, 0); cp_commit();
    load_stage(1, 1); cp_commit();

    for (int kt = 0; kt < NK; kt++) {
        cp_wait<TC_STAGES - 2>();
        __syncthreads();   // stage kt ready for everyone; prior stage reads done

        // issue next stage load (empty commit when past the end keeps counts consistent)
        {
            int nk = kt + TC_STAGES - 1;
            if (nk < NK) load_stage(nk % TC_STAGES, nk);
            cp_commit();
        }

        const int cs = kt % TC_STAGES;
        const float* as = As + cs * TC_STAGE_FLOATS;
        const float* bs = Bs + cs * TC_STAGE_FLOATS;

        uint32_t af[2][2][4];
        uint32_t bf[2][8][2];

        auto load_frags = [&](int ks, uint32_t (&a)[2][4], uint32_t (&b)[8][2]) {
#pragma unroll
            for (int mt = 0; mt < 2; mt++) {
                int m = warp_m + mt * 16;
                a[mt][0] = f2tf32(as[(m + grp    ) * TC_KSTR + ks + tig    ]);
                a[mt][1] = f2tf32(as[(m + grp + 8) * TC_KSTR + ks + tig    ]);
                a[mt][2] = f2tf32(as[(m + grp    ) * TC_KSTR + ks + tig + 4]);
                a[mt][3] = f2tf32(as[(m + grp + 8) * TC_KSTR + ks + tig + 4]);
            }
#pragma unroll
            for (int nt = 0; nt < 8; nt++) {
                int n = warp_n + nt * 8;
                b[nt][0] = f2tf32(bs[(n + grp) * TC_KSTR + ks + tig    ]);
                b[nt][1] = f2tf32(bs[(n + grp) * TC_KSTR + ks + tig + 4]);
            }
        };

        load_frags(0, af[0], bf[0]);
#pragma unroll
        for (int ksi = 0; ksi < 4; ksi++) {
            const int cur = ksi & 1;
            const int nxt = cur ^ 1;
            if (ksi < 3) load_frags((ksi + 1) * 8, af[nxt], bf[nxt]);
#pragma unroll
            for (int mt = 0; mt < 2; mt++)
#pragma unroll
                for (int nt = 0; nt < 8; nt++)
                    mma_tf32(acc[mt][nt], af[cur][mt], bf[cur][nt]);
        }
        // no bottom barrier: next iteration's top __syncthreads orders the
        // stage-(kt) overwrite (at kt+3) after all reads of stage kt.
    }

    // epilogue
#pragma unroll
    for (int mt = 0; mt < 2; mt++) {
        int r = bm + warp_m + mt * 16 + grp;
#pragma unroll
        for (int nt = 0; nt < 8; nt++) {
            int c0 = bn + warp_n + nt * 8 + tig * 2;
            float v0 = acc[mt][nt][0];
            float v1 = acc[mt][nt][1];
            float v2 = acc[mt][nt][2];
            float v3 = acc[mt][nt][3];
            if (HAS_BIAS) {
                float b0 = bias[c0], b1 = bias[c0 + 1];
                v0 += b0; v1 += b1; v2 += b0; v3 += b1;
            }
            if (ACT == 1) { v0 = act_gelu(v0); v1 = act_gelu(v1); v2 = act_gelu(v2); v3 = act_gelu(v3); }
            long o0 = (long)r * ldc + c0;
            long o1 = (long)(r + 8) * ldc + c0;
            if (HAS_RES) {
                v0 += res[o0]; v1 += res[o0 + 1];
                v2 += res[o1]; v3 += res[o1 + 1];
            }
            C[o0] = v0; C[o0 + 1] = v1;
            C[o1] = v2; C[o1 + 1] = v3;
        }
    }
}

// ---------------------------------------------------------------------------
// Generic fp32 GEMM (odd shapes: x_proj, dt_proj, attention).
// ---------------------------------------------------------------------------
template<int TRANS_B, int ACT, int HAS_BIAS, int HAS_RES>
__global__ __launch_bounds__(256)
void gemm_kernel(const float* __restrict__ A, const float* __restrict__ B,
                 const float* __restrict__ bias, const float* __restrict__ res,
                 float* __restrict__ C,
                 int M, int N, int K, int lda, int ldb, int ldc,
                 long sA, long sB, long sC, float alpha)
{
    A += (long)blockIdx.z * sA;
    B += (long)blockIdx.z * sB;
    C += (long)blockIdx.z * sC;
    if (HAS_RES) res += (long)blockIdx.z * sC;

    __shared__ float As[16][65];
    __shared__ float Bs[16][65];

    const int tid = threadIdx.x;
    const int bm = blockIdx.y * 64;
    const int bn = blockIdx.x * 64;
    const int ty = tid >> 4;
    const int tx = tid & 15;

    float acc[4][4];
#pragma unroll
    for (int i = 0; i < 4; i++)
#pragma unroll
        for (int j = 0; j < 4; j++) acc[i][j] = 0.0f;

    const int nkt = (K + 15) >> 4;
    for (int kt = 0; kt < nkt; kt++) {
        const int k0 = kt << 4;
#pragma unroll
        for (int p = 0; p < 4; p++) {
            int r  = (tid >> 4) + p * 16;
            int gm = bm + r;
            int gk = k0 + (tid & 15);
            As[tid & 15][r] = (gm < M && gk < K) ? A[(long)gm * lda + gk] : 0.0f;
        }
        if (TRANS_B) {
#pragma unroll
            for (int p = 0; p < 4; p++) {
                int r  = (tid >> 4) + p * 16;
                int gn = bn + r;
                int gk = k0 + (tid & 15);
                Bs[tid & 15][r] = (gn < N && gk < K) ? B[(long)gn * ldb + gk] : 0.0f;
            }
        } else {
#pragma unroll
            for (int p = 0; p < 4; p++) {
                int kk = (tid >> 6) + p * 4;
                int nn = tid & 63;
                int gk = k0 + kk;
                int gn = bn + nn;
                Bs[kk][nn] = (gk < K && gn < N) ? B[(long)gk * ldb + gn] : 0.0f;
            }
        }
        __syncthreads();
#pragma unroll
        for (int kk = 0; kk < 16; kk++) {
            float a[4], b[4];
#pragma unroll
            for (int i = 0; i < 4; i++) a[i] = As[kk][ty * 4 + i];
#pragma unroll
            for (int j = 0; j < 4; j++) b[j] = Bs[kk][tx * 4 + j];
#pragma unroll
            for (int i = 0; i < 4; i++)
#pragma unroll
                for (int j = 0; j < 4; j++) acc[i][j] = fmaf(a[i], b[j], acc[i][j]);
        }
        __syncthreads();
    }

#pragma unroll
    for (int i = 0; i < 4; i++) {
        int gm = bm + ty * 4 + i;
        if (gm >= M) continue;
#pragma unroll
        for (int j = 0; j < 4; j++) {
            int gn = bn + tx * 4 + j;
            if (gn >= N) continue;
            float v = acc[i][j] * alpha;
            if (HAS_BIAS) v += bias[gn];
            if (ACT == 1) v = act_gelu(v);
            else if (ACT == 2) v = act_softplus(v);
            if (HAS_RES) v += res[(long)gm * ldc + gn];
            C[(long)gm * ldc + gn] = v;
        }
    }
}

// ---------------------------------------------------------------------------
// im2col for the 16x16/stride-16 patch conv.
// ---------------------------------------------------------------------------
__global__ void im2col_kernel(const float* __restrict__ x)
{
    int idx = blockIdx.x * blockDim.x + threadIdx.x;
    const int n = TOK * PATCHK;
    if (idx >= n) return;
    int tok  = idx / PATCHK;
    int cidx = idx - tok * PATCHK;
    int b  = tok / SEQL;
    int l  = tok - b * SEQL;
    int ph = l / 14, pw = l - ph * 14;
    int c  = cidx >> 8;
    int r  = cidx & 255;
    int kh = r >> 4, kw = r & 15;
    g_col[idx] = x[(((long)b * 3 + c) * 224 + (ph * 16 + kh)) * 224 + (pw * 16 + kw)];
}

// ---------------------------------------------------------------------------
// LayerNorm over last dim (512).
// ---------------------------------------------------------------------------
__global__ __launch_bounds__(128)
void layernorm_kernel(const float* __restrict__ in, const float* __restrict__ g,
                      const float* __restrict__ b, float* __restrict__ out)
{
    int tok = blockIdx.x;
    int tid = threadIdx.x;
    const float* row = in + (long)tok * DMODEL;
    float v[4];
    float s = 0.0f, s2 = 0.0f;
#pragma unroll
    for (int i = 0; i < 4; i++) {
        v[i] = row[tid + i * 128];
        s  += v[i];
        s2 += v[i] * v[i];
    }
#pragma unroll
    for (int o = 16; o > 0; o >>= 1) {
        s  += __shfl_xor_sync(0xffffffffu, s,  o);
        s2 += __shfl_xor_sync(0xffffffffu, s2, o);
    }
    __shared__ float ss[4], ss2[4];
    int warp = tid >> 5, lane = tid & 31;
    if (lane == 0) { ss[warp] = s; ss2[warp] = s2; }
    __syncthreads();
    s  = ss[0] + ss[1] + ss[2] + ss[3];
    s2 = ss2[0] + ss2[1] + ss2[2] + ss2[3];
    float mean = s * (1.0f / DMODEL);
    float var  = s2 * (1.0f / DMODEL) - mean * mean;
    float inv  = rsqrtf(var + 1e-6f);
    float* orow = out + (long)tok * DMODEL;
#pragma unroll
    for (int i = 0; i < 4; i++) {
        int col = tid + i * 128;
        orow[col] = (v[i] - mean) * inv * g[col] + b[col];
    }
}

// ---------------------------------------------------------------------------
// Causal depthwise conv (width 4) + SiLU for both halves of xz.
// ---------------------------------------------------------------------------
__global__ void dwconv_silu_kernel(const float* __restrict__ wx, const float* __restrict__ bx,
                                   const float* __restrict__ wz, const float* __restrict__ bz)
{
    int idx = blockIdx.x * blockDim.x + threadIdx.x;
    const int n = TOK * DINNER;
    if (idx >= 2 * n) return;
    int half = idx >= n;
    int id   = half ? idx - n : idx;
    int tok  = id >> 8;
    int c    = id & 255;
    int b    = tok / SEQL;
    int l    = tok - b * SEQL;
    const float* w  = half ? wz : wx;
    const float* bb = half ? bz : bx;
    int off = half ? DINNER : 0;
    float sum = bb[c];
#pragma unroll
    for (int k = 0; k < 4; k++) {
        int ll = l - 3 + k;
        if (ll >= 0)
            sum += g_xz[((long)(b * SEQL + ll)) * DMODEL + off + c] * w[c * 4 + k];
    }
    sum = act_silu(sum);
    if (half) g_cat[(long)tok * DMODEL + DINNER + c] = sum;
    else      g_xm[(long)tok * DINNER + c] = sum;
}

// ---------------------------------------------------------------------------
// Selective scan.
// ---------------------------------------------------------------------------
__global__ __launch_bounds__(256)
void scan_kernel(const float* __restrict__ A_log, const float* __restrict__ Dp)
{
    int b    = blockIdx.x >> 4;
    int dblk = blockIdx.x & 15;
    int nidx = threadIdx.x & 15;
    int d    = dblk * 16 + (threadIdx.x >> 4);

    float An = -expf(A_log[d * DSTATE + nidx]);
    float Dd = Dp[d];
    float h  = 0.0f;
    const long tokbase = (long)b * SEQL;
    for (int l = 0; l < SEQL; l++) {
        long t   = tokbase + l;
        float dtv = g_dt[t * DINNER + d];
        float u   = g_xm[t * DINNER + d];
        float Bn  = g_xdbl[t * 48 + DTRANK + nidx];
        float Cn  = g_xdbl[t * 48 + DTRANK + DSTATE + nidx];
        h = __expf(dtv * An) * h + dtv * u * Bn;
        float y = h * Cn;
        y += __shfl_xor_sync(0xffffffffu, y, 8);
        y += __shfl_xor_sync(0xffffffffu, y, 4);
        y += __shfl_xor_sync(0xffffffffu, y, 2);
        y += __shfl_xor_sync(0xffffffffu, y, 1);
        if (nidx == 0)
            g_cat[t * DMODEL + d] = y + u * Dd;
    }
}

// ---------------------------------------------------------------------------
// qkv split: [tok, 3, 8, 64] -> q/k/v [bh, 196, 64]
// ---------------------------------------------------------------------------
__global__ void split_qkv_kernel()
{
    int idx = blockIdx.x * blockDim.x + threadIdx.x;
    const int n = TOK * 3 * DMODEL;
    if (idx >= n) return;
    int tok = idx / (3 * DMODEL);
    int r   = idx - tok * (3 * DMODEL);
    int which = r / DMODEL;
    int h  = (r % DMODEL) / HDIM;
    int dd = r % HDIM;
    int b = tok / SEQL, l = tok - b * SEQL;
    long dst = ((long)(b * NHEAD + h) * SEQL + l) * HDIM + dd;
    float val = g_qkv[idx];
    if (which == 0)      g_q[dst] = val;
    else if (which == 1) g_k[dst] = val;
    else                 g_v[dst] = val;
}

// ---------------------------------------------------------------------------
// Row softmax over 196 cols.
// ---------------------------------------------------------------------------
__global__ __launch_bounds__(128)
void softmax_kernel()
{
    long rowbase = (long)blockIdx.x * SEQL;
    int tid = threadIdx.x;
    float m = -1e30f;
    for (int j = tid; j < SEQL; j += 128) m = fmaxf(m, g_sc[rowbase + j]);
#pragma unroll
    for (int o = 16; o > 0; o >>= 1) m = fmaxf(m, __shfl_xor_sync(0xffffffffu, m, o));
    __shared__ float sm[4], ssum[4];
    int warp = tid >> 5, lane = tid & 31;
    if (lane == 0) sm[warp] = m;
    __syncthreads();
    m = fmaxf(fmaxf(sm[0], sm[1]), fmaxf(sm[2], sm[3]));
    float s = 0.0f;
    for (int j = tid; j < SEQL; j += 128) {
        float e = __expf(g_sc[rowbase + j] - m);
        g_sc[rowbase + j] = e;
        s += e;
    }
#pragma unroll
    for (int o = 16; o > 0; o >>= 1) s += __shfl_xor_sync(0xffffffffu, s, o);
    if (lane == 0) ssum[warp] = s;
    __syncthreads();
    s = ssum[0] + ssum[1] + ssum[2] + ssum[3];
    float inv = 1.0f / s;
    for (int j = tid; j < SEQL; j += 128) g_sc[rowbase + j] *= inv;
}

// ---------------------------------------------------------------------------
// Merge attention output: [bh, 196, 64] -> [tok, 512]
// ---------------------------------------------------------------------------
__global__ void merge_o_kernel()
{
    int idx = blockIdx.x * blockDim.x + threadIdx.x;
    const int n = TOK * DMODEL;
    if (idx >= n) return;
    int tok = idx >> 9;
    int ch  = idx & 511;
    int h = ch >> 6, dd = ch & 63;
    int b = tok / SEQL, l = tok - b * SEQL;
    g_o[idx] = g_obh[((long)(b * NHEAD + h) * SEQL + l) * HDIM + dd];
}

// ---------------------------------------------------------------------------
// Mean pool over L.
// ---------------------------------------------------------------------------
__global__ __launch_bounds__(256)
void pool_kernel()
{
    int b = blockIdx.x;
    for (int j = threadIdx.x; j < 1024; j += blockDim.x) {
        float s = 0.0f;
        const float* base = g_feat + (long)b * SEQL * 1024 + j;
        for (int l = 0; l < SEQL; l++) s += base[(long)l * 1024];
        g_pool[b * 1024 + j] = s * (1.0f / SEQL);
    }
}

// ---------------------------------------------------------------------------
// Final fc: [32,1024] @ [4,1024]^T + b -> [32,4]
// ---------------------------------------------------------------------------
__global__ __launch_bounds__(128)
void fc_kernel(const float* __restrict__ fc_w, const float* __restrict__ fc_b,
               float* __restrict__ out)
{
    int o = threadIdx.x;
    if (o >= BATCH * 4) return;
    int b = o >> 2, c = o & 3;
    float s = fc_b[c];
    const float* p = g_pool + b * 1024;
    const float* w = fc_w + c * 1024;
    for (int k = 0; k < 1024; k++) s = fmaf(p[k], w[k], s);
    out[o] = s;
}

// ---------------------------------------------------------------------------
// Launch
// ---------------------------------------------------------------------------
static inline dim3 gemm_grid(int M, int N, int batch) {
    return dim3((N + 63) / 64, (M + 63) / 64, batch);
}
static inline dim3 tc_grid(int M, int N) {
    return dim3(N / 128, M / 128, 1);
}

extern "C" void kernel_launch(void* const* d_in, const int* in_sizes, int n_in,
                              void* d_out, int out_size)
{
    const float* x          = (const float*)d_in[0];
    const float* patch_w    = (const float*)d_in[1];
    const float* patch_b    = (const float*)d_in[2];
    const float* ln1_g      = (const float*)d_in[3];
    const float* ln1_b      = (const float*)d_in[4];
    const float* in_proj_w  = (const float*)d_in[5];
    const float* convx_w    = (const float*)d_in[6];
    const float* convx_b    = (const float*)d_in[7];
    const float* convz_w    = (const float*)d_in[8];
    const float* convz_b    = (const float*)d_in[9];
    const float* x_proj_w   = (const float*)d_in[10];
    const float* dt_proj_w  = (const float*)d_in[11];
    const float* dt_proj_b  = (const float*)d_in[12];
    const float* A_log      = (const float*)d_in[13];
    const float* Dp         = (const float*)d_in[14];
    const float* out_proj_w = (const float*)d_in[15];
    const float* ln2_g      = (const float*)d_in[16];
    const float* ln2_b      = (const float*)d_in[17];
    const float* qkv_w      = (const float*)d_in[18];
    const float* attn_proj_w= (const float*)d_in[19];
    const float* ln3_g      = (const float*)d_in[20];
    const float* ln3_b      = (const float*)d_in[21];
    const float* mlp_w1     = (const float*)d_in[22];
    const float* mlp_b1     = (const float*)d_in[23];
    const float* mlp_w2     = (const float*)d_in[24];
    const float* mlp_b2     = (const float*)d_in[25];
    const float* head_w     = (const float*)d_in[26];
    const float* head_b     = (const float*)d_in[27];
    const float* fc_w       = (const float*)d_in[28];
    const float* fc_b       = (const float*)d_in[29];
    float* out = (float*)d_out;

    float *p_col, *p_t, *p_ln, *p_xz, *p_xm, *p_xdbl, *p_dt, *p_cat, *p_qkv;
    float *p_q, *p_k, *p_v, *p_sc, *p_obh, *p_o, *p_mlp, *p_feat;
    cudaGetSymbolAddress((void**)&p_col,  g_col);
    cudaGetSymbolAddress((void**)&p_t,    g_t);
    cudaGetSymbolAddress((void**)&p_ln,   g_ln);
    cudaGetSymbolAddress((void**)&p_xz,   g_xz);
    cudaGetSymbolAddress((void**)&p_xm,   g_xm);
    cudaGetSymbolAddress((void**)&p_xdbl, g_xdbl);
    cudaGetSymbolAddress((void**)&p_dt,   g_dt);
    cudaGetSymbolAddress((void**)&p_cat,  g_cat);
    cudaGetSymbolAddress((void**)&p_qkv,  g_qkv);
    cudaGetSymbolAddress((void**)&p_q,    g_q);
    cudaGetSymbolAddress((void**)&p_k,    g_k);
    cudaGetSymbolAddress((void**)&p_v,    g_v);
    cudaGetSymbolAddress((void**)&p_sc,   g_sc);
    cudaGetSymbolAddress((void**)&p_obh,  g_obh);
    cudaGetSymbolAddress((void**)&p_o,    g_o);
    cudaGetSymbolAddress((void**)&p_mlp,  g_mlp);
    cudaGetSymbolAddress((void**)&p_feat, g_feat);

    // allow 110.6KB dynamic smem on all TC GEMM instantiations (idempotent)
    cudaFuncSetAttribute(gemm_tc_kernel<0,1,0>, cudaFuncAttributeMaxDynamicSharedMemorySize, TC_SMEM_BYTES);
    cudaFuncSetAttribute(gemm_tc_kernel<0,0,0>, cudaFuncAttributeMaxDynamicSharedMemorySize, TC_SMEM_BYTES);
    cudaFuncSetAttribute(gemm_tc_kernel<0,0,1>, cudaFuncAttributeMaxDynamicSharedMemorySize, TC_SMEM_BYTES);
    cudaFuncSetAttribute(gemm_tc_kernel<1,1,0>, cudaFuncAttributeMaxDynamicSharedMemorySize, TC_SMEM_BYTES);
    cudaFuncSetAttribute(gemm_tc_kernel<0,1,1>, cudaFuncAttributeMaxDynamicSharedMemorySize, TC_SMEM_BYTES);

    // 1) im2col
    {
        int n = TOK * PATCHK;
        im2col_kernel<<<(n + 255) / 256, 256>>>(x);
    }
    // 2) patch embed (TC)
    gemm_tc_kernel<0,1,0><<<tc_grid(TOK, DMODEL), 256, TC_SMEM_BYTES>>>(
        p_col, patch_w, patch_b, nullptr, p_t,
        TOK, DMODEL, PATCHK, PATCHK, PATCHK, DMODEL);
    // 3) LN1
    layernorm_kernel<<<TOK, 128>>>(p_t, ln1_g, ln1_b, p_ln);
    // 4) in_proj (TC)
    gemm_tc_kernel<0,0,0><<<tc_grid(TOK, DMODEL), 256, TC_SMEM_BYTES>>>(
        p_ln, in_proj_w, nullptr, nullptr, p_xz,
        TOK, DMODEL, DMODEL, DMODEL, DMODEL, DMODEL);
    // 5) causal dwconv + silu
    {
        int n = 2 * TOK * DINNER;
        dwconv_silu_kernel<<<(n + 255) / 256, 256>>>(convx_w, convx_b, convz_w, convz_b);
    }
    // 6) x_proj (fp32 small)
    gemm_kernel<1,0,0,0><<<gemm_grid(TOK, 48, 1), 256>>>(
        p_xm, x_proj_w, nullptr, nullptr, p_xdbl,
        TOK, 48, DINNER, DINNER, DINNER, 48, 0, 0, 0, 1.0f);
    // 7) dt_proj + softplus (fp32 small K)
    gemm_kernel<1,2,1,0><<<gemm_grid(TOK, DINNER, 1), 256>>>(
        p_xdbl, dt_proj_w, dt_proj_b, nullptr, p_dt,
        TOK, DINNER, DTRANK, 48, DTRANK, DINNER, 0, 0, 0, 1.0f);
    // 8) selective scan
    scan_kernel<<<BATCH * 16, 256>>>(A_log, Dp);
    // 9) out_proj + residual (TC)
    gemm_tc_kernel<0,0,1><<<tc_grid(TOK, DMODEL), 256, TC_SMEM_BYTES>>>(
        p_cat, out_proj_w, nullptr, p_t, p_t,
        TOK, DMODEL, DMODEL, DMODEL, DMODEL, DMODEL);
    // 10) LN2
    layernorm_kernel<<<TOK, 128>>>(p_t, ln2_g, ln2_b, p_ln);
    // 11) qkv (TC)
    gemm_tc_kernel<0,0,0><<<tc_grid(TOK, 3 * DMODEL), 256, TC_SMEM_BYTES>>>(
        p_ln, qkv_w, nullptr, nullptr, p_qkv,
        TOK, 3 * DMODEL, DMODEL, DMODEL, DMODEL, 3 * DMODEL);
    // 12) split qkv
    {
        int n = TOK * 3 * DMODEL;
        split_qkv_kernel<<<(n + 255) / 256, 256>>>();
    }
    // 13) scores = Q K^T / 8 (batched fp32)
    gemm_kernel<1,0,0,0><<<gemm_grid(SEQL, SEQL, NBH), 256>>>(
        p_q, p_k, nullptr, nullptr, p_sc,
        SEQL, SEQL, HDIM, HDIM, HDIM, SEQL,
        (long)SEQL * HDIM, (long)SEQL * HDIM, (long)SEQL * SEQL, 0.125f);
    // 14) softmax
    softmax_kernel<<<NBH * SEQL, 128>>>();
    // 15) O = P V (batched fp32, NN)
    gemm_kernel<0,0,0,0><<<gemm_grid(SEQL, HDIM, NBH), 256>>>(
        p_sc, p_v, nullptr, nullptr, p_obh,
        SEQL, HDIM, SEQL, SEQL, HDIM, HDIM,
        (long)SEQL * SEQL, (long)SEQL * HDIM, (long)SEQL * HDIM, 1.0f);
    // 16) merge O
    {
        int n = TOK * DMODEL;
        merge_o_kernel<<<(n + 255) / 256, 256>>>();
    }
    // 17) attn_proj + residual (TC)
    gemm_tc_kernel<0,0,1><<<tc_grid(TOK, DMODEL), 256, TC_SMEM_BYTES>>>(
        p_o, attn_proj_w, nullptr, p_t, p_t,
        TOK, DMODEL, DMODEL, DMODEL, DMODEL, DMODEL);
    // 18) LN3
    layernorm_kernel<<<TOK, 128>>>(p_t, ln3_g, ln3_b, p_ln);
    // 19) mlp1 + gelu (TC)
    gemm_tc_kernel<1,1,0><<<tc_grid(TOK, 4 * DMODEL), 256, TC_SMEM_BYTES>>>(
        p_ln, mlp_w1, mlp_b1, nullptr, p_mlp,
        TOK, 4 * DMODEL, DMODEL, DMODEL, DMODEL, 4 * DMODEL);
    // 20) mlp2 + b2 + residual (TC)
    gemm_tc_kernel<0,1,1><<<tc_grid(TOK, DMODEL), 256, TC_SMEM_BYTES>>>(
        p_mlp, mlp_w2, mlp_b2, p_t, p_t,
        TOK, DMODEL, 4 * DMODEL, 4 * DMODEL, 4 * DMODEL, DMODEL);
    // 21) head (TC)
    gemm_tc_kernel<0,1,0><<<tc_grid(TOK, 1024), 256, TC_SMEM_BYTES>>>(
        p_t, head_w, head_b, nullptr, p_feat,
        TOK, 1024, DMODEL, DMODEL, DMODEL, 1024);
    // 22) mean pool
    pool_kernel<<<BATCH, 256>>>();
    // 23) fc
    fc_kernel<<<1, 128>>>(fc_w, fc_b, out);
}

// round 9
// speedup vs baseline: 2.9413x; 1.0262x over previous
#include <cuda_runtime.h>
#include <cuda_bf16.h>
#include <math.h>
#include <stdint.h>

// ---------------------------------------------------------------------------
// Problem constants
// ---------------------------------------------------------------------------
#define BATCH   32
#define SEQL    196          // 14*14 patches
#define TOK     (BATCH*SEQL) // 6272
#define DMODEL  512
#define DINNER  256
#define DSTATE  16
#define DTRANK  16
#define NHEAD   8
#define HDIM    64
#define NBH     (BATCH*NHEAD) // 256
#define PATCHK  768          // 3*16*16

// ---------------------------------------------------------------------------
// Scratch (static device globals; no runtime allocation allowed)
// ---------------------------------------------------------------------------
__device__ float g_col  [TOK * PATCHK];
__device__ float g_t    [TOK * DMODEL];
__device__ float g_ln   [TOK * DMODEL];
__device__ float g_xz   [TOK * DMODEL];
__device__ float g_xm   [TOK * DINNER];
__device__ float g_xdbl [TOK * 48];
__device__ float g_dt   [TOK * DINNER];
__device__ float g_cat  [TOK * DMODEL];
__device__ float g_qkv  [TOK * 3 * DMODEL];
__device__ float g_q    [NBH * SEQL * HDIM];
__device__ float g_k    [NBH * SEQL * HDIM];
__device__ float g_v    [NBH * SEQL * HDIM];
__device__ float g_sc   [NBH * SEQL * SEQL];
__device__ float g_obh  [NBH * SEQL * HDIM];
__device__ float g_o    [TOK * DMODEL];
__device__ float g_mlp  [TOK * 4 * DMODEL];
__device__ float g_feat [TOK * 1024];
__device__ float g_pool [BATCH * 1024];

// ---------------------------------------------------------------------------
// Activation helpers
// ---------------------------------------------------------------------------
__device__ __forceinline__ float act_gelu(float x) {
    float x3 = x * x * x;
    return 0.5f * x * (1.0f + tanhf(0.7978845608028654f * (x + 0.044715f * x3)));
}
__device__ __forceinline__ float act_softplus(float x) {
    return (x > 20.0f) ? x : log1pf(expf(x));
}
__device__ __forceinline__ float act_silu(float x) {
    return x / (1.0f + expf(-x));
}

// ---------------------------------------------------------------------------
// tf32 / async-copy helpers
// ---------------------------------------------------------------------------
__device__ __forceinline__ uint32_t f2tf32(float x) {
    uint32_t r;
    asm("cvt.rna.tf32.f32 %0, %1;" : "=r"(r) : "f"(x));
    return r;
}
__device__ __forceinline__ void mma_tf32(float* d, const uint32_t* a, const uint32_t* b) {
    asm volatile(
        "mma.sync.aligned.m16n8k8.row.col.f32.tf32.tf32.f32 "
        "{%0,%1,%2,%3}, {%4,%5,%6,%7}, {%8,%9}, {%0,%1,%2,%3};\n"
        : "+f"(d[0]), "+f"(d[1]), "+f"(d[2]), "+f"(d[3])
        : "r"(a[0]), "r"(a[1]), "r"(a[2]), "r"(a[3]), "r"(b[0]), "r"(b[1]));
}
__device__ __forceinline__ void cp_async16(uint32_t saddr, const void* gptr) {
    asm volatile("cp.async.cg.shared.global [%0], [%1], 16;\n" :: "r"(saddr), "l"(gptr));
}
__device__ __forceinline__ void cp_commit() {
    asm volatile("cp.async.commit_group;\n");
}
template<int N>
__device__ __forceinline__ void cp_wait() {
    asm volatile("cp.async.wait_group %0;\n" :: "n"(N));
}

#define TC_STAGES 3
#define TC_KSTR   36

// ---------------------------------------------------------------------------
// Pipelined tensor-core tf32 GEMM, 128x128 CTA tile (for N >= 1024).
// C[M,N] = A[M,K] * B[N,K]^T (+bias)(act)(+res). M%128==0, N%128==0, K%32==0.
// 8 warps 4(m)x2(n), warp 32x64; 3-stage cp.async; frag double-buffering.
// ---------------------------------------------------------------------------
#define TC_STAGE_FLOATS (128 * TC_KSTR)
#define TC_SMEM_BYTES (2 * TC_STAGES * TC_STAGE_FLOATS * 4)

template<int ACT, int HAS_BIAS, int HAS_RES>
__global__ __launch_bounds__(256)
void gemm_tc_kernel(const float* __restrict__ A, const float* __restrict__ B,
                    const float* __restrict__ bias, const float* __restrict__ res,
                    float* __restrict__ C, int M, int N, int K,
                    int lda, int ldb, int ldc)
{
    extern __shared__ float smem[];
    float* As = smem;                                  // [S][128][36]
    float* Bs = smem + TC_STAGES * TC_STAGE_FLOATS;    // [S][128][36]

    const int tid  = threadIdx.x;
    const int wid  = tid >> 5;
    const int lane = tid & 31;
    const int bm = blockIdx.y * 128;
    const int bn = blockIdx.x * 128;
    const int warp_m = (wid >> 1) * 32;
    const int warp_n = (wid & 1) * 64;
    const int tig = lane & 3;
    const int grp = lane >> 2;

    float acc[2][8][4];
#pragma unroll
    for (int mt = 0; mt < 2; mt++)
#pragma unroll
        for (int nt = 0; nt < 8; nt++)
#pragma unroll
            for (int i = 0; i < 4; i++) acc[mt][nt][i] = 0.0f;

    const int NK = K >> 5;

    auto load_stage = [&](int s, int kt) {
        const int k0 = kt << 5;
        float* as = As + s * TC_STAGE_FLOATS;
        float* bs = Bs + s * TC_STAGE_FLOATS;
#pragma unroll
        for (int p = 0; p < 4; p++) {
            int item = tid + p * 256;
            int row  = item >> 3;
            int kq   = (item & 7) * 4;
            const float* ga = A + (long)(bm + row) * lda + k0 + kq;
            cp_async16((uint32_t)__cvta_generic_to_shared(as + row * TC_KSTR + kq), ga);
            const float* gb = B + (long)(bn + row) * ldb + k0 + kq;
            cp_async16((uint32_t)__cvta_generic_to_shared(bs + row * TC_KSTR + kq), gb);
        }
    };

    load_stage(0, 0); cp_commit();
    load_stage(1, 1); cp_commit();

    for (int kt = 0; kt < NK; kt++) {
        cp_wait<TC_STAGES - 2>();
        __syncthreads();

        {
            int nk = kt + TC_STAGES - 1;
            if (nk < NK) load_stage(nk % TC_STAGES, nk);
            cp_commit();
        }

        const int cs = kt % TC_STAGES;
        const float* as = As + cs * TC_STAGE_FLOATS;
        const float* bs = Bs + cs * TC_STAGE_FLOATS;

        uint32_t af[2][2][4];
        uint32_t bf[2][8][2];

        auto load_frags = [&](int ks, uint32_t (&a)[2][4], uint32_t (&b)[8][2]) {
#pragma unroll
            for (int mt = 0; mt < 2; mt++) {
                int m = warp_m + mt * 16;
                a[mt][0] = f2tf32(as[(m + grp    ) * TC_KSTR + ks + tig    ]);
                a[mt][1] = f2tf32(as[(m + grp + 8) * TC_KSTR + ks + tig    ]);
                a[mt][2] = f2tf32(as[(m + grp    ) * TC_KSTR + ks + tig + 4]);
                a[mt][3] = f2tf32(as[(m + grp + 8) * TC_KSTR + ks + tig + 4]);
            }
#pragma unroll
            for (int nt = 0; nt < 8; nt++) {
                int n = warp_n + nt * 8;
                b[nt][0] = f2tf32(bs[(n + grp) * TC_KSTR + ks + tig    ]);
                b[nt][1] = f2tf32(bs[(n + grp) * TC_KSTR + ks + tig + 4]);
            }
        };

        load_frags(0, af[0], bf[0]);
#pragma unroll
        for (int ksi = 0; ksi < 4; ksi++) {
            const int cur = ksi & 1;
            const int nxt = cur ^ 1;
            if (ksi < 3) load_frags((ksi + 1) * 8, af[nxt], bf[nxt]);
#pragma unroll
            for (int mt = 0; mt < 2; mt++)
#pragma unroll
                for (int nt = 0; nt < 8; nt++)
                    mma_tf32(acc[mt][nt], af[cur][mt], bf[cur][nt]);
        }
    }

#pragma unroll
    for (int mt = 0; mt < 2; mt++) {
        int r = bm + warp_m + mt * 16 + grp;
#pragma unroll
        for (int nt = 0; nt < 8; nt++) {
            int c0 = bn + warp_n + nt * 8 + tig * 2;
            float v0 = acc[mt][nt][0];
            float v1 = acc[mt][nt][1];
            float v2 = acc[mt][nt][2];
            float v3 = acc[mt][nt][3];
            if (HAS_BIAS) {
                float b0 = bias[c0], b1 = bias[c0 + 1];
                v0 += b0; v1 += b1; v2 += b0; v3 += b1;
            }
            if (ACT == 1) { v0 = act_gelu(v0); v1 = act_gelu(v1); v2 = act_gelu(v2); v3 = act_gelu(v3); }
            long o0 = (long)r * ldc + c0;
            long o1 = (long)(r + 8) * ldc + c0;
            if (HAS_RES) {
                v0 += res[o0]; v1 += res[o0 + 1];
                v2 += res[o1]; v3 += res[o1 + 1];
            }
            C[o0] = v0; C[o0 + 1] = v1;
            C[o1] = v2; C[o1 + 1] = v3;
        }
    }
}

// ---------------------------------------------------------------------------
// Pipelined tensor-core tf32 GEMM, 64x128 CTA tile (for N == 512: balances
// the wave — grid 392 instead of 196 on 148 SMs).
// 8 warps 2(m)x4(n), warp 32x32. M%64==0, N%128==0, K%32==0.
// smem: As [S][64][36], Bs [S][128][36] = 82.9 KB.
// ---------------------------------------------------------------------------
#define TC64_A_FLOATS (64 * TC_KSTR)
#define TC64_B_FLOATS (128 * TC_KSTR)
#define TC64_SMEM_BYTES (TC_STAGES * (TC64_A_FLOATS + TC64_B_FLOATS) * 4)

template<int ACT, int HAS_BIAS, int HAS_RES>
__global__ __launch_bounds__(256)
void gemm_tc64_kernel(const float* __restrict__ A, const float* __restrict__ B,
                      const float* __restrict__ bias, const float* __restrict__ res,
                      float* __restrict__ C, int M, int N, int K,
                      int lda, int ldb, int ldc)
{
    extern __shared__ float smem[];
    float* As = smem;                                       // [S][64][36]
    float* Bs = smem + TC_STAGES * TC64_A_FLOATS;           // [S][128][36]

    const int tid  = threadIdx.x;
    const int wid  = tid >> 5;
    const int lane = tid & 31;
    const int bm = blockIdx.y * 64;
    const int bn = blockIdx.x * 128;
    const int warp_m = (wid >> 2) * 32;   // 0,32
    const int warp_n = (wid & 3) * 32;    // 0,32,64,96
    const int tig = lane & 3;
    const int grp = lane >> 2;

    float acc[2][4][4];
#pragma unroll
    for (int mt = 0; mt < 2; mt++)
#pragma unroll
        for (int nt = 0; nt < 4; nt++)
#pragma unroll
            for (int i = 0; i < 4; i++) acc[mt][nt][i] = 0.0f;

    const int NK = K >> 5;

    // A: 64 rows x 8 quads = 512 items (2/thread); B: 128 x 8 = 1024 (4/thread)
    auto load_stage = [&](int s, int kt) {
        const int k0 = kt << 5;
        float* as = As + s * TC64_A_FLOATS;
        float* bs = Bs + s * TC64_B_FLOATS;
#pragma unroll
        for (int p = 0; p < 2; p++) {
            int item = tid + p * 256;
            int row  = item >> 3;
            int kq   = (item & 7) * 4;
            const float* ga = A + (long)(bm + row) * lda + k0 + kq;
            cp_async16((uint32_t)__cvta_generic_to_shared(as + row * TC_KSTR + kq), ga);
        }
#pragma unroll
        for (int p = 0; p < 4; p++) {
            int item = tid + p * 256;
            int row  = item >> 3;
            int kq   = (item & 7) * 4;
            const float* gb = B + (long)(bn + row) * ldb + k0 + kq;
            cp_async16((uint32_t)__cvta_generic_to_shared(bs + row * TC_KSTR + kq), gb);
        }
    };

    load_stage(0, 0); cp_commit();
    load_stage(1, 1); cp_commit();

    for (int kt = 0; kt < NK; kt++) {
        cp_wait<TC_STAGES - 2>();
        __syncthreads();

        {
            int nk = kt + TC_STAGES - 1;
            if (nk < NK) load_stage(nk % TC_STAGES, nk);
            cp_commit();
        }

        const int cs = kt % TC_STAGES;
        const float* as = As + cs * TC64_A_FLOATS;
        const float* bs = Bs + cs * TC64_B_FLOATS;

        uint32_t af[2][2][4];
        uint32_t bf[2][4][2];

        auto load_frags = [&](int ks, uint32_t (&a)[2][4], uint32_t (&b)[4][2]) {
#pragma unroll
            for (int mt = 0; mt < 2; mt++) {
                int m = warp_m + mt * 16;
                a[mt][0] = f2tf32(as[(m + grp    ) * TC_KSTR + ks + tig    ]);
                a[mt][1] = f2tf32(as[(m + grp + 8) * TC_KSTR + ks + tig    ]);
                a[mt][2] = f2tf32(as[(m + grp    ) * TC_KSTR + ks + tig + 4]);
                a[mt][3] = f2tf32(as[(m + grp + 8) * TC_KSTR + ks + tig + 4]);
            }
#pragma unroll
            for (int nt = 0; nt < 4; nt++) {
                int n = warp_n + nt * 8;
                b[nt][0] = f2tf32(bs[(n + grp) * TC_KSTR + ks + tig    ]);
                b[nt][1] = f2tf32(bs[(n + grp) * TC_KSTR + ks + tig + 4]);
            }
        };

        load_frags(0, af[0], bf[0]);
#pragma unroll
        for (int ksi = 0; ksi < 4; ksi++) {
            const int cur = ksi & 1;
            const int nxt = cur ^ 1;
            if (ksi < 3) load_frags((ksi + 1) * 8, af[nxt], bf[nxt]);
#pragma unroll
            for (int mt = 0; mt < 2; mt++)
#pragma unroll
                for (int nt = 0; nt < 4; nt++)
                    mma_tf32(acc[mt][nt], af[cur][mt], bf[cur][nt]);
        }
    }

#pragma unroll
    for (int mt = 0; mt < 2; mt++) {
        int r = bm + warp_m + mt * 16 + grp;
#pragma unroll
        for (int nt = 0; nt < 4; nt++) {
            int c0 = bn + warp_n + nt * 8 + tig * 2;
            float v0 = acc[mt][nt][0];
            float v1 = acc[mt][nt][1];
            float v2 = acc[mt][nt][2];
            float v3 = acc[mt][nt][3];
            if (HAS_BIAS) {
                float b0 = bias[c0], b1 = bias[c0 + 1];
                v0 += b0; v1 += b1; v2 += b0; v3 += b1;
            }
            if (ACT == 1) { v0 = act_gelu(v0); v1 = act_gelu(v1); v2 = act_gelu(v2); v3 = act_gelu(v3); }
            long o0 = (long)r * ldc + c0;
            long o1 = (long)(r + 8) * ldc + c0;
            if (HAS_RES) {
                v0 += res[o0]; v1 += res[o0 + 1];
                v2 += res[o1]; v3 += res[o1 + 1];
            }
            C[o0] = v0; C[o0 + 1] = v1;
            C[o1] = v2; C[o1 + 1] = v3;
        }
    }
}

// ---------------------------------------------------------------------------
// Generic fp32 GEMM (odd shapes: x_proj, dt_proj, attention).
// ---------------------------------------------------------------------------
template<int TRANS_B, int ACT, int HAS_BIAS, int HAS_RES>
__global__ __launch_bounds__(256)
void gemm_kernel(const float* __restrict__ A, const float* __restrict__ B,
                 const float* __restrict__ bias, const float* __restrict__ res,
                 float* __restrict__ C,
                 int M, int N, int K, int lda, int ldb, int ldc,
                 long sA, long sB, long sC, float alpha)
{
    A += (long)blockIdx.z * sA;
    B += (long)blockIdx.z * sB;
    C += (long)blockIdx.z * sC;
    if (HAS_RES) res += (long)blockIdx.z * sC;

    __shared__ float As[16][65];
    __shared__ float Bs[16][65];

    const int tid = threadIdx.x;
    const int bm = blockIdx.y * 64;
    const int bn = blockIdx.x * 64;
    const int ty = tid >> 4;
    const int tx = tid & 15;

    float acc[4][4];
#pragma unroll
    for (int i = 0; i < 4; i++)
#pragma unroll
        for (int j = 0; j < 4; j++) acc[i][j] = 0.0f;

    const int nkt = (K + 15) >> 4;
    for (int kt = 0; kt < nkt; kt++) {
        const int k0 = kt << 4;
#pragma unroll
        for (int p = 0; p < 4; p++) {
            int r  = (tid >> 4) + p * 16;
            int gm = bm + r;
            int gk = k0 + (tid & 15);
            As[tid & 15][r] = (gm < M && gk < K) ? A[(long)gm * lda + gk] : 0.0f;
        }
        if (TRANS_B) {
#pragma unroll
            for (int p = 0; p < 4; p++) {
                int r  = (tid >> 4) + p * 16;
                int gn = bn + r;
                int gk = k0 + (tid & 15);
                Bs[tid & 15][r] = (gn < N && gk < K) ? B[(long)gn * ldb + gk] : 0.0f;
            }
        } else {
#pragma unroll
            for (int p = 0; p < 4; p++) {
                int kk = (tid >> 6) + p * 4;
                int nn = tid & 63;
                int gk = k0 + kk;
                int gn = bn + nn;
                Bs[kk][nn] = (gk < K && gn < N) ? B[(long)gk * ldb + gn] : 0.0f;
            }
        }
        __syncthreads();
#pragma unroll
        for (int kk = 0; kk < 16; kk++) {
            float a[4], b[4];
#pragma unroll
            for (int i = 0; i < 4; i++) a[i] = As[kk][ty * 4 + i];
#pragma unroll
            for (int j = 0; j < 4; j++) b[j] = Bs[kk][tx * 4 + j];
#pragma unroll
            for (int i = 0; i < 4; i++)
#pragma unroll
                for (int j = 0; j < 4; j++) acc[i][j] = fmaf(a[i], b[j], acc[i][j]);
        }
        __syncthreads();
    }

#pragma unroll
    for (int i = 0; i < 4; i++) {
        int gm = bm + ty * 4 + i;
        if (gm >= M) continue;
#pragma unroll
        for (int j = 0; j < 4; j++) {
            int gn = bn + tx * 4 + j;
            if (gn >= N) continue;
            float v = acc[i][j] * alpha;
            if (HAS_BIAS) v += bias[gn];
            if (ACT == 1) v = act_gelu(v);
            else if (ACT == 2) v = act_softplus(v);
            if (HAS_RES) v += res[(long)gm * ldc + gn];
            C[(long)gm * ldc + gn] = v;
        }
    }
}

// ---------------------------------------------------------------------------
// im2col for the 16x16/stride-16 patch conv.
// ---------------------------------------------------------------------------
__global__ void im2col_kernel(const float* __restrict__ x)
{
    int idx = blockIdx.x * blockDim.x + threadIdx.x;
    const int n = TOK * PATCHK;
    if (idx >= n) return;
    int tok  = idx / PATCHK;
    int cidx = idx - tok * PATCHK;
    int b  = tok / SEQL;
    int l  = tok - b * SEQL;
    int ph = l / 14, pw = l - ph * 14;
    int c  = cidx >> 8;
    int r  = cidx & 255;
    int kh = r >> 4, kw = r & 15;
    g_col[idx] = x[(((long)b * 3 + c) * 224 + (ph * 16 + kh)) * 224 + (pw * 16 + kw)];
}

// ---------------------------------------------------------------------------
// LayerNorm over last dim (512).
// ---------------------------------------------------------------------------
__global__ __launch_bounds__(128)
void layernorm_kernel(const float* __restrict__ in, const float* __restrict__ g,
                      const float* __restrict__ b, float* __restrict__ out)
{
    int tok = blockIdx.x;
    int tid = threadIdx.x;
    const float* row = in + (long)tok * DMODEL;
    float v[4];
    float s = 0.0f, s2 = 0.0f;
#pragma unroll
    for (int i = 0; i < 4; i++) {
        v[i] = row[tid + i * 128];
        s  += v[i];
        s2 += v[i] * v[i];
    }
#pragma unroll
    for (int o = 16; o > 0; o >>= 1) {
        s  += __shfl_xor_sync(0xffffffffu, s,  o);
        s2 += __shfl_xor_sync(0xffffffffu, s2, o);
    }
    __shared__ float ss[4], ss2[4];
    int warp = tid >> 5, lane = tid & 31;
    if (lane == 0) { ss[warp] = s; ss2[warp] = s2; }
    __syncthreads();
    s  = ss[0] + ss[1] + ss[2] + ss[3];
    s2 = ss2[0] + ss2[1] + ss2[2] + ss2[3];
    float mean = s * (1.0f / DMODEL);
    float var  = s2 * (1.0f / DMODEL) - mean * mean;
    float inv  = rsqrtf(var + 1e-6f);
    float* orow = out + (long)tok * DMODEL;
#pragma unroll
    for (int i = 0; i < 4; i++) {
        int col = tid + i * 128;
        orow[col] = (v[i] - mean) * inv * g[col] + b[col];
    }
}

// ---------------------------------------------------------------------------
// Causal depthwise conv (width 4) + SiLU for both halves of xz.
// ---------------------------------------------------------------------------
__global__ void dwconv_silu_kernel(const float* __restrict__ wx, const float* __restrict__ bx,
                                   const float* __restrict__ wz, const float* __restrict__ bz)
{
    int idx = blockIdx.x * blockDim.x + threadIdx.x;
    const int n = TOK * DINNER;
    if (idx >= 2 * n) return;
    int half = idx >= n;
    int id   = half ? idx - n : idx;
    int tok  = id >> 8;
    int c    = id & 255;
    int b    = tok / SEQL;
    int l    = tok - b * SEQL;
    const float* w  = half ? wz : wx;
    const float* bb = half ? bz : bx;
    int off = half ? DINNER : 0;
    float sum = bb[c];
#pragma unroll
    for (int k = 0; k < 4; k++) {
        int ll = l - 3 + k;
        if (ll >= 0)
            sum += g_xz[((long)(b * SEQL + ll)) * DMODEL + off + c] * w[c * 4 + k];
    }
    sum = act_silu(sum);
    if (half) g_cat[(long)tok * DMODEL + DINNER + c] = sum;
    else      g_xm[(long)tok * DINNER + c] = sum;
}

// ---------------------------------------------------------------------------
// Selective scan.
// ---------------------------------------------------------------------------
__global__ __launch_bounds__(256)
void scan_kernel(const float* __restrict__ A_log, const float* __restrict__ Dp)
{
    int b    = blockIdx.x >> 4;
    int dblk = blockIdx.x & 15;
    int nidx = threadIdx.x & 15;
    int d    = dblk * 16 + (threadIdx.x >> 4);

    float An = -expf(A_log[d * DSTATE + nidx]);
    float Dd = Dp[d];
    float h  = 0.0f;
    const long tokbase = (long)b * SEQL;
    for (int l = 0; l < SEQL; l++) {
        long t   = tokbase + l;
        float dtv = g_dt[t * DINNER + d];
        float u   = g_xm[t * DINNER + d];
        float Bn  = g_xdbl[t * 48 + DTRANK + nidx];
        float Cn  = g_xdbl[t * 48 + DTRANK + DSTATE + nidx];
        h = __expf(dtv * An) * h + dtv * u * Bn;
        float y = h * Cn;
        y += __shfl_xor_sync(0xffffffffu, y, 8);
        y += __shfl_xor_sync(0xffffffffu, y, 4);
        y += __shfl_xor_sync(0xffffffffu, y, 2);
        y += __shfl_xor_sync(0xffffffffu, y, 1);
        if (nidx == 0)
            g_cat[t * DMODEL + d] = y + u * Dd;
    }
}

// ---------------------------------------------------------------------------
// qkv split: [tok, 3, 8, 64] -> q/k/v [bh, 196, 64]
// ---------------------------------------------------------------------------
__global__ void split_qkv_kernel()
{
    int idx = blockIdx.x * blockDim.x + threadIdx.x;
    const int n = TOK * 3 * DMODEL;
    if (idx >= n) return;
    int tok = idx / (3 * DMODEL);
    int r   = idx - tok * (3 * DMODEL);
    int which = r / DMODEL;
    int h  = (r % DMODEL) / HDIM;
    int dd = r % HDIM;
    int b = tok / SEQL, l = tok - b * SEQL;
    long dst = ((long)(b * NHEAD + h) * SEQL + l) * HDIM + dd;
    float val = g_qkv[idx];
    if (which == 0)      g_q[dst] = val;
    else if (which == 1) g_k[dst] = val;
    else                 g_v[dst] = val;
}

// ---------------------------------------------------------------------------
// Row softmax over 196 cols.
// ---------------------------------------------------------------------------
__global__ __launch_bounds__(128)
void softmax_kernel()
{
    long rowbase = (long)blockIdx.x * SEQL;
    int tid = threadIdx.x;
    float m = -1e30f;
    for (int j = tid; j < SEQL; j += 128) m = fmaxf(m, g_sc[rowbase + j]);
#pragma unroll
    for (int o = 16; o > 0; o >>= 1) m = fmaxf(m, __shfl_xor_sync(0xffffffffu, m, o));
    __shared__ float sm[4], ssum[4];
    int warp = tid >> 5, lane = tid & 31;
    if (lane == 0) sm[warp] = m;
    __syncthreads();
    m = fmaxf(fmaxf(sm[0], sm[1]), fmaxf(sm[2], sm[3]));
    float s = 0.0f;
    for (int j = tid; j < SEQL; j += 128) {
        float e = __expf(g_sc[rowbase + j] - m);
        g_sc[rowbase + j] = e;
        s += e;
    }
#pragma unroll
    for (int o = 16; o > 0; o >>= 1) s += __shfl_xor_sync(0xffffffffu, s, o);
    if (lane == 0) ssum[warp] = s;
    __syncthreads();
    s = ssum[0] + ssum[1] + ssum[2] + ssum[3];
    float inv = 1.0f / s;
    for (int j = tid; j < SEQL; j += 128) g_sc[rowbase + j] *= inv;
}

// ---------------------------------------------------------------------------
// Merge attention output: [bh, 196, 64] -> [tok, 512]
// ---------------------------------------------------------------------------
__global__ void merge_o_kernel()
{
    int idx = blockIdx.x * blockDim.x + threadIdx.x;
    const int n = TOK * DMODEL;
    if (idx >= n) return;
    int tok = idx >> 9;
    int ch  = idx & 511;
    int h = ch >> 6, dd = ch & 63;
    int b = tok / SEQL, l = tok - b * SEQL;
    g_o[idx] = g_obh[((long)(b * NHEAD + h) * SEQL + l) * HDIM + dd];
}

// ---------------------------------------------------------------------------
// Mean pool over L.
// ---------------------------------------------------------------------------
__global__ __launch_bounds__(256)
void pool_kernel()
{
    int b = blockIdx.x;
    for (int j = threadIdx.x; j < 1024; j += blockDim.x) {
        float s = 0.0f;
        const float* base = g_feat + (long)b * SEQL * 1024 + j;
        for (int l = 0; l < SEQL; l++) s += base[(long)l * 1024];
        g_pool[b * 1024 + j] = s * (1.0f / SEQL);
    }
}

// ---------------------------------------------------------------------------
// Final fc: [32,1024] @ [4,1024]^T + b -> [32,4]
// ---------------------------------------------------------------------------
__global__ __launch_bounds__(128)
void fc_kernel(const float* __restrict__ fc_w, const float* __restrict__ fc_b,
               float* __restrict__ out)
{
    int o = threadIdx.x;
    if (o >= BATCH * 4) return;
    int b = o >> 2, c = o & 3;
    float s = fc_b[c];
    const float* p = g_pool + b * 1024;
    const float* w = fc_w + c * 1024;
    for (int k = 0; k < 1024; k++) s = fmaf(p[k], w[k], s);
    out[o] = s;
}

// ---------------------------------------------------------------------------
// Launch
// ---------------------------------------------------------------------------
static inline dim3 gemm_grid(int M, int N, int batch) {
    return dim3((N + 63) / 64, (M + 63) / 64, batch);
}
static inline dim3 tc_grid(int M, int N) {
    return dim3(N / 128, M / 128, 1);
}
static inline dim3 tc64_grid(int M, int N) {
    return dim3(N / 128, M / 64, 1);
}

extern "C" void kernel_launch(void* const* d_in, const int* in_sizes, int n_in,
                              void* d_out, int out_size)
{
    const float* x          = (const float*)d_in[0];
    const float* patch_w    = (const float*)d_in[1];
    const float* patch_b    = (const float*)d_in[2];
    const float* ln1_g      = (const float*)d_in[3];
    const float* ln1_b      = (const float*)d_in[4];
    const float* in_proj_w  = (const float*)d_in[5];
    const float* convx_w    = (const float*)d_in[6];
    const float* convx_b    = (const float*)d_in[7];
    const float* convz_w    = (const float*)d_in[8];
    const float* convz_b    = (const float*)d_in[9];
    const float* x_proj_w   = (const float*)d_in[10];
    const float* dt_proj_w  = (const float*)d_in[11];
    const float* dt_proj_b  = (const float*)d_in[12];
    const float* A_log      = (const float*)d_in[13];
    const float* Dp         = (const float*)d_in[14];
    const float* out_proj_w = (const float*)d_in[15];
    const float* ln2_g      = (const float*)d_in[16];
    const float* ln2_b      = (const float*)d_in[17];
    const float* qkv_w      = (const float*)d_in[18];
    const float* attn_proj_w= (const float*)d_in[19];
    const float* ln3_g      = (const float*)d_in[20];
    const float* ln3_b      = (const float*)d_in[21];
    const float* mlp_w1     = (const float*)d_in[22];
    const float* mlp_b1     = (const float*)d_in[23];
    const float* mlp_w2     = (const float*)d_in[24];
    const float* mlp_b2     = (const float*)d_in[25];
    const float* head_w     = (const float*)d_in[26];
    const float* head_b     = (const float*)d_in[27];
    const float* fc_w       = (const float*)d_in[28];
    const float* fc_b       = (const float*)d_in[29];
    float* out = (float*)d_out;

    float *p_col, *p_t, *p_ln, *p_xz, *p_xm, *p_xdbl, *p_dt, *p_cat, *p_qkv;
    float *p_q, *p_k, *p_v, *p_sc, *p_obh, *p_o, *p_mlp, *p_feat;
    cudaGetSymbolAddress((void**)&p_col,  g_col);
    cudaGetSymbolAddress((void**)&p_t,    g_t);
    cudaGetSymbolAddress((void**)&p_ln,   g_ln);
    cudaGetSymbolAddress((void**)&p_xz,   g_xz);
    cudaGetSymbolAddress((void**)&p_xm,   g_xm);
    cudaGetSymbolAddress((void**)&p_xdbl, g_xdbl);
    cudaGetSymbolAddress((void**)&p_dt,   g_dt);
    cudaGetSymbolAddress((void**)&p_cat,  g_cat);
    cudaGetSymbolAddress((void**)&p_qkv,  g_qkv);
    cudaGetSymbolAddress((void**)&p_q,    g_q);
    cudaGetSymbolAddress((void**)&p_k,    g_k);
    cudaGetSymbolAddress((void**)&p_v,    g_v);
    cudaGetSymbolAddress((void**)&p_sc,   g_sc);
    cudaGetSymbolAddress((void**)&p_obh,  g_obh);
    cudaGetSymbolAddress((void**)&p_o,    g_o);
    cudaGetSymbolAddress((void**)&p_mlp,  g_mlp);
    cudaGetSymbolAddress((void**)&p_feat, g_feat);

    // smem attributes (idempotent)
    cudaFuncSetAttribute(gemm_tc_kernel<0,0,0>,   cudaFuncAttributeMaxDynamicSharedMemorySize, TC_SMEM_BYTES);
    cudaFuncSetAttribute(gemm_tc_kernel<1,1,0>,   cudaFuncAttributeMaxDynamicSharedMemorySize, TC_SMEM_BYTES);
    cudaFuncSetAttribute(gemm_tc_kernel<0,1,0>,   cudaFuncAttributeMaxDynamicSharedMemorySize, TC_SMEM_BYTES);
    cudaFuncSetAttribute(gemm_tc64_kernel<0,1,0>, cudaFuncAttributeMaxDynamicSharedMemorySize, TC64_SMEM_BYTES);
    cudaFuncSetAttribute(gemm_tc64_kernel<0,0,0>, cudaFuncAttributeMaxDynamicSharedMemorySize, TC64_SMEM_BYTES);
    cudaFuncSetAttribute(gemm_tc64_kernel<0,0,1>, cudaFuncAttributeMaxDynamicSharedMemorySize, TC64_SMEM_BYTES);
    cudaFuncSetAttribute(gemm_tc64_kernel<0,1,1>, cudaFuncAttributeMaxDynamicSharedMemorySize, TC64_SMEM_BYTES);

    // 1) im2col
    {
        int n = TOK * PATCHK;
        im2col_kernel<<<(n + 255) / 256, 256>>>(x);
    }
    // 2) patch embed (TC64: N=512)
    gemm_tc64_kernel<0,1,0><<<tc64_grid(TOK, DMODEL), 256, TC64_SMEM_BYTES>>>(
        p_col, patch_w, patch_b, nullptr, p_t,
        TOK, DMODEL, PATCHK, PATCHK, PATCHK, DMODEL);
    // 3) LN1
    layernorm_kernel<<<TOK, 128>>>(p_t, ln1_g, ln1_b, p_ln);
    // 4) in_proj (TC64)
    gemm_tc64_kernel<0,0,0><<<tc64_grid(TOK, DMODEL), 256, TC64_SMEM_BYTES>>>(
        p_ln, in_proj_w, nullptr, nullptr, p_xz,
        TOK, DMODEL, DMODEL, DMODEL, DMODEL, DMODEL);
    // 5) causal dwconv + silu
    {
        int n = 2 * TOK * DINNER;
        dwconv_silu_kernel<<<(n + 255) / 256, 256>>>(convx_w, convx_b, convz_w, convz_b);
    }
    // 6) x_proj (fp32 small)
    gemm_kernel<1,0,0,0><<<gemm_grid(TOK, 48, 1), 256>>>(
        p_xm, x_proj_w, nullptr, nullptr, p_xdbl,
        TOK, 48, DINNER, DINNER, DINNER, 48, 0, 0, 0, 1.0f);
    // 7) dt_proj + softplus (fp32 small K)
    gemm_kernel<1,2,1,0><<<gemm_grid(TOK, DINNER, 1), 256>>>(
        p_xdbl, dt_proj_w, dt_proj_b, nullptr, p_dt,
        TOK, DINNER, DTRANK, 48, DTRANK, DINNER, 0, 0, 0, 1.0f);
    // 8) selective scan
    scan_kernel<<<BATCH * 16, 256>>>(A_log, Dp);
    // 9) out_proj + residual (TC64)
    gemm_tc64_kernel<0,0,1><<<tc64_grid(TOK, DMODEL), 256, TC64_SMEM_BYTES>>>(
        p_cat, out_proj_w, nullptr, p_t, p_t,
        TOK, DMODEL, DMODEL, DMODEL, DMODEL, DMODEL);
    // 10) LN2
    layernorm_kernel<<<TOK, 128>>>(p_t, ln2_g, ln2_b, p_ln);
    // 11) qkv (TC 128x128: N=1536)
    gemm_tc_kernel<0,0,0><<<tc_grid(TOK, 3 * DMODEL), 256, TC_SMEM_BYTES>>>(
        p_ln, qkv_w, nullptr, nullptr, p_qkv,
        TOK, 3 * DMODEL, DMODEL, DMODEL, DMODEL, 3 * DMODEL);
    // 12) split qkv
    {
        int n = TOK * 3 * DMODEL;
        split_qkv_kernel<<<(n + 255) / 256, 256>>>();
    }
    // 13) scores = Q K^T / 8 (batched fp32)
    gemm_kernel<1,0,0,0><<<gemm_grid(SEQL, SEQL, NBH), 256>>>(
        p_q, p_k, nullptr, nullptr, p_sc,
        SEQL, SEQL, HDIM, HDIM, HDIM, SEQL,
        (long)SEQL * HDIM, (long)SEQL * HDIM, (long)SEQL * SEQL, 0.125f);
    // 14) softmax
    softmax_kernel<<<NBH * SEQL, 128>>>();
    // 15) O = P V (batched fp32, NN)
    gemm_kernel<0,0,0,0><<<gemm_grid(SEQL, HDIM, NBH), 256>>>(
        p_sc, p_v, nullptr, nullptr, p_obh,
        SEQL, HDIM, SEQL, SEQL, HDIM, HDIM,
        (long)SEQL * SEQL, (long)SEQL * HDIM, (long)SEQL * HDIM, 1.0f);
    // 16) merge O
    {
        int n = TOK * DMODEL;
        merge_o_kernel<<<(n + 255) / 256, 256>>>();
    }
    // 17) attn_proj + residual (TC64)
    gemm_tc64_kernel<0,0,1><<<tc64_grid(TOK, DMODEL), 256, TC64_SMEM_BYTES>>>(
        p_o, attn_proj_w, nullptr, p_t, p_t,
        TOK, DMODEL, DMODEL, DMODEL, DMODEL, DMODEL);
    // 18) LN3
    layernorm_kernel<<<TOK, 128>>>(p_t, ln3_g, ln3_b, p_ln);
    // 19) mlp1 + gelu (TC 128x128: N=2048)
    gemm_tc_kernel<1,1,0><<<tc_grid(TOK, 4 * DMODEL), 256, TC_SMEM_BYTES>>>(
        p_ln, mlp_w1, mlp_b1, nullptr, p_mlp,
        TOK, 4 * DMODEL, DMODEL, DMODEL, DMODEL, 4 * DMODEL);
    // 20) mlp2 + b2 + residual (TC64: N=512, K=2048)
    gemm_tc64_kernel<0,1,1><<<tc64_grid(TOK, DMODEL), 256, TC64_SMEM_BYTES>>>(
        p_mlp, mlp_w2, mlp_b2, p_t, p_t,
        TOK, DMODEL, 4 * DMODEL, 4 * DMODEL, 4 * DMODEL, DMODEL);
    // 21) head (TC 128x128: N=1024)
    gemm_tc_kernel<0,1,0><<<tc_grid(TOK, 1024), 256, TC_SMEM_BYTES>>>(
        p_t, head_w, head_b, nullptr, p_feat,
        TOK, 1024, DMODEL, DMODEL, DMODEL, 1024);
    // 22) mean pool
    pool_kernel<<<BATCH, 256>>>();
    // 23) fc
    fc_kernel<<<1, 128>>>(fc_w, fc_b, out);
}

// round 16
// speedup vs baseline: 3.3281x; 1.1315x over previous
#include <cuda_runtime.h>
#include <cuda_bf16.h>
#include <math.h>
#include <stdint.h>

// ---------------------------------------------------------------------------
// Problem constants
// ---------------------------------------------------------------------------
#define BATCH   32
#define SEQL    196          // 14*14 patches
#define SEQP    256          // padded seq for TC attention
#define TOK     (BATCH*SEQL) // 6272
#define DMODEL  512
#define DINNER  256
#define DSTATE  16
#define DTRANK  16
#define NHEAD   8
#define HDIM    64
#define NBH     (BATCH*NHEAD) // 256
#define PATCHK  768          // 3*16*16

// ---------------------------------------------------------------------------
// Scratch (static device globals; zero-initialized at module load).
// q/k/v/obh are padded to SEQP rows per (b,h); padding rows are NEVER written
// and therefore stay zero forever -> TC attention needs no bounds checks.
// ---------------------------------------------------------------------------
__device__ float g_col  [TOK * PATCHK];
__device__ float g_t    [TOK * DMODEL];
__device__ float g_ln   [TOK * DMODEL];
__device__ float g_xz   [TOK * DMODEL];
__device__ float g_xm   [TOK * DINNER];
__device__ float g_xdbl [TOK * 48];
__device__ float g_dt   [TOK * DINNER];
__device__ float g_cat  [TOK * DMODEL];
__device__ float g_qkv  [TOK * 3 * DMODEL];
__device__ float g_q    [NBH * SEQP * HDIM];
__device__ float g_k    [NBH * SEQP * HDIM];
__device__ float g_v    [NBH * SEQP * HDIM];
__device__ float g_sc   [NBH * SEQP * SEQP];   // scores, stride 256
__device__ float g_obh  [NBH * SEQP * HDIM];
__device__ float g_o    [TOK * DMODEL];
__device__ float g_mlp  [TOK * 4 * DMODEL];
__device__ float g_feat [TOK * 1024];
__device__ float g_pool [BATCH * 1024];

// ---------------------------------------------------------------------------
// Activation helpers
// ---------------------------------------------------------------------------
__device__ __forceinline__ float act_gelu(float x) {
    float x3 = x * x * x;
    return 0.5f * x * (1.0f + tanhf(0.7978845608028654f * (x + 0.044715f * x3)));
}
__device__ __forceinline__ float act_softplus(float x) {
    return (x > 20.0f) ? x : log1pf(expf(x));
}
__device__ __forceinline__ float act_silu(float x) {
    return x / (1.0f + expf(-x));
}

// ---------------------------------------------------------------------------
// tf32 / async-copy helpers
// ---------------------------------------------------------------------------
__device__ __forceinline__ uint32_t f2tf32(float x) {
    uint32_t r;
    asm("cvt.rna.tf32.f32 %0, %1;" : "=r"(r) : "f"(x));
    return r;
}
__device__ __forceinline__ void mma_tf32(float* d, const uint32_t* a, const uint32_t* b) {
    asm volatile(
        "mma.sync.aligned.m16n8k8.row.col.f32.tf32.tf32.f32 "
        "{%0,%1,%2,%3}, {%4,%5,%6,%7}, {%8,%9}, {%0,%1,%2,%3};\n"
        : "+f"(d[0]), "+f"(d[1]), "+f"(d[2]), "+f"(d[3])
        : "r"(a[0]), "r"(a[1]), "r"(a[2]), "r"(a[3]), "r"(b[0]), "r"(b[1]));
}
__device__ __forceinline__ void cp_async16(uint32_t saddr, const void* gptr) {
    asm volatile("cp.async.cg.shared.global [%0], [%1], 16;\n" :: "r"(saddr), "l"(gptr));
}
__device__ __forceinline__ void cp_commit() {
    asm volatile("cp.async.commit_group;\n");
}
template<int N>
__device__ __forceinline__ void cp_wait() {
    asm volatile("cp.async.wait_group %0;\n" :: "n"(N));
}

#define TC_STAGES 3
#define TC_KSTR   36

// ---------------------------------------------------------------------------
// Pipelined tensor-core tf32 GEMM, 128x128 CTA tile (for N >= 1024).
// C[M,N] = A[M,K] * B[N,K]^T (+bias)(act)(+res). M%128==0, N%128==0, K%32==0.
// ---------------------------------------------------------------------------
#define TC_STAGE_FLOATS (128 * TC_KSTR)
#define TC_SMEM_BYTES (2 * TC_STAGES * TC_STAGE_FLOATS * 4)

template<int ACT, int HAS_BIAS, int HAS_RES>
__global__ __launch_bounds__(256)
void gemm_tc_kernel(const float* __restrict__ A, const float* __restrict__ B,
                    const float* __restrict__ bias, const float* __restrict__ res,
                    float* __restrict__ C, int M, int N, int K,
                    int lda, int ldb, int ldc)
{
    extern __shared__ float smem[];
    float* As = smem;
    float* Bs = smem + TC_STAGES * TC_STAGE_FLOATS;

    const int tid  = threadIdx.x;
    const int wid  = tid >> 5;
    const int lane = tid & 31;
    const int bm = blockIdx.y * 128;
    const int bn = blockIdx.x * 128;
    const int warp_m = (wid >> 1) * 32;
    const int warp_n = (wid & 1) * 64;
    const int tig = lane & 3;
    const int grp = lane >> 2;

    float acc[2][8][4];
#pragma unroll
    for (int mt = 0; mt < 2; mt++)
#pragma unroll
        for (int nt = 0; nt < 8; nt++)
#pragma unroll
            for (int i = 0; i < 4; i++) acc[mt][nt][i] = 0.0f;

    const int NK = K >> 5;

    auto load_stage = [&](int s, int kt) {
        const int k0 = kt << 5;
        float* as = As + s * TC_STAGE_FLOATS;
        float* bs = Bs + s * TC_STAGE_FLOATS;
#pragma unroll
        for (int p = 0; p < 4; p++) {
            int item = tid + p * 256;
            int row  = item >> 3;
            int kq   = (item & 7) * 4;
            const float* ga = A + (long)(bm + row) * lda + k0 + kq;
            cp_async16((uint32_t)__cvta_generic_to_shared(as + row * TC_KSTR + kq), ga);
            const float* gb = B + (long)(bn + row) * ldb + k0 + kq;
            cp_async16((uint32_t)__cvta_generic_to_shared(bs + row * TC_KSTR + kq), gb);
        }
    };

    load_stage(0, 0); cp_commit();
    load_stage(1, 1); cp_commit();

    for (int kt = 0; kt < NK; kt++) {
        cp_wait<TC_STAGES - 2>();
        __syncthreads();

        {
            int nk = kt + TC_STAGES - 1;
            if (nk < NK) load_stage(nk % TC_STAGES, nk);
            cp_commit();
        }

        const int cs = kt % TC_STAGES;
        const float* as = As + cs * TC_STAGE_FLOATS;
        const float* bs = Bs + cs * TC_STAGE_FLOATS;

        uint32_t af[2][2][4];
        uint32_t bf[2][8][2];

        auto load_frags = [&](int ks, uint32_t (&a)[2][4], uint32_t (&b)[8][2]) {
#pragma unroll
            for (int mt = 0; mt < 2; mt++) {
                int m = warp_m + mt * 16;
                a[mt][0] = f2tf32(as[(m + grp    ) * TC_KSTR + ks + tig    ]);
                a[mt][1] = f2tf32(as[(m + grp + 8) * TC_KSTR + ks + tig    ]);
                a[mt][2] = f2tf32(as[(m + grp    ) * TC_KSTR + ks + tig + 4]);
                a[mt][3] = f2tf32(as[(m + grp + 8) * TC_KSTR + ks + tig + 4]);
            }
#pragma unroll
            for (int nt = 0; nt < 8; nt++) {
                int n = warp_n + nt * 8;
                b[nt][0] = f2tf32(bs[(n + grp) * TC_KSTR + ks + tig    ]);
                b[nt][1] = f2tf32(bs[(n + grp) * TC_KSTR + ks + tig + 4]);
            }
        };

        load_frags(0, af[0], bf[0]);
#pragma unroll
        for (int ksi = 0; ksi < 4; ksi++) {
            const int cur = ksi & 1;
            const int nxt = cur ^ 1;
            if (ksi < 3) load_frags((ksi + 1) * 8, af[nxt], bf[nxt]);
#pragma unroll
            for (int mt = 0; mt < 2; mt++)
#pragma unroll
                for (int nt = 0; nt < 8; nt++)
                    mma_tf32(acc[mt][nt], af[cur][mt], bf[cur][nt]);
        }
    }

#pragma unroll
    for (int mt = 0; mt < 2; mt++) {
        int r = bm + warp_m + mt * 16 + grp;
#pragma unroll
        for (int nt = 0; nt < 8; nt++) {
            int c0 = bn + warp_n + nt * 8 + tig * 2;
            float v0 = acc[mt][nt][0];
            float v1 = acc[mt][nt][1];
            float v2 = acc[mt][nt][2];
            float v3 = acc[mt][nt][3];
            if (HAS_BIAS) {
                float b0 = bias[c0], b1 = bias[c0 + 1];
                v0 += b0; v1 += b1; v2 += b0; v3 += b1;
            }
            if (ACT == 1) { v0 = act_gelu(v0); v1 = act_gelu(v1); v2 = act_gelu(v2); v3 = act_gelu(v3); }
            long o0 = (long)r * ldc + c0;
            long o1 = (long)(r + 8) * ldc + c0;
            if (HAS_RES) {
                v0 += res[o0]; v1 += res[o0 + 1];
                v2 += res[o1]; v3 += res[o1 + 1];
            }
            C[o0] = v0; C[o0 + 1] = v1;
            C[o1] = v2; C[o1 + 1] = v3;
        }
    }
}

// ---------------------------------------------------------------------------
// Pipelined tf32 GEMM, 64x128 CTA tile, batched (z) via element strides.
// C[M,N] = A[M,K] * B[N,K]^T (+bias)(act)(+res). M%64==0, N%128==0, K%32==0.
// Used for all N==512 projections (strides 0, z=1) and batched QK^T.
// ---------------------------------------------------------------------------
#define TC64_A_FLOATS (64 * TC_KSTR)
#define TC64_B_FLOATS (128 * TC_KSTR)
#define TC64_SMEM_BYTES (TC_STAGES * (TC64_A_FLOATS + TC64_B_FLOATS) * 4)

template<int ACT, int HAS_BIAS, int HAS_RES>
__global__ __launch_bounds__(256)
void gemm_tc64_kernel(const float* __restrict__ A, const float* __restrict__ B,
                      const float* __restrict__ bias, const float* __restrict__ res,
                      float* __restrict__ C, int M, int N, int K,
                      int lda, int ldb, int ldc,
                      long sA, long sB, long sC)
{
    extern __shared__ float smem[];
    float* As = smem;
    float* Bs = smem + TC_STAGES * TC64_A_FLOATS;

    A += (long)blockIdx.z * sA;
    B += (long)blockIdx.z * sB;
    C += (long)blockIdx.z * sC;

    const int tid  = threadIdx.x;
    const int wid  = tid >> 5;
    const int lane = tid & 31;
    const int bm = blockIdx.y * 64;
    const int bn = blockIdx.x * 128;
    const int warp_m = (wid >> 2) * 32;
    const int warp_n = (wid & 3) * 32;
    const int tig = lane & 3;
    const int grp = lane >> 2;

    float acc[2][4][4];
#pragma unroll
    for (int mt = 0; mt < 2; mt++)
#pragma unroll
        for (int nt = 0; nt < 4; nt++)
#pragma unroll
            for (int i = 0; i < 4; i++) acc[mt][nt][i] = 0.0f;

    const int NK = K >> 5;

    auto load_stage = [&](int s, int kt) {
        const int k0 = kt << 5;
        float* as = As + s * TC64_A_FLOATS;
        float* bs = Bs + s * TC64_B_FLOATS;
#pragma unroll
        for (int p = 0; p < 2; p++) {
            int item = tid + p * 256;
            int row  = item >> 3;
            int kq   = (item & 7) * 4;
            const float* ga = A + (long)(bm + row) * lda + k0 + kq;
            cp_async16((uint32_t)__cvta_generic_to_shared(as + row * TC_KSTR + kq), ga);
        }
#pragma unroll
        for (int p = 0; p < 4; p++) {
            int item = tid + p * 256;
            int row  = item >> 3;
            int kq   = (item & 7) * 4;
            const float* gb = B + (long)(bn + row) * ldb + k0 + kq;
            cp_async16((uint32_t)__cvta_generic_to_shared(bs + row * TC_KSTR + kq), gb);
        }
    };

    load_stage(0, 0); cp_commit();
    load_stage(1, 1); cp_commit();

    for (int kt = 0; kt < NK; kt++) {
        cp_wait<TC_STAGES - 2>();
        __syncthreads();

        {
            int nk = kt + TC_STAGES - 1;
            if (nk < NK) load_stage(nk % TC_STAGES, nk);
            cp_commit();
        }

        const int cs = kt % TC_STAGES;
        const float* as = As + cs * TC64_A_FLOATS;
        const float* bs = Bs + cs * TC64_B_FLOATS;

        uint32_t af[2][2][4];
        uint32_t bf[2][4][2];

        auto load_frags = [&](int ks, uint32_t (&a)[2][4], uint32_t (&b)[4][2]) {
#pragma unroll
            for (int mt = 0; mt < 2; mt++) {
                int m = warp_m + mt * 16;
                a[mt][0] = f2tf32(as[(m + grp    ) * TC_KSTR + ks + tig    ]);
                a[mt][1] = f2tf32(as[(m + grp + 8) * TC_KSTR + ks + tig    ]);
                a[mt][2] = f2tf32(as[(m + grp    ) * TC_KSTR + ks + tig + 4]);
                a[mt][3] = f2tf32(as[(m + grp + 8) * TC_KSTR + ks + tig + 4]);
            }
#pragma unroll
            for (int nt = 0; nt < 4; nt++) {
                int n = warp_n + nt * 8;
                b[nt][0] = f2tf32(bs[(n + grp) * TC_KSTR + ks + tig    ]);
                b[nt][1] = f2tf32(bs[(n + grp) * TC_KSTR + ks + tig + 4]);
            }
        };

        load_frags(0, af[0], bf[0]);
#pragma unroll
        for (int ksi = 0; ksi < 4; ksi++) {
            const int cur = ksi & 1;
            const int nxt = cur ^ 1;
            if (ksi < 3) load_frags((ksi + 1) * 8, af[nxt], bf[nxt]);
#pragma unroll
            for (int mt = 0; mt < 2; mt++)
#pragma unroll
                for (int nt = 0; nt < 4; nt++)
                    mma_tf32(acc[mt][nt], af[cur][mt], bf[cur][nt]);
        }
    }

#pragma unroll
    for (int mt = 0; mt < 2; mt++) {
        int r = bm + warp_m + mt * 16 + grp;
#pragma unroll
        for (int nt = 0; nt < 4; nt++) {
            int c0 = bn + warp_n + nt * 8 + tig * 2;
            float v0 = acc[mt][nt][0];
            float v1 = acc[mt][nt][1];
            float v2 = acc[mt][nt][2];
            float v3 = acc[mt][nt][3];
            if (HAS_BIAS) {
                float b0 = bias[c0], b1 = bias[c0 + 1];
                v0 += b0; v1 += b1; v2 += b0; v3 += b1;
            }
            if (ACT == 1) { v0 = act_gelu(v0); v1 = act_gelu(v1); v2 = act_gelu(v2); v3 = act_gelu(v3); }
            long o0 = (long)r * ldc + c0;
            long o1 = (long)(r + 8) * ldc + c0;
            if (HAS_RES) {
                v0 += res[o0]; v1 += res[o0 + 1];
                v2 += res[o1]; v3 += res[o1 + 1];
            }
            C[o0] = v0; C[o0 + 1] = v1;
            C[o1] = v2; C[o1 + 1] = v3;
        }
    }
}

// ---------------------------------------------------------------------------
// Pipelined tf32 GEMM, non-trans B, 128x64 CTA tile, batched.
// C[M,64] = A[M,K] * B[K,64]   (B row-major [K][64]) — the PV product.
// M%128==0, K%32==0, N fixed 64. 8 warps 4(m)x2(n), warp 32x32.
// smem: As [S][128][36], Bs [S][32][72] (stride 72 -> conflict-free).
// ---------------------------------------------------------------------------
#define PVB_KSTR 72
#define PV_A_FLOATS (128 * TC_KSTR)
#define PV_B_FLOATS (32 * PVB_KSTR)
#define PV_SMEM_BYTES (TC_STAGES * (PV_A_FLOATS + PV_B_FLOATS) * 4)

__global__ __launch_bounds__(256)
void gemm_pv_kernel(const float* __restrict__ A, const float* __restrict__ B,
                    float* __restrict__ C, int M, int K,
                    int lda, int ldb, int ldc,
                    long sA, long sB, long sC)
{
    extern __shared__ float smem[];
    float* As = smem;
    float* Bs = smem + TC_STAGES * PV_A_FLOATS;

    A += (long)blockIdx.z * sA;
    B += (long)blockIdx.z * sB;
    C += (long)blockIdx.z * sC;

    const int tid  = threadIdx.x;
    const int wid  = tid >> 5;
    const int lane = tid & 31;
    const int bm = blockIdx.y * 128;
    const int warp_m = (wid >> 1) * 32;
    const int warp_n = (wid & 1) * 32;
    const int tig = lane & 3;
    const int grp = lane >> 2;

    float acc[2][4][4];
#pragma unroll
    for (int mt = 0; mt < 2; mt++)
#pragma unroll
        for (int nt = 0; nt < 4; nt++)
#pragma unroll
            for (int i = 0; i < 4; i++) acc[mt][nt][i] = 0.0f;

    const int NK = K >> 5;

    // A: 128 rows x 8 quads = 1024 items (4/thread).
    // B: 32 k-rows x 16 quads (64 cols) = 512 items (2/thread).
    auto load_stage = [&](int s, int kt) {
        const int k0 = kt << 5;
        float* as = As + s * PV_A_FLOATS;
        float* bs = Bs + s * PV_B_FLOATS;
#pragma unroll
        for (int p = 0; p < 4; p++) {
            int item = tid + p * 256;
            int row  = item >> 3;
            int kq   = (item & 7) * 4;
            const float* ga = A + (long)(bm + row) * lda + k0 + kq;
            cp_async16((uint32_t)__cvta_generic_to_shared(as + row * TC_KSTR + kq), ga);
        }
#pragma unroll
        for (int p = 0; p < 2; p++) {
            int item = tid + p * 256;
            int krow = item >> 4;
            int cq   = (item & 15) * 4;
            const float* gb = B + (long)(k0 + krow) * ldb + cq;
            cp_async16((uint32_t)__cvta_generic_to_shared(bs + krow * PVB_KSTR + cq), gb);
        }
    };

    load_stage(0, 0); cp_commit();
    load_stage(1, 1); cp_commit();

    for (int kt = 0; kt < NK; kt++) {
        cp_wait<TC_STAGES - 2>();
        __syncthreads();

        {
            int nk = kt + TC_STAGES - 1;
            if (nk < NK) load_stage(nk % TC_STAGES, nk);
            cp_commit();
        }

        const int cs = kt % TC_STAGES;
        const float* as = As + cs * PV_A_FLOATS;
        const float* bs = Bs + cs * PV_B_FLOATS;

        uint32_t af[2][2][4];
        uint32_t bf[2][4][2];

        auto load_frags = [&](int ks, uint32_t (&a)[2][4], uint32_t (&b)[4][2]) {
#pragma unroll
            for (int mt = 0; mt < 2; mt++) {
                int m = warp_m + mt * 16;
                a[mt][0] = f2tf32(as[(m + grp    ) * TC_KSTR + ks + tig    ]);
                a[mt][1] = f2tf32(as[(m + grp + 8) * TC_KSTR + ks + tig    ]);
                a[mt][2] = f2tf32(as[(m + grp    ) * TC_KSTR + ks + tig + 4]);
                a[mt][3] = f2tf32(as[(m + grp + 8) * TC_KSTR + ks + tig + 4]);
            }
#pragma unroll
            for (int nt = 0; nt < 4; nt++) {
                int n = warp_n + nt * 8;
                // B stored [k][n]: b0 = B[ks+tig][n+grp], b1 = B[ks+tig+4][n+grp]
                b[nt][0] = f2tf32(bs[(ks + tig    ) * PVB_KSTR + n + grp]);
                b[nt][1] = f2tf32(bs[(ks + tig + 4) * PVB_KSTR + n + grp]);
            }
        };

        load_frags(0, af[0], bf[0]);
#pragma unroll
        for (int ksi = 0; ksi < 4; ksi++) {
            const int cur = ksi & 1;
            const int nxt = cur ^ 1;
            if (ksi < 3) load_frags((ksi + 1) * 8, af[nxt], bf[nxt]);
#pragma unroll
            for (int mt = 0; mt < 2; mt++)
#pragma unroll
                for (int nt = 0; nt < 4; nt++)
                    mma_tf32(acc[mt][nt], af[cur][mt], bf[cur][nt]);
        }
    }

#pragma unroll
    for (int mt = 0; mt < 2; mt++) {
        int r = bm + warp_m + mt * 16 + grp;
#pragma unroll
        for (int nt = 0; nt < 4; nt++) {
            int c0 = warp_n + nt * 8 + tig * 2;
            long o0 = (long)r * ldc + c0;
            long o1 = (long)(r + 8) * ldc + c0;
            C[o0] = acc[mt][nt][0]; C[o0 + 1] = acc[mt][nt][1];
            C[o1] = acc[mt][nt][2]; C[o1 + 1] = acc[mt][nt][3];
        }
    }
}

// ---------------------------------------------------------------------------
// Generic fp32 GEMM (x_proj, dt_proj).
// ---------------------------------------------------------------------------
template<int TRANS_B, int ACT, int HAS_BIAS, int HAS_RES>
__global__ __launch_bounds__(256)
void gemm_kernel(const float* __restrict__ A, const float* __restrict__ B,
                 const float* __restrict__ bias, const float* __restrict__ res,
                 float* __restrict__ C,
                 int M, int N, int K, int lda, int ldb, int ldc,
                 long sA, long sB, long sC, float alpha)
{
    A += (long)blockIdx.z * sA;
    B += (long)blockIdx.z * sB;
    C += (long)blockIdx.z * sC;
    if (HAS_RES) res += (long)blockIdx.z * sC;

    __shared__ float As[16][65];
    __shared__ float Bs[16][65];

    const int tid = threadIdx.x;
    const int bm = blockIdx.y * 64;
    const int bn = blockIdx.x * 64;
    const int ty = tid >> 4;
    const int tx = tid & 15;

    float acc[4][4];
#pragma unroll
    for (int i = 0; i < 4; i++)
#pragma unroll
        for (int j = 0; j < 4; j++) acc[i][j] = 0.0f;

    const int nkt = (K + 15) >> 4;
    for (int kt = 0; kt < nkt; kt++) {
        const int k0 = kt << 4;
#pragma unroll
        for (int p = 0; p < 4; p++) {
            int r  = (tid >> 4) + p * 16;
            int gm = bm + r;
            int gk = k0 + (tid & 15);
            As[tid & 15][r] = (gm < M && gk < K) ? A[(long)gm * lda + gk] : 0.0f;
        }
        if (TRANS_B) {
#pragma unroll
            for (int p = 0; p < 4; p++) {
                int r  = (tid >> 4) + p * 16;
                int gn = bn + r;
                int gk = k0 + (tid & 15);
                Bs[tid & 15][r] = (gn < N && gk < K) ? B[(long)gn * ldb + gk] : 0.0f;
            }
        } else {
#pragma unroll
            for (int p = 0; p < 4; p++) {
                int kk = (tid >> 6) + p * 4;
                int nn = tid & 63;
                int gk = k0 + kk;
                int gn = bn + nn;
                Bs[kk][nn] = (gk < K && gn < N) ? B[(long)gk * ldb + gn] : 0.0f;
            }
        }
        __syncthreads();
#pragma unroll
        for (int kk = 0; kk < 16; kk++) {
            float a[4], b[4];
#pragma unroll
            for (int i = 0; i < 4; i++) a[i] = As[kk][ty * 4 + i];
#pragma unroll
            for (int j = 0; j < 4; j++) b[j] = Bs[kk][tx * 4 + j];
#pragma unroll
            for (int i = 0; i < 4; i++)
#pragma unroll
                for (int j = 0; j < 4; j++) acc[i][j] = fmaf(a[i], b[j], acc[i][j]);
        }
        __syncthreads();
    }

#pragma unroll
    for (int i = 0; i < 4; i++) {
        int gm = bm + ty * 4 + i;
        if (gm >= M) continue;
#pragma unroll
        for (int j = 0; j < 4; j++) {
            int gn = bn + tx * 4 + j;
            if (gn >= N) continue;
            float v = acc[i][j] * alpha;
            if (HAS_BIAS) v += bias[gn];
            if (ACT == 1) v = act_gelu(v);
            else if (ACT == 2) v = act_softplus(v);
            if (HAS_RES) v += res[(long)gm * ldc + gn];
            C[(long)gm * ldc + gn] = v;
        }
    }
}

// ---------------------------------------------------------------------------
// im2col for the 16x16/stride-16 patch conv.
// ---------------------------------------------------------------------------
__global__ void im2col_kernel(const float* __restrict__ x)
{
    int idx = blockIdx.x * blockDim.x + threadIdx.x;
    const int n = TOK * PATCHK;
    if (idx >= n) return;
    int tok  = idx / PATCHK;
    int cidx = idx - tok * PATCHK;
    int b  = tok / SEQL;
    int l  = tok - b * SEQL;
    int ph = l / 14, pw = l - ph * 14;
    int c  = cidx >> 8;
    int r  = cidx & 255;
    int kh = r >> 4, kw = r & 15;
    g_col[idx] = x[(((long)b * 3 + c) * 224 + (ph * 16 + kh)) * 224 + (pw * 16 + kw)];
}

// ---------------------------------------------------------------------------
// LayerNorm over last dim (512).
// ---------------------------------------------------------------------------
__global__ __launch_bounds__(128)
void layernorm_kernel(const float* __restrict__ in, const float* __restrict__ g,
                      const float* __restrict__ b, float* __restrict__ out)
{
    int tok = blockIdx.x;
    int tid = threadIdx.x;
    const float* row = in + (long)tok * DMODEL;
    float v[4];
    float s = 0.0f, s2 = 0.0f;
#pragma unroll
    for (int i = 0; i < 4; i++) {
        v[i] = row[tid + i * 128];
        s  += v[i];
        s2 += v[i] * v[i];
    }
#pragma unroll
    for (int o = 16; o > 0; o >>= 1) {
        s  += __shfl_xor_sync(0xffffffffu, s,  o);
        s2 += __shfl_xor_sync(0xffffffffu, s2, o);
    }
    __shared__ float ss[4], ss2[4];
    int warp = tid >> 5, lane = tid & 31;
    if (lane == 0) { ss[warp] = s; ss2[warp] = s2; }
    __syncthreads();
    s  = ss[0] + ss[1] + ss[2] + ss[3];
    s2 = ss2[0] + ss2[1] + ss2[2] + ss2[3];
    float mean = s * (1.0f / DMODEL);
    float var  = s2 * (1.0f / DMODEL) - mean * mean;
    float inv  = rsqrtf(var + 1e-6f);
    float* orow = out + (long)tok * DMODEL;
#pragma unroll
    for (int i = 0; i < 4; i++) {
        int col = tid + i * 128;
        orow[col] = (v[i] - mean) * inv * g[col] + b[col];
    }
}

// ---------------------------------------------------------------------------
// Causal depthwise conv (width 4) + SiLU for both halves of xz.
// ---------------------------------------------------------------------------
__global__ void dwconv_silu_kernel(const float* __restrict__ wx, const float* __restrict__ bx,
                                   const float* __restrict__ wz, const float* __restrict__ bz)
{
    int idx = blockIdx.x * blockDim.x + threadIdx.x;
    const int n = TOK * DINNER;
    if (idx >= 2 * n) return;
    int half = idx >= n;
    int id   = half ? idx - n : idx;
    int tok  = id >> 8;
    int c    = id & 255;
    int b    = tok / SEQL;
    int l    = tok - b * SEQL;
    const float* w  = half ? wz : wx;
    const float* bb = half ? bz : bx;
    int off = half ? DINNER : 0;
    float sum = bb[c];
#pragma unroll
    for (int k = 0; k < 4; k++) {
        int ll = l - 3 + k;
        if (ll >= 0)
            sum += g_xz[((long)(b * SEQL + ll)) * DMODEL + off + c] * w[c * 4 + k];
    }
    sum = act_silu(sum);
    if (half) g_cat[(long)tok * DMODEL + DINNER + c] = sum;
    else      g_xm[(long)tok * DINNER + c] = sum;
}

// ---------------------------------------------------------------------------
// Selective scan.
// ---------------------------------------------------------------------------
__global__ __launch_bounds__(256)
void scan_kernel(const float* __restrict__ A_log, const float* __restrict__ Dp)
{
    int b    = blockIdx.x >> 4;
    int dblk = blockIdx.x & 15;
    int nidx = threadIdx.x & 15;
    int d    = dblk * 16 + (threadIdx.x >> 4);

    float An = -expf(A_log[d * DSTATE + nidx]);
    float Dd = Dp[d];
    float h  = 0.0f;
    const long tokbase = (long)b * SEQL;
    for (int l = 0; l < SEQL; l++) {
        long t   = tokbase + l;
        float dtv = g_dt[t * DINNER + d];
        float u   = g_xm[t * DINNER + d];
        float Bn  = g_xdbl[t * 48 + DTRANK + nidx];
        float Cn  = g_xdbl[t * 48 + DTRANK + DSTATE + nidx];
        h = __expf(dtv * An) * h + dtv * u * Bn;
        float y = h * Cn;
        y += __shfl_xor_sync(0xffffffffu, y, 8);
        y += __shfl_xor_sync(0xffffffffu, y, 4);
        y += __shfl_xor_sync(0xffffffffu, y, 2);
        y += __shfl_xor_sync(0xffffffffu, y, 1);
        if (nidx == 0)
            g_cat[t * DMODEL + d] = y + u * Dd;
    }
}

// ---------------------------------------------------------------------------
// qkv split: [tok, 3, 8, 64] -> q/k/v [bh, SEQP, 64]; q pre-scaled by 1/8
// (exact power of two: identical to scaling scores).
// ---------------------------------------------------------------------------
__global__ void split_qkv_kernel()
{
    int idx = blockIdx.x * blockDim.x + threadIdx.x;
    const int n = TOK * 3 * DMODEL;
    if (idx >= n) return;
    int tok = idx / (3 * DMODEL);
    int r   = idx - tok * (3 * DMODEL);
    int which = r / DMODEL;
    int h  = (r % DMODEL) / HDIM;
    int dd = r % HDIM;
    int b = tok / SEQL, l = tok - b * SEQL;
    long dst = ((long)(b * NHEAD + h) * SEQP + l) * HDIM + dd;
    float val = g_qkv[idx];
    if (which == 0)      g_q[dst] = val * 0.125f;
    else if (which == 1) g_k[dst] = val;
    else                 g_v[dst] = val;
}

// ---------------------------------------------------------------------------
// Row softmax over 196 cols of the padded [SEQP][SEQP] score matrix.
// grid = NBH*SEQL rows.
// ---------------------------------------------------------------------------
__global__ __launch_bounds__(128)
void softmax_kernel()
{
    int rowid = blockIdx.x;
    int bh = rowid / SEQL;
    int i  = rowid - bh * SEQL;
    long rowbase = ((long)bh * SEQP + i) * SEQP;
    int tid = threadIdx.x;
    float m = -1e30f;
    for (int j = tid; j < SEQL; j += 128) m = fmaxf(m, g_sc[rowbase + j]);
#pragma unroll
    for (int o = 16; o > 0; o >>= 1) m = fmaxf(m, __shfl_xor_sync(0xffffffffu, m, o));
    __shared__ float sm[4], ssum[4];
    int warp = tid >> 5, lane = tid & 31;
    if (lane == 0) sm[warp] = m;
    __syncthreads();
    m = fmaxf(fmaxf(sm[0], sm[1]), fmaxf(sm[2], sm[3]));
    float s = 0.0f;
    for (int j = tid; j < SEQL; j += 128) {
        float e = __expf(g_sc[rowbase + j] - m);
        g_sc[rowbase + j] = e;
        s += e;
    }
#pragma unroll
    for (int o = 16; o > 0; o >>= 1) s += __shfl_xor_sync(0xffffffffu, s, o);
    if (lane == 0) ssum[warp] = s;
    __syncthreads();
    s = ssum[0] + ssum[1] + ssum[2] + ssum[3];
    float inv = 1.0f / s;
    for (int j = tid; j < SEQL; j += 128) g_sc[rowbase + j] *= inv;
}

// ---------------------------------------------------------------------------
// Merge attention output: [bh, SEQP, 64] -> [tok, 512]
// ---------------------------------------------------------------------------
__global__ void merge_o_kernel()
{
    int idx = blockIdx.x * blockDim.x + threadIdx.x;
    const int n = TOK * DMODEL;
    if (idx >= n) return;
    int tok = idx >> 9;
    int ch  = idx & 511;
    int h = ch >> 6, dd = ch & 63;
    int b = tok / SEQL, l = tok - b * SEQL;
    g_o[idx] = g_obh[((long)(b * NHEAD + h) * SEQP + l) * HDIM + dd];
}

// ---------------------------------------------------------------------------
// Mean pool over L.
// ---------------------------------------------------------------------------
__global__ __launch_bounds__(256)
void pool_kernel()
{
    int b = blockIdx.x;
    for (int j = threadIdx.x; j < 1024; j += blockDim.x) {
        float s = 0.0f;
        const float* base = g_feat + (long)b * SEQL * 1024 + j;
        for (int l = 0; l < SEQL; l++) s += base[(long)l * 1024];
        g_pool[b * 1024 + j] = s * (1.0f / SEQL);
    }
}

// ---------------------------------------------------------------------------
// Final fc: [32,1024] @ [4,1024]^T + b -> [32,4]
// ---------------------------------------------------------------------------
__global__ __launch_bounds__(128)
void fc_kernel(const float* __restrict__ fc_w, const float* __restrict__ fc_b,
               float* __restrict__ out)
{
    int o = threadIdx.x;
    if (o >= BATCH * 4) return;
    int b = o >> 2, c = o & 3;
    float s = fc_b[c];
    const float* p = g_pool + b * 1024;
    const float* w = fc_w + c * 1024;
    for (int k = 0; k < 1024; k++) s = fmaf(p[k], w[k], s);
    out[o] = s;
}

// ---------------------------------------------------------------------------
// Launch
// ---------------------------------------------------------------------------
static inline dim3 gemm_grid(int M, int N, int batch) {
    return dim3((N + 63) / 64, (M + 63) / 64, batch);
}
static inline dim3 tc_grid(int M, int N) {
    return dim3(N / 128, M / 128, 1);
}
static inline dim3 tc64_grid(int M, int N, int batch = 1) {
    return dim3(N / 128, M / 64, batch);
}

extern "C" void kernel_launch(void* const* d_in, const int* in_sizes, int n_in,
                              void* d_out, int out_size)
{
    const float* x          = (const float*)d_in[0];
    const float* patch_w    = (const float*)d_in[1];
    const float* patch_b    = (const float*)d_in[2];
    const float* ln1_g      = (const float*)d_in[3];
    const float* ln1_b      = (const float*)d_in[4];
    const float* in_proj_w  = (const float*)d_in[5];
    const float* convx_w    = (const float*)d_in[6];
    const float* convx_b    = (const float*)d_in[7];
    const float* convz_w    = (const float*)d_in[8];
    const float* convz_b    = (const float*)d_in[9];
    const float* x_proj_w   = (const float*)d_in[10];
    const float* dt_proj_w  = (const float*)d_in[11];
    const float* dt_proj_b  = (const float*)d_in[12];
    const float* A_log      = (const float*)d_in[13];
    const float* Dp         = (const float*)d_in[14];
    const float* out_proj_w = (const float*)d_in[15];
    const float* ln2_g      = (const float*)d_in[16];
    const float* ln2_b      = (const float*)d_in[17];
    const float* qkv_w      = (const float*)d_in[18];
    const float* attn_proj_w= (const float*)d_in[19];
    const float* ln3_g      = (const float*)d_in[20];
    const float* ln3_b      = (const float*)d_in[21];
    const float* mlp_w1     = (const float*)d_in[22];
    const float* mlp_b1     = (const float*)d_in[23];
    const float* mlp_w2     = (const float*)d_in[24];
    const float* mlp_b2     = (const float*)d_in[25];
    const float* head_w     = (const float*)d_in[26];
    const float* head_b     = (const float*)d_in[27];
    const float* fc_w       = (const float*)d_in[28];
    const float* fc_b       = (const float*)d_in[29];
    float* out = (float*)d_out;

    float *p_col, *p_t, *p_ln, *p_xz, *p_xm, *p_xdbl, *p_dt, *p_cat, *p_qkv;
    float *p_q, *p_k, *p_v, *p_sc, *p_obh, *p_o, *p_mlp, *p_feat;
    cudaGetSymbolAddress((void**)&p_col,  g_col);
    cudaGetSymbolAddress((void**)&p_t,    g_t);
    cudaGetSymbolAddress((void**)&p_ln,   g_ln);
    cudaGetSymbolAddress((void**)&p_xz,   g_xz);
    cudaGetSymbolAddress((void**)&p_xm,   g_xm);
    cudaGetSymbolAddress((void**)&p_xdbl, g_xdbl);
    cudaGetSymbolAddress((void**)&p_dt,   g_dt);
    cudaGetSymbolAddress((void**)&p_cat,  g_cat);
    cudaGetSymbolAddress((void**)&p_qkv,  g_qkv);
    cudaGetSymbolAddress((void**)&p_q,    g_q);
    cudaGetSymbolAddress((void**)&p_k,    g_k);
    cudaGetSymbolAddress((void**)&p_v,    g_v);
    cudaGetSymbolAddress((void**)&p_sc,   g_sc);
    cudaGetSymbolAddress((void**)&p_obh,  g_obh);
    cudaGetSymbolAddress((void**)&p_o,    g_o);
    cudaGetSymbolAddress((void**)&p_mlp,  g_mlp);
    cudaGetSymbolAddress((void**)&p_feat, g_feat);

    // smem attributes (idempotent)
    cudaFuncSetAttribute(gemm_tc_kernel<0,0,0>,   cudaFuncAttributeMaxDynamicSharedMemorySize, TC_SMEM_BYTES);
    cudaFuncSetAttribute(gemm_tc_kernel<1,1,0>,   cudaFuncAttributeMaxDynamicSharedMemorySize, TC_SMEM_BYTES);
    cudaFuncSetAttribute(gemm_tc_kernel<0,1,0>,   cudaFuncAttributeMaxDynamicSharedMemorySize, TC_SMEM_BYTES);
    cudaFuncSetAttribute(gemm_tc64_kernel<0,1,0>, cudaFuncAttributeMaxDynamicSharedMemorySize, TC64_SMEM_BYTES);
    cudaFuncSetAttribute(gemm_tc64_kernel<0,0,0>, cudaFuncAttributeMaxDynamicSharedMemorySize, TC64_SMEM_BYTES);
    cudaFuncSetAttribute(gemm_tc64_kernel<0,0,1>, cudaFuncAttributeMaxDynamicSharedMemorySize, TC64_SMEM_BYTES);
    cudaFuncSetAttribute(gemm_tc64_kernel<0,1,1>, cudaFuncAttributeMaxDynamicSharedMemorySize, TC64_SMEM_BYTES);
    cudaFuncSetAttribute(gemm_pv_kernel,          cudaFuncAttributeMaxDynamicSharedMemorySize, PV_SMEM_BYTES);

    // 1) im2col
    {
        int n = TOK * PATCHK;
        im2col_kernel<<<(n + 255) / 256, 256>>>(x);
    }
    // 2) patch embed (TC64: N=512)
    gemm_tc64_kernel<0,1,0><<<tc64_grid(TOK, DMODEL), 256, TC64_SMEM_BYTES>>>(
        p_col, patch_w, patch_b, nullptr, p_t,
        TOK, DMODEL, PATCHK, PATCHK, PATCHK, DMODEL, 0, 0, 0);
    // 3) LN1
    layernorm_kernel<<<TOK, 128>>>(p_t, ln1_g, ln1_b, p_ln);
    // 4) in_proj (TC64)
    gemm_tc64_kernel<0,0,0><<<tc64_grid(TOK, DMODEL), 256, TC64_SMEM_BYTES>>>(
        p_ln, in_proj_w, nullptr, nullptr, p_xz,
        TOK, DMODEL, DMODEL, DMODEL, DMODEL, DMODEL, 0, 0, 0);
    // 5) causal dwconv + silu
    {
        int n = 2 * TOK * DINNER;
        dwconv_silu_kernel<<<(n + 255) / 256, 256>>>(convx_w, convx_b, convz_w, convz_b);
    }
    // 6) x_proj (fp32 small)
    gemm_kernel<1,0,0,0><<<gemm_grid(TOK, 48, 1), 256>>>(
        p_xm, x_proj_w, nullptr, nullptr, p_xdbl,
        TOK, 48, DINNER, DINNER, DINNER, 48, 0, 0, 0, 1.0f);
    // 7) dt_proj + softplus (fp32 small K)
    gemm_kernel<1,2,1,0><<<gemm_grid(TOK, DINNER, 1), 256>>>(
        p_xdbl, dt_proj_w, dt_proj_b, nullptr, p_dt,
        TOK, DINNER, DTRANK, 48, DTRANK, DINNER, 0, 0, 0, 1.0f);
    // 8) selective scan
    scan_kernel<<<BATCH * 16, 256>>>(A_log, Dp);
    // 9) out_proj + residual (TC64)
    gemm_tc64_kernel<0,0,1><<<tc64_grid(TOK, DMODEL), 256, TC64_SMEM_BYTES>>>(
        p_cat, out_proj_w, nullptr, p_t, p_t,
        TOK, DMODEL, DMODEL, DMODEL, DMODEL, DMODEL, 0, 0, 0);
    // 10) LN2
    layernorm_kernel<<<TOK, 128>>>(p_t, ln2_g, ln2_b, p_ln);
    // 11) qkv (TC 128x128: N=1536)
    gemm_tc_kernel<0,0,0><<<tc_grid(TOK, 3 * DMODEL), 256, TC_SMEM_BYTES>>>(
        p_ln, qkv_w, nullptr, nullptr, p_qkv,
        TOK, 3 * DMODEL, DMODEL, DMODEL, DMODEL, 3 * DMODEL);
    // 12) split qkv (q pre-scaled by 1/8)
    {
        int n = TOK * 3 * DMODEL;
        split_qkv_kernel<<<(n + 255) / 256, 256>>>();
    }
    // 13) scores = Q K^T (TC, batched over 256 bh; padded to 256x256)
    gemm_tc64_kernel<0,0,0><<<tc64_grid(SEQP, SEQP, NBH), 256, TC64_SMEM_BYTES>>>(
        p_q, p_k, nullptr, nullptr, p_sc,
        SEQP, SEQP, HDIM, HDIM, HDIM, SEQP,
        (long)SEQP * HDIM, (long)SEQP * HDIM, (long)SEQP * SEQP);
    // 14) softmax (196 valid cols of padded rows)
    softmax_kernel<<<NBH * SEQL, 128>>>();
    // 15) O = P V (TC non-trans, batched)
    gemm_pv_kernel<<<dim3(1, SEQP / 128, NBH), 256, PV_SMEM_BYTES>>>(
        p_sc, p_v, p_obh,
        SEQP, SEQP, SEQP, HDIM, HDIM,
        (long)SEQP * SEQP, (long)SEQP * HDIM, (long)SEQP * HDIM);
    // 16) merge O
    {
        int n = TOK * DMODEL;
        merge_o_kernel<<<(n + 255) / 256, 256>>>();
    }
    // 17) attn_proj + residual (TC64)
    gemm_tc64_kernel<0,0,1><<<tc64_grid(TOK, DMODEL), 256, TC64_SMEM_BYTES>>>(
        p_o, attn_proj_w, nullptr, p_t, p_t,
        TOK, DMODEL, DMODEL, DMODEL, DMODEL, DMODEL, 0, 0, 0);
    // 18) LN3
    layernorm_kernel<<<TOK, 128>>>(p_t, ln3_g, ln3_b, p_ln);
    // 19) mlp1 + gelu (TC 128x128: N=2048)
    gemm_tc_kernel<1,1,0><<<tc_grid(TOK, 4 * DMODEL), 256, TC_SMEM_BYTES>>>(
        p_ln, mlp_w1, mlp_b1, nullptr, p_mlp,
        TOK, 4 * DMODEL, DMODEL, DMODEL, DMODEL, 4 * DMODEL);
    // 20) mlp2 + b2 + residual (TC64: N=512, K=2048)
    gemm_tc64_kernel<0,1,1><<<tc64_grid(TOK, DMODEL), 256, TC64_SMEM_BYTES>>>(
        p_mlp, mlp_w2, mlp_b2, p_t, p_t,
        TOK, DMODEL, 4 * DMODEL, 4 * DMODEL, 4 * DMODEL, DMODEL, 0, 0, 0);
    // 21) head (TC 128x128: N=1024)
    gemm_tc_kernel<0,1,0><<<tc_grid(TOK, 1024), 256, TC_SMEM_BYTES>>>(
        p_t, head_w, head_b, nullptr, p_feat,
        TOK, 1024, DMODEL, DMODEL, DMODEL, 1024);
    // 22) mean pool
    pool_kernel<<<BATCH, 256>>>();
    // 23) fc
    fc_kernel<<<1, 128>>>(fc_w, fc_b, out);
}